// round 1
// baseline (speedup 1.0000x reference)
#include <cuda_runtime.h>
#include <cuda_bf16.h>
#include <math.h>

// Problem constants
#define B_SZ 4
#define L_SZ 4096
#define D_MODEL 1024
#define N_HEADS 16
#define D_HEAD 64
#define CHUNK 128
#define NCHUNK 32
#define M_TOT (B_SZ * L_SZ)          // 16384

// Scratch: q, k, v, attention-out  (4 x 64MB, static device globals — allowed)
__device__ float g_q[M_TOT * D_MODEL];
__device__ float g_k[M_TOT * D_MODEL];
__device__ float g_v[M_TOT * D_MODEL];
__device__ float g_ao[M_TOT * D_MODEL];

// ---------------------------------------------------------------------------
// SGEMM: C[M,N] = A[M,K] @ B[K,N] + bias[N]
// 128x128 block tile, BK=8, 256 threads, 8x8 per thread, float4 loads.
// M,N,K multiples of 128 assumed (true here).
// ---------------------------------------------------------------------------
__global__ __launch_bounds__(256) void sgemm128(
    const float* __restrict__ A, const float* __restrict__ Bm,
    const float* __restrict__ bias, float* __restrict__ C,
    int M, int N, int K)
{
    __shared__ __align__(16) float As[8][128];
    __shared__ __align__(16) float Bs[8][128];

    const int tid = threadIdx.x;
    const int bx  = blockIdx.x;   // N tile
    const int by  = blockIdx.y;   // M tile
    const int tx  = tid & 15;     // 0..15
    const int ty  = tid >> 4;     // 0..15

    float acc[8][8];
#pragma unroll
    for (int i = 0; i < 8; i++)
#pragma unroll
        for (int j = 0; j < 8; j++) acc[i][j] = 0.f;

    // A tile load mapping: thread -> (arow, acol4)
    const int arow = tid >> 1;            // 0..127
    const int acol = (tid & 1) * 4;       // 0 or 4
    // B tile load mapping
    const int brow = tid >> 5;            // 0..7
    const int bcol = (tid & 31) * 4;      // 0..124

    const float* Aptr = A + (long)(by * 128 + arow) * K + acol;
    const float* Bptr = Bm + (long)brow * N + bx * 128 + bcol;

    for (int k0 = 0; k0 < K; k0 += 8) {
        float4 av = *(const float4*)(Aptr + k0);
        float4 bv = *(const float4*)(Bptr + (long)k0 * N);

        As[acol + 0][arow] = av.x;
        As[acol + 1][arow] = av.y;
        As[acol + 2][arow] = av.z;
        As[acol + 3][arow] = av.w;
        *(float4*)&Bs[brow][bcol] = bv;
        __syncthreads();

#pragma unroll
        for (int kk = 0; kk < 8; kk++) {
            float ar[8], br[8];
            *(float4*)&ar[0] = *(const float4*)&As[kk][ty * 8];
            *(float4*)&ar[4] = *(const float4*)&As[kk][ty * 8 + 4];
            *(float4*)&br[0] = *(const float4*)&Bs[kk][tx * 8];
            *(float4*)&br[4] = *(const float4*)&Bs[kk][tx * 8 + 4];
#pragma unroll
            for (int i = 0; i < 8; i++)
#pragma unroll
                for (int j = 0; j < 8; j++)
                    acc[i][j] = fmaf(ar[i], br[j], acc[i][j]);
        }
        __syncthreads();
    }

    // epilogue: add bias, store
#pragma unroll
    for (int i = 0; i < 8; i++) {
        const int row = by * 128 + ty * 8 + i;
        float* crow = C + (long)row * N + bx * 128 + tx * 8;
#pragma unroll
        for (int j = 0; j < 8; j += 4) {
            float4 o;
            o.x = acc[i][j + 0] + bias[bx * 128 + tx * 8 + j + 0];
            o.y = acc[i][j + 1] + bias[bx * 128 + tx * 8 + j + 1];
            o.z = acc[i][j + 2] + bias[bx * 128 + tx * 8 + j + 2];
            o.w = acc[i][j + 3] + bias[bx * 128 + tx * 8 + j + 3];
            *(float4*)(crow + j) = o;
        }
    }
}

// ---------------------------------------------------------------------------
// Chunked retention attention.
// Grid: (nC=32, H=16, B=4). Block: 128 threads (thread = query position).
// kf/vf = [129][64] staged in dynamic smem (key 0 = last token of previous
// chunk, zeros for chunk 0). Scores row-scaled by scale * decay[h]^q BEFORE
// softmax. Online softmax with fp32 accumulators in registers.
// Output written directly in [B, L, H*Dh] layout.
// ---------------------------------------------------------------------------
__global__ __launch_bounds__(128) void attn_kernel(
    const float* __restrict__ q, const float* __restrict__ k,
    const float* __restrict__ v, const float* __restrict__ decay,
    float* __restrict__ ao)
{
    const int c = blockIdx.x;
    const int h = blockIdx.y;
    const int b = blockIdx.z;
    const int tid = threadIdx.x;

    extern __shared__ float sm[];
    float* kf = sm;               // [129*64]
    float* vf = sm + 129 * 64;    // [129*64]

    const long base = ((long)b * L_SZ + (long)c * CHUNK) * D_MODEL + h * D_HEAD;

    // cooperative load of kf/vf (129 rows x 64 dims)
    for (int idx = tid; idx < 129 * 64; idx += 128) {
        const int j = idx >> 6;       // 0..128
        const int d = idx & 63;
        float kk = 0.f, vv = 0.f;
        if (j > 0 || c > 0) {
            const long g = base + (long)(j - 1) * D_MODEL + d;
            kk = k[g];
            vv = v[g];
        }
        kf[idx] = kk;
        vf[idx] = vv;
    }
    __syncthreads();

    // per-thread query vector
    float qreg[64];
    const float* qp = q + base + (long)tid * D_MODEL;
#pragma unroll
    for (int d = 0; d < 64; d++) qreg[d] = qp[d];

    const float sf = 0.125f * powf(decay[h], (float)tid);  // scale * decay^q

    float m = -1e30f, l = 0.f;
    float o[64];
#pragma unroll
    for (int d = 0; d < 64; d++) o[d] = 0.f;

    for (int j = 0; j < 129; j++) {
        const float* kj = kf + j * 64;
        float s = 0.f;
#pragma unroll
        for (int d = 0; d < 64; d++) s = fmaf(qreg[d], kj[d], s);
        s *= sf;

        const float mnew = fmaxf(m, s);
        const float corr = __expf(m - mnew);
        const float p    = __expf(s - mnew);
        l = l * corr + p;
        const float* vj = vf + j * 64;
#pragma unroll
        for (int d = 0; d < 64; d++) o[d] = fmaf(p, vj[d], o[d] * corr);
        m = mnew;
    }

    const float inv = 1.f / l;
    float* op = ao + base + (long)tid * D_MODEL;
#pragma unroll
    for (int d = 0; d < 64; d++) op[d] = o[d] * inv;
}

// ---------------------------------------------------------------------------
// Launch
// ---------------------------------------------------------------------------
extern "C" void kernel_launch(void* const* d_in, const int* in_sizes, int n_in,
                              void* d_out, int out_size)
{
    const float* x     = (const float*)d_in[0];
    const float* Wq    = (const float*)d_in[1];
    const float* bq    = (const float*)d_in[2];
    const float* Wk    = (const float*)d_in[3];
    const float* bk    = (const float*)d_in[4];
    const float* Wv    = (const float*)d_in[5];
    const float* bv    = (const float*)d_in[6];
    const float* Wo    = (const float*)d_in[7];
    const float* bo    = (const float*)d_in[8];
    const float* decay = (const float*)d_in[9];
    float* out = (float*)d_out;

    float *q, *k, *v, *ao;
    cudaGetSymbolAddress((void**)&q,  g_q);
    cudaGetSymbolAddress((void**)&k,  g_k);
    cudaGetSymbolAddress((void**)&v,  g_v);
    cudaGetSymbolAddress((void**)&ao, g_ao);

    const int smem_attn = 2 * 129 * 64 * (int)sizeof(float);  // 66 KB
    cudaFuncSetAttribute(attn_kernel, cudaFuncAttributeMaxDynamicSharedMemorySize,
                         smem_attn);

    dim3 ggrid(D_MODEL / 128, M_TOT / 128);  // (8, 128)

    sgemm128<<<ggrid, 256>>>(x, Wq, bq, q, M_TOT, D_MODEL, D_MODEL);
    sgemm128<<<ggrid, 256>>>(x, Wk, bk, k, M_TOT, D_MODEL, D_MODEL);
    sgemm128<<<ggrid, 256>>>(x, Wv, bv, v, M_TOT, D_MODEL, D_MODEL);

    attn_kernel<<<dim3(NCHUNK, N_HEADS, B_SZ), 128, smem_attn>>>(q, k, v, decay, ao);

    sgemm128<<<ggrid, 256>>>(ao, Wo, bo, out, M_TOT, D_MODEL, D_MODEL);
}

// round 4
// speedup vs baseline: 1.8049x; 1.8049x over previous
#include <cuda_runtime.h>
#include <cuda_bf16.h>
#include <math.h>
#include <stdint.h>

// ---------------------------------------------------------------- constants
#define B_SZ 4
#define L_SZ 4096
#define D_MODEL 1024
#define N_HEADS 16
#define D_HEAD 64
#define CHUNK 128
#define NCHUNK 32
#define M_TOT (B_SZ * L_SZ)      // 16384
#define KDIM 1024
#define NDIM 1024
#define WSL (KDIM * NDIM)

// GEMM tiling
#define BM 128
#define BN 128
#define BK 32
#define NKSTEP (KDIM / BK)       // 32
#define PAD_K 40                 // smem row stride in bf16 (conflict-free ldmatrix)
#define TILE_B (128 * PAD_K * 2) // 10240 bytes per 128x32 bf16 tile
#define STG (4 * TILE_B)         // Ah, Al, Bh, Bl per stage = 40960
#define NSTAGE 3
#define GSMEM (NSTAGE * STG)     // 122880

// ---------------------------------------------------------------- scratch
__device__ float g_q[M_TOT * D_MODEL];
__device__ float g_k[M_TOT * D_MODEL];
__device__ float g_v[M_TOT * D_MODEL];
__device__ __nv_bfloat16 g_xh[M_TOT * D_MODEL];
__device__ __nv_bfloat16 g_xl[M_TOT * D_MODEL];
__device__ __nv_bfloat16 g_aoh[M_TOT * D_MODEL];
__device__ __nv_bfloat16 g_aol[M_TOT * D_MODEL];
__device__ __nv_bfloat16 g_wth[4 * WSL];   // W^T [N,K] hi
__device__ __nv_bfloat16 g_wtl[4 * WSL];   // W^T [N,K] lo

// ---------------------------------------------------------------- helpers
__device__ __forceinline__ uint32_t smem_u32(const void* p) {
    uint32_t a;
    asm("{ .reg .u64 t; cvta.to.shared.u64 t, %1; cvt.u32.u64 %0, t; }" : "=r"(a) : "l"(p));
    return a;
}
__device__ __forceinline__ void cp16(uint32_t so, const void* g) {
    asm volatile("cp.async.cg.shared.global [%0], [%1], 16;" :: "r"(so), "l"(g));
}
#define CP_COMMIT() asm volatile("cp.async.commit_group;" ::: "memory")
#define CP_WAIT1()  asm volatile("cp.async.wait_group 1;" ::: "memory")

__device__ __forceinline__ void ldm_x4(uint32_t* r, uint32_t addr) {
    asm volatile("ldmatrix.sync.aligned.m8n8.x4.shared.b16 {%0,%1,%2,%3}, [%4];"
                 : "=r"(r[0]), "=r"(r[1]), "=r"(r[2]), "=r"(r[3]) : "r"(addr));
}
__device__ __forceinline__ void mma_bf16(float* c, const uint32_t* a, const uint32_t* b) {
    asm volatile(
        "mma.sync.aligned.m16n8k16.row.col.f32.bf16.bf16.f32 "
        "{%0,%1,%2,%3}, {%4,%5,%6,%7}, {%8,%9}, {%0,%1,%2,%3};"
        : "+f"(c[0]), "+f"(c[1]), "+f"(c[2]), "+f"(c[3])
        : "r"(a[0]), "r"(a[1]), "r"(a[2]), "r"(a[3]), "r"(b[0]), "r"(b[1]));
}

// ---------------------------------------------------------------- tensor GEMM
// C[M,N] = (Ah+Al)[M,K] @ (Bh+Bl)[N,K]^T + bias   (Al*Bl dropped)
__device__ __forceinline__ void tile_async(uint32_t sdst, const __nv_bfloat16* src,
                                           int row0, int k0, int K) {
    const int tid = threadIdx.x;
#pragma unroll
    for (int c = 0; c < 2; c++) {
        const int chunk = tid + c * 256;       // 0..511
        const int r = chunk >> 2, c16 = chunk & 3;
        cp16(sdst + (uint32_t)(r * (PAD_K * 2) + c16 * 16),
             src + (size_t)(row0 + r) * K + k0 + c16 * 8);
    }
}

__global__ __launch_bounds__(256, 1)
void gemm_tc(const __nv_bfloat16* __restrict__ Ah, const __nv_bfloat16* __restrict__ Al,
             const __nv_bfloat16* __restrict__ Bh, const __nv_bfloat16* __restrict__ Bl,
             const float* __restrict__ bias, float* __restrict__ C,
             int M, int N, int K)
{
    extern __shared__ char sm[];
    const uint32_t sb = smem_u32(sm);
    const int tid = threadIdx.x;
    const int wid = tid >> 5, lane = tid & 31;
    const int wm = wid & 1, wn = wid >> 1;          // 2 x 4 warp grid
    const int row0 = blockIdx.y * BM, col0 = blockIdx.x * BN;

    float acc[4][4][4];
#pragma unroll
    for (int i = 0; i < 4; i++)
#pragma unroll
        for (int j = 0; j < 4; j++)
#pragma unroll
            for (int t = 0; t < 4; t++) acc[i][j][t] = 0.f;

    // prologue: stages 0, 1
#pragma unroll
    for (int s = 0; s < 2; s++) {
        const uint32_t st = sb + s * STG;
        const int k0 = s * BK;
        tile_async(st + 0 * TILE_B, Ah, row0, k0, K);
        tile_async(st + 1 * TILE_B, Al, row0, k0, K);
        tile_async(st + 2 * TILE_B, Bh, col0, k0, K);
        tile_async(st + 3 * TILE_B, Bl, col0, k0, K);
        CP_COMMIT();
    }

    // ldmatrix address components (element offsets within a tile)
    const uint32_t a_row = (uint32_t)(wm * 64 + (lane & 15));
    const uint32_t a_kof = (uint32_t)((lane >> 4) * 8);
    const uint32_t b_row = (uint32_t)(wn * 32 + (lane & 7) + ((lane >> 4) << 3));
    const uint32_t b_kof = (uint32_t)(((lane >> 3) & 1) * 8);

    for (int it = 0; it < NKSTEP; it++) {
        CP_WAIT1();
        __syncthreads();

        if (it + 2 < NKSTEP) {
            const uint32_t st = sb + ((it + 2) % NSTAGE) * STG;
            const int k0 = (it + 2) * BK;
            tile_async(st + 0 * TILE_B, Ah, row0, k0, K);
            tile_async(st + 1 * TILE_B, Al, row0, k0, K);
            tile_async(st + 2 * TILE_B, Bh, col0, k0, K);
            tile_async(st + 3 * TILE_B, Bl, col0, k0, K);
        }
        CP_COMMIT();

        const uint32_t st = sb + (it % NSTAGE) * STG;
#pragma unroll
        for (int kk = 0; kk < BK; kk += 16) {
            uint32_t ah[4][4], al[4][4], bh[2][4], bl[2][4];
#pragma unroll
            for (int i = 0; i < 4; i++) {
                const uint32_t ao = ((a_row + i * 16) * PAD_K + kk + a_kof) * 2;
                ldm_x4(ah[i], st + 0 * TILE_B + ao);
                ldm_x4(al[i], st + 1 * TILE_B + ao);
            }
#pragma unroll
            for (int p = 0; p < 2; p++) {
                const uint32_t bo = ((b_row + p * 16) * PAD_K + kk + b_kof) * 2;
                ldm_x4(bh[p], st + 2 * TILE_B + bo);
                ldm_x4(bl[p], st + 3 * TILE_B + bo);
            }
#pragma unroll
            for (int i = 0; i < 4; i++)
#pragma unroll
                for (int j = 0; j < 4; j++) {
                    const uint32_t* bhf = &bh[j >> 1][(j & 1) * 2];
                    const uint32_t* blf = &bl[j >> 1][(j & 1) * 2];
                    mma_bf16(acc[i][j], ah[i], bhf);
                    mma_bf16(acc[i][j], ah[i], blf);
                    mma_bf16(acc[i][j], al[i], bhf);
                }
        }
        __syncthreads();
    }

    // epilogue
    const int rbase = row0 + wm * 64 + (lane >> 2);
    const int cbase = col0 + wn * 32 + (lane & 3) * 2;
#pragma unroll
    for (int i = 0; i < 4; i++)
#pragma unroll
        for (int j = 0; j < 4; j++) {
            const int cc = cbase + j * 8;
            const float b0 = bias[cc], b1 = bias[cc + 1];
#pragma unroll
            for (int hrow = 0; hrow < 2; hrow++) {
                const int rr = rbase + i * 16 + hrow * 8;
                float2 o;
                o.x = acc[i][j][hrow * 2 + 0] + b0;
                o.y = acc[i][j][hrow * 2 + 1] + b1;
                *(float2*)(C + (size_t)rr * N + cc) = o;
            }
        }
}

// ---------------------------------------------------------------- conversions
__global__ void split_f32(const float4* __restrict__ in, uint2* __restrict__ hi,
                          uint2* __restrict__ lo, int n4)
{
    const int i = blockIdx.x * blockDim.x + threadIdx.x;
    if (i >= n4) return;
    const float4 a = in[i];
    const __nv_bfloat16 h0 = __float2bfloat16(a.x), h1 = __float2bfloat16(a.y);
    const __nv_bfloat16 h2 = __float2bfloat16(a.z), h3 = __float2bfloat16(a.w);
    const __nv_bfloat16 l0 = __float2bfloat16(a.x - __bfloat162float(h0));
    const __nv_bfloat16 l1 = __float2bfloat16(a.y - __bfloat162float(h1));
    const __nv_bfloat16 l2 = __float2bfloat16(a.z - __bfloat162float(h2));
    const __nv_bfloat16 l3 = __float2bfloat16(a.w - __bfloat162float(h3));
    hi[i] = make_uint2((uint32_t)__bfloat16_as_ushort(h0) | ((uint32_t)__bfloat16_as_ushort(h1) << 16),
                       (uint32_t)__bfloat16_as_ushort(h2) | ((uint32_t)__bfloat16_as_ushort(h3) << 16));
    lo[i] = make_uint2((uint32_t)__bfloat16_as_ushort(l0) | ((uint32_t)__bfloat16_as_ushort(l1) << 16),
                       (uint32_t)__bfloat16_as_ushort(l2) | ((uint32_t)__bfloat16_as_ushort(l3) << 16));
}

// W[K,N] fp32 -> W^T[N,K] bf16 hi/lo
__global__ void wsplit(const float* __restrict__ W, __nv_bfloat16* __restrict__ th,
                       __nv_bfloat16* __restrict__ tl)
{
    __shared__ float t[32][33];
    const int n0 = blockIdx.x * 32, k0 = blockIdx.y * 32;
    const int tx = threadIdx.x, ty = threadIdx.y;
    for (int i = ty; i < 32; i += 8)
        t[i][tx] = W[(size_t)(k0 + i) * NDIM + n0 + tx];
    __syncthreads();
    for (int i = ty; i < 32; i += 8) {
        const float a = t[tx][i];
        const __nv_bfloat16 h = __float2bfloat16(a);
        const size_t o = (size_t)(n0 + i) * KDIM + k0 + tx;
        th[o] = h;
        tl[o] = __float2bfloat16(a - __bfloat162float(h));
    }
}

// ---------------------------------------------------------------- attention
__global__ __launch_bounds__(128) void attn_kernel(
    const float* __restrict__ q, const float* __restrict__ k,
    const float* __restrict__ v, const float* __restrict__ decay,
    __nv_bfloat16* __restrict__ aoh, __nv_bfloat16* __restrict__ aol)
{
    const int c = blockIdx.x, h = blockIdx.y, b = blockIdx.z;
    const int tid = threadIdx.x;

    extern __shared__ float smf[];
    float* kf = smf;
    float* vf = smf + 129 * 64;

    const size_t base = ((size_t)b * L_SZ + (size_t)c * CHUNK) * D_MODEL + h * D_HEAD;

    for (int idx = tid; idx < 129 * 64; idx += 128) {
        const int j = idx >> 6, d = idx & 63;
        float kk = 0.f, vv = 0.f;
        if (j > 0 || c > 0) {
            const size_t g = base + (size_t)(j - 1) * D_MODEL + d;
            kk = k[g]; vv = v[g];
        }
        kf[idx] = kk; vf[idx] = vv;
    }
    __syncthreads();

    float qreg[64];
    const float* qp = q + base + (size_t)tid * D_MODEL;
#pragma unroll
    for (int d = 0; d < 64; d++) qreg[d] = qp[d];

    const float sf = 0.125f * powf(decay[h], (float)tid);

    float m = -1e30f, l = 0.f;
    float o[64];
#pragma unroll
    for (int d = 0; d < 64; d++) o[d] = 0.f;

    for (int j = 0; j < 129; j++) {
        const float* kj = kf + j * 64;
        float s = 0.f;
#pragma unroll
        for (int d = 0; d < 64; d++) s = fmaf(qreg[d], kj[d], s);
        s *= sf;
        const float mnew = fmaxf(m, s);
        const float corr = __expf(m - mnew);
        const float p    = __expf(s - mnew);
        l = l * corr + p;
        const float* vj = vf + j * 64;
#pragma unroll
        for (int d = 0; d < 64; d++) o[d] = fmaf(p, vj[d], o[d] * corr);
        m = mnew;
    }

    const float inv = 1.f / l;
    __nv_bfloat16* oh = aoh + base + (size_t)tid * D_MODEL;
    __nv_bfloat16* ol = aol + base + (size_t)tid * D_MODEL;
#pragma unroll
    for (int d = 0; d < 64; d++) {
        const float val = o[d] * inv;
        const __nv_bfloat16 hh = __float2bfloat16(val);
        oh[d] = hh;
        ol[d] = __float2bfloat16(val - __bfloat162float(hh));
    }
}

// ---------------------------------------------------------------- launch
extern "C" void kernel_launch(void* const* d_in, const int* in_sizes, int n_in,
                              void* d_out, int out_size)
{
    const float* x     = (const float*)d_in[0];
    const float* Wq    = (const float*)d_in[1];
    const float* bq    = (const float*)d_in[2];
    const float* Wk    = (const float*)d_in[3];
    const float* bk    = (const float*)d_in[4];
    const float* Wv    = (const float*)d_in[5];
    const float* bv    = (const float*)d_in[6];
    const float* Wo    = (const float*)d_in[7];
    const float* bo    = (const float*)d_in[8];
    const float* decay = (const float*)d_in[9];
    float* out = (float*)d_out;

    float *q, *k, *v;
    __nv_bfloat16 *xh, *xl, *aoh, *aol, *wth, *wtl;
    cudaGetSymbolAddress((void**)&q,   g_q);
    cudaGetSymbolAddress((void**)&k,   g_k);
    cudaGetSymbolAddress((void**)&v,   g_v);
    cudaGetSymbolAddress((void**)&xh,  g_xh);
    cudaGetSymbolAddress((void**)&xl,  g_xl);
    cudaGetSymbolAddress((void**)&aoh, g_aoh);
    cudaGetSymbolAddress((void**)&aol, g_aol);
    cudaGetSymbolAddress((void**)&wth, g_wth);
    cudaGetSymbolAddress((void**)&wtl, g_wtl);

    cudaFuncSetAttribute(gemm_tc, cudaFuncAttributeMaxDynamicSharedMemorySize, GSMEM);
    const int smem_attn = 2 * 129 * 64 * (int)sizeof(float);
    cudaFuncSetAttribute(attn_kernel, cudaFuncAttributeMaxDynamicSharedMemorySize, smem_attn);

    // weight transpose + split
    dim3 wgrid(NDIM / 32, KDIM / 32), wblk(32, 8);
    wsplit<<<wgrid, wblk>>>(Wq, wth + 0 * WSL, wtl + 0 * WSL);
    wsplit<<<wgrid, wblk>>>(Wk, wth + 1 * WSL, wtl + 1 * WSL);
    wsplit<<<wgrid, wblk>>>(Wv, wth + 2 * WSL, wtl + 2 * WSL);
    wsplit<<<wgrid, wblk>>>(Wo, wth + 3 * WSL, wtl + 3 * WSL);

    // x split
    const int n4 = M_TOT * D_MODEL / 4;
    split_f32<<<(n4 + 255) / 256, 256>>>((const float4*)x, (uint2*)xh, (uint2*)xl, n4);

    dim3 ggrid(NDIM / BN, M_TOT / BM);   // (8, 128)
    gemm_tc<<<ggrid, 256, GSMEM>>>(xh, xl, wth + 0 * WSL, wtl + 0 * WSL, bq, q, M_TOT, NDIM, KDIM);
    gemm_tc<<<ggrid, 256, GSMEM>>>(xh, xl, wth + 1 * WSL, wtl + 1 * WSL, bk, k, M_TOT, NDIM, KDIM);
    gemm_tc<<<ggrid, 256, GSMEM>>>(xh, xl, wth + 2 * WSL, wtl + 2 * WSL, bv, v, M_TOT, NDIM, KDIM);

    attn_kernel<<<dim3(NCHUNK, N_HEADS, B_SZ), 128, smem_attn>>>(q, k, v, decay, aoh, aol);

    gemm_tc<<<ggrid, 256, GSMEM>>>(aoh, aol, wth + 3 * WSL, wtl + 3 * WSL, bo, out, M_TOT, NDIM, KDIM);
}

// round 6
// speedup vs baseline: 1.8978x; 1.0515x over previous
#include <cuda_runtime.h>
#include <cuda_bf16.h>
#include <cuda_fp16.h>
#include <math.h>
#include <stdint.h>

// ---------------------------------------------------------------- constants
#define B_SZ 4
#define L_SZ 4096
#define D_MODEL 1024
#define N_HEADS 16
#define D_HEAD 64
#define CHUNK 128
#define NCHUNK 32
#define M_TOT (B_SZ * L_SZ)      // 16384
#define KDIM 1024
#define NDIM 1024
#define WSL (KDIM * NDIM)

// GEMM tiling
#define BM 128
#define BN 128
#define BK 32
#define NKSTEP (KDIM / BK)       // 32
#define PAD_K 40
#define TILE_B (128 * PAD_K * 2)
#define STG (4 * TILE_B)
#define NSTAGE 3
#define GSMEM (NSTAGE * STG)     // 122880

// attention smem layout (bytes)
#define AT_QH 0                   // Qh bf16 [128][72]
#define AT_QL 18432               // Ql
#define AT_KH 36864               // Kh bf16 [144][72]
#define AT_KL 57600               // Kl
#define AT_VH 78336               // Vth fp16 [64][152]
#define AT_VL 97792               // Vtl
#define AT_DF 117248              // decay factor / 1/l, 128 f32
#define AT_S  117760              // S f32 [128][168]; reused Ph/Pl fp16 per-row
#define SPITCH 168                // floats per S row (672 B, bank-rotating)
#define PL_OFF 336                // Pl byte offset within a row
#define AT_SZ (AT_S + 128 * SPITCH * 4)   // 203776

// ---------------------------------------------------------------- scratch
__device__ float g_q[M_TOT * D_MODEL];
__device__ float g_k[M_TOT * D_MODEL];
__device__ float g_v[M_TOT * D_MODEL];
__device__ __nv_bfloat16 g_xh[M_TOT * D_MODEL];
__device__ __nv_bfloat16 g_xl[M_TOT * D_MODEL];
__device__ __nv_bfloat16 g_aoh[M_TOT * D_MODEL];
__device__ __nv_bfloat16 g_aol[M_TOT * D_MODEL];
__device__ __nv_bfloat16 g_wth[4 * WSL];
__device__ __nv_bfloat16 g_wtl[4 * WSL];

// ---------------------------------------------------------------- helpers
__device__ __forceinline__ uint32_t smem_u32(const void* p) {
    uint32_t a;
    asm("{ .reg .u64 t; cvta.to.shared.u64 t, %1; cvt.u32.u64 %0, t; }" : "=r"(a) : "l"(p));
    return a;
}
__device__ __forceinline__ void cp16(uint32_t so, const void* g) {
    asm volatile("cp.async.cg.shared.global [%0], [%1], 16;" :: "r"(so), "l"(g));
}
#define CP_COMMIT() asm volatile("cp.async.commit_group;" ::: "memory")
#define CP_WAIT1()  asm volatile("cp.async.wait_group 1;" ::: "memory")

__device__ __forceinline__ void ldm_x4(uint32_t* r, uint32_t addr) {
    asm volatile("ldmatrix.sync.aligned.m8n8.x4.shared.b16 {%0,%1,%2,%3}, [%4];"
                 : "=r"(r[0]), "=r"(r[1]), "=r"(r[2]), "=r"(r[3]) : "r"(addr));
}
__device__ __forceinline__ void mma_bf16(float* c, const uint32_t* a, const uint32_t* b) {
    asm volatile(
        "mma.sync.aligned.m16n8k16.row.col.f32.bf16.bf16.f32 "
        "{%0,%1,%2,%3}, {%4,%5,%6,%7}, {%8,%9}, {%0,%1,%2,%3};"
        : "+f"(c[0]), "+f"(c[1]), "+f"(c[2]), "+f"(c[3])
        : "r"(a[0]), "r"(a[1]), "r"(a[2]), "r"(a[3]), "r"(b[0]), "r"(b[1]));
}
__device__ __forceinline__ void mma_f16(float* c, const uint32_t* a, const uint32_t* b) {
    asm volatile(
        "mma.sync.aligned.m16n8k16.row.col.f32.f16.f16.f32 "
        "{%0,%1,%2,%3}, {%4,%5,%6,%7}, {%8,%9}, {%0,%1,%2,%3};"
        : "+f"(c[0]), "+f"(c[1]), "+f"(c[2]), "+f"(c[3])
        : "r"(a[0]), "r"(a[1]), "r"(a[2]), "r"(a[3]), "r"(b[0]), "r"(b[1]));
}

// ---------------------------------------------------------------- tensor GEMM
__device__ __forceinline__ void tile_async(uint32_t sdst, const __nv_bfloat16* src,
                                           int row0, int k0, int K) {
    const int tid = threadIdx.x;
#pragma unroll
    for (int c = 0; c < 2; c++) {
        const int chunk = tid + c * 256;
        const int r = chunk >> 2, c16 = chunk & 3;
        cp16(sdst + (uint32_t)(r * (PAD_K * 2) + c16 * 16),
             src + (size_t)(row0 + r) * K + k0 + c16 * 8);
    }
}

__global__ __launch_bounds__(256, 1)
void gemm_tc(const __nv_bfloat16* __restrict__ Ah, const __nv_bfloat16* __restrict__ Al,
             const __nv_bfloat16* __restrict__ Bh, const __nv_bfloat16* __restrict__ Bl,
             const float* __restrict__ bias, float* __restrict__ C,
             int M, int N, int K)
{
    extern __shared__ char sm[];
    const uint32_t sb = smem_u32(sm);
    const int tid = threadIdx.x;
    const int wid = tid >> 5, lane = tid & 31;
    const int wm = wid & 1, wn = wid >> 1;
    const int row0 = blockIdx.y * BM, col0 = blockIdx.x * BN;

    float acc[4][4][4];
#pragma unroll
    for (int i = 0; i < 4; i++)
#pragma unroll
        for (int j = 0; j < 4; j++)
#pragma unroll
            for (int t = 0; t < 4; t++) acc[i][j][t] = 0.f;

#pragma unroll
    for (int s = 0; s < 2; s++) {
        const uint32_t st = sb + s * STG;
        const int k0 = s * BK;
        tile_async(st + 0 * TILE_B, Ah, row0, k0, K);
        tile_async(st + 1 * TILE_B, Al, row0, k0, K);
        tile_async(st + 2 * TILE_B, Bh, col0, k0, K);
        tile_async(st + 3 * TILE_B, Bl, col0, k0, K);
        CP_COMMIT();
    }

    const uint32_t a_row = (uint32_t)(wm * 64 + (lane & 15));
    const uint32_t a_kof = (uint32_t)((lane >> 4) * 8);
    const uint32_t b_row = (uint32_t)(wn * 32 + (lane & 7) + ((lane >> 4) << 3));
    const uint32_t b_kof = (uint32_t)(((lane >> 3) & 1) * 8);

    for (int it = 0; it < NKSTEP; it++) {
        CP_WAIT1();
        __syncthreads();

        if (it + 2 < NKSTEP) {
            const uint32_t st = sb + ((it + 2) % NSTAGE) * STG;
            const int k0 = (it + 2) * BK;
            tile_async(st + 0 * TILE_B, Ah, row0, k0, K);
            tile_async(st + 1 * TILE_B, Al, row0, k0, K);
            tile_async(st + 2 * TILE_B, Bh, col0, k0, K);
            tile_async(st + 3 * TILE_B, Bl, col0, k0, K);
        }
        CP_COMMIT();

        const uint32_t st = sb + (it % NSTAGE) * STG;
#pragma unroll
        for (int kk = 0; kk < BK; kk += 16) {
            uint32_t ah[4][4], al[4][4], bh[2][4], bl[2][4];
#pragma unroll
            for (int i = 0; i < 4; i++) {
                const uint32_t ao = ((a_row + i * 16) * PAD_K + kk + a_kof) * 2;
                ldm_x4(ah[i], st + 0 * TILE_B + ao);
                ldm_x4(al[i], st + 1 * TILE_B + ao);
            }
#pragma unroll
            for (int p = 0; p < 2; p++) {
                const uint32_t bo = ((b_row + p * 16) * PAD_K + kk + b_kof) * 2;
                ldm_x4(bh[p], st + 2 * TILE_B + bo);
                ldm_x4(bl[p], st + 3 * TILE_B + bo);
            }
#pragma unroll
            for (int i = 0; i < 4; i++)
#pragma unroll
                for (int j = 0; j < 4; j++) {
                    const uint32_t* bhf = &bh[j >> 1][(j & 1) * 2];
                    const uint32_t* blf = &bl[j >> 1][(j & 1) * 2];
                    mma_bf16(acc[i][j], ah[i], bhf);
                    mma_bf16(acc[i][j], ah[i], blf);
                    mma_bf16(acc[i][j], al[i], bhf);
                }
        }
        __syncthreads();
    }

    const int rbase = row0 + wm * 64 + (lane >> 2);
    const int cbase = col0 + wn * 32 + (lane & 3) * 2;
#pragma unroll
    for (int i = 0; i < 4; i++)
#pragma unroll
        for (int j = 0; j < 4; j++) {
            const int cc = cbase + j * 8;
            const float b0 = bias[cc], b1 = bias[cc + 1];
#pragma unroll
            for (int hrow = 0; hrow < 2; hrow++) {
                const int rr = rbase + i * 16 + hrow * 8;
                float2 o;
                o.x = acc[i][j][hrow * 2 + 0] + b0;
                o.y = acc[i][j][hrow * 2 + 1] + b1;
                *(float2*)(C + (size_t)rr * N + cc) = o;
            }
        }
}

// ---------------------------------------------------------------- conversions
__global__ void split_f32(const float4* __restrict__ in, uint2* __restrict__ hi,
                          uint2* __restrict__ lo, int n4)
{
    const int i = blockIdx.x * blockDim.x + threadIdx.x;
    if (i >= n4) return;
    const float4 a = in[i];
    const __nv_bfloat16 h0 = __float2bfloat16(a.x), h1 = __float2bfloat16(a.y);
    const __nv_bfloat16 h2 = __float2bfloat16(a.z), h3 = __float2bfloat16(a.w);
    const __nv_bfloat16 l0 = __float2bfloat16(a.x - __bfloat162float(h0));
    const __nv_bfloat16 l1 = __float2bfloat16(a.y - __bfloat162float(h1));
    const __nv_bfloat16 l2 = __float2bfloat16(a.z - __bfloat162float(h2));
    const __nv_bfloat16 l3 = __float2bfloat16(a.w - __bfloat162float(h3));
    hi[i] = make_uint2((uint32_t)__bfloat16_as_ushort(h0) | ((uint32_t)__bfloat16_as_ushort(h1) << 16),
                       (uint32_t)__bfloat16_as_ushort(h2) | ((uint32_t)__bfloat16_as_ushort(h3) << 16));
    lo[i] = make_uint2((uint32_t)__bfloat16_as_ushort(l0) | ((uint32_t)__bfloat16_as_ushort(l1) << 16),
                       (uint32_t)__bfloat16_as_ushort(l2) | ((uint32_t)__bfloat16_as_ushort(l3) << 16));
}

__global__ void wsplit(const float* __restrict__ W, __nv_bfloat16* __restrict__ th,
                       __nv_bfloat16* __restrict__ tl)
{
    __shared__ float t[32][33];
    const int n0 = blockIdx.x * 32, k0 = blockIdx.y * 32;
    const int tx = threadIdx.x, ty = threadIdx.y;
    for (int i = ty; i < 32; i += 8)
        t[i][tx] = W[(size_t)(k0 + i) * NDIM + n0 + tx];
    __syncthreads();
    for (int i = ty; i < 32; i += 8) {
        const float a = t[tx][i];
        const __nv_bfloat16 h = __float2bfloat16(a);
        const size_t o = (size_t)(n0 + i) * KDIM + k0 + tx;
        th[o] = h;
        tl[o] = __float2bfloat16(a - __bfloat162float(h));
    }
}

// ---------------------------------------------------------------- attention (tensor core)
// One block per (chunk, head, batch). 128 threads = 4 warps; warp w owns rows
// w*32..w*32+31. S = Q Kf^T (bf16 hi/lo, 3 products) -> smem fp32 -> softmax
// with decay prefactor -> P (fp16 hi/lo, in-place over S) -> O = P Vf (3
// products) -> scale by 1/l -> aoh/aol.
__global__ __launch_bounds__(128, 1) void attn_tc(
    const float* __restrict__ q, const float* __restrict__ k,
    const float* __restrict__ v, const float* __restrict__ decay,
    __nv_bfloat16* __restrict__ aoh, __nv_bfloat16* __restrict__ aol)
{
    const int c = blockIdx.x, h = blockIdx.y, b = blockIdx.z;
    const int tid = threadIdx.x, wm = tid >> 5, lane = tid & 31;

    extern __shared__ char sma[];
    const uint32_t sb = smem_u32(sma);
    __nv_bfloat16* Qh = (__nv_bfloat16*)(sma + AT_QH);
    __nv_bfloat16* Ql = (__nv_bfloat16*)(sma + AT_QL);
    __nv_bfloat16* Kh = (__nv_bfloat16*)(sma + AT_KH);
    __nv_bfloat16* Kl = (__nv_bfloat16*)(sma + AT_KL);
    __half* Vh = (__half*)(sma + AT_VH);
    __half* Vl = (__half*)(sma + AT_VL);
    float* df = (float*)(sma + AT_DF);
    float* S  = (float*)(sma + AT_S);

    const size_t base = ((size_t)b * L_SZ + (size_t)c * CHUNK) * D_MODEL + h * D_HEAD;

    // zero Vt regions (pad cols) and K pad rows 129..143
    {
        uint4 z = make_uint4(0, 0, 0, 0);
        uint4* vz = (uint4*)(sma + AT_VH);
        for (int i = tid; i < (2 * 64 * 152 * 2) / 16; i += 128) vz[i] = z;
        for (int i = tid; i < 15 * 72; i += 128) {
            Kh[129 * 72 + i] = __float2bfloat16(0.f);
            Kl[129 * 72 + i] = __float2bfloat16(0.f);
        }
    }
    __syncthreads();

    // load Q
    for (int idx = tid; idx < 128 * 64; idx += 128) {
        const int r = idx >> 6, d = idx & 63;
        const float val = q[base + (size_t)r * D_MODEL + d];
        const __nv_bfloat16 hh = __float2bfloat16(val);
        Qh[r * 72 + d] = hh;
        Ql[r * 72 + d] = __float2bfloat16(val - __bfloat162float(hh));
    }
    // load Kf, Vf (row j: j==0 -> prev chunk last token or zeros)
    for (int idx = tid; idx < 129 * 64; idx += 128) {
        const int j = idx >> 6, d = idx & 63;
        float kk = 0.f, vv = 0.f;
        if (j > 0 || c > 0) {
            const size_t g = base + (size_t)(j - 1) * D_MODEL + d;
            kk = k[g]; vv = v[g];
        }
        const __nv_bfloat16 kh = __float2bfloat16(kk);
        Kh[j * 72 + d] = kh;
        Kl[j * 72 + d] = __float2bfloat16(kk - __bfloat162float(kh));
        const __half vh = __float2half_rn(vv);
        Vh[d * 152 + j] = vh;
        Vl[d * 152 + j] = __float2half_rn(vv - __half2float(vh));
    }
    df[tid] = 0.125f * powf(decay[h], (float)tid);
    __syncthreads();

    // ---------------- S = Q Kf^T ----------------
    const uint32_t a_ro = (uint32_t)(lane & 15);
    const uint32_t a_ko = (uint32_t)((lane >> 4) * 8);
    const uint32_t b_ro = (uint32_t)((lane & 7) + ((lane >> 4) << 3));
    const uint32_t b_ko = (uint32_t)(((lane >> 3) & 1) * 8);

    uint32_t qh[2][4][4], ql[2][4][4];
#pragma unroll
    for (int mt = 0; mt < 2; mt++)
#pragma unroll
        for (int kt = 0; kt < 4; kt++) {
            const uint32_t ao = ((wm * 32 + mt * 16 + a_ro) * 72 + kt * 16 + a_ko) * 2;
            ldm_x4(qh[mt][kt], sb + AT_QH + ao);
            ldm_x4(ql[mt][kt], sb + AT_QL + ao);
        }

#pragma unroll
    for (int nt = 0; nt < 9; nt++) {              // 9 n16 groups -> 144 cols
        uint32_t kh[4][4], kl[4][4];
#pragma unroll
        for (int kt = 0; kt < 4; kt++) {
            const uint32_t bo = ((nt * 16 + b_ro) * 72 + kt * 16 + b_ko) * 2;
            ldm_x4(kh[kt], sb + AT_KH + bo);
            ldm_x4(kl[kt], sb + AT_KL + bo);
        }
#pragma unroll
        for (int mt = 0; mt < 2; mt++)
#pragma unroll
            for (int half = 0; half < 2; half++) {
                float acc[4] = {0.f, 0.f, 0.f, 0.f};
#pragma unroll
                for (int kt = 0; kt < 4; kt++) {
                    mma_bf16(acc, qh[mt][kt], &kh[kt][half * 2]);
                    mma_bf16(acc, qh[mt][kt], &kl[kt][half * 2]);
                    mma_bf16(acc, ql[mt][kt], &kh[kt][half * 2]);
                }
                const int r0 = wm * 32 + mt * 16 + (lane >> 2);
                const int c0 = nt * 16 + half * 8 + (lane & 3) * 2;
                *(float2*)&S[r0 * SPITCH + c0]       = make_float2(acc[0], acc[1]);
                *(float2*)&S[(r0 + 8) * SPITCH + c0] = make_float2(acc[2], acc[3]);
            }
    }
    __syncwarp();

    // ---------------- softmax rows (warp-cooperative) ----------------
    for (int rr = 0; rr < 32; rr++) {
        const int row = wm * 32 + rr;
        const float sf = df[row];
        float sv[5];
        float mx = -1e30f;
#pragma unroll
        for (int i = 0; i < 5; i++) {
            const int j = lane + 32 * i;
            sv[i] = (j < 129) ? S[row * SPITCH + j] * sf : -1e30f;
            mx = fmaxf(mx, sv[i]);
        }
#pragma unroll
        for (int off = 16; off > 0; off >>= 1)
            mx = fmaxf(mx, __shfl_xor_sync(0xFFFFFFFFu, mx, off));
        float lsum = 0.f;
        float pv[5];
#pragma unroll
        for (int i = 0; i < 5; i++) {
            pv[i] = __expf(sv[i] - mx);        // exp(-huge)=0 for padded
            lsum += pv[i];
        }
#pragma unroll
        for (int off = 16; off > 0; off >>= 1)
            lsum += __shfl_xor_sync(0xFFFFFFFFu, lsum, off);
        // write unnormalized P (fp16 hi/lo) in place over this row
        char* prow = sma + AT_S + row * (SPITCH * 4);
#pragma unroll
        for (int i = 0; i < 5; i++) {
            const int j = lane + 32 * i;
            if (j < 144) {
                const float p = (j < 129) ? pv[i] : 0.f;
                const __half ph = __float2half_rn(p);
                ((__half*)prow)[j] = ph;
                ((__half*)(prow + PL_OFF))[j] = __float2half_rn(p - __half2float(ph));
            }
        }
        if (lane == 0) df[row] = 1.f / lsum;
    }
    __syncwarp();

    // ---------------- O = P Vf ----------------
    float oacc[2][8][4];
#pragma unroll
    for (int mt = 0; mt < 2; mt++)
#pragma unroll
        for (int n8 = 0; n8 < 8; n8++)
#pragma unroll
            for (int t = 0; t < 4; t++) oacc[mt][n8][t] = 0.f;

#pragma unroll
    for (int kt = 0; kt < 9; kt++) {              // K = 144
        uint32_t ph[2][4], pl[2][4];
#pragma unroll
        for (int mt = 0; mt < 2; mt++) {
            const uint32_t ao = AT_S + (wm * 32 + mt * 16 + a_ro) * (SPITCH * 4)
                              + (kt * 16 + a_ko) * 2;
            ldm_x4(ph[mt], sb + ao);
            ldm_x4(pl[mt], sb + ao + PL_OFF);
        }
        uint32_t vh[4][4], vl[4][4];
#pragma unroll
        for (int g = 0; g < 4; g++) {
            const uint32_t bo = ((g * 16 + b_ro) * 152 + kt * 16 + b_ko) * 2;
            ldm_x4(vh[g], sb + AT_VH + bo);
            ldm_x4(vl[g], sb + AT_VL + bo);
        }
#pragma unroll
        for (int mt = 0; mt < 2; mt++)
#pragma unroll
            for (int n8 = 0; n8 < 8; n8++) {
                const uint32_t* bh = &vh[n8 >> 1][(n8 & 1) * 2];
                const uint32_t* bl = &vl[n8 >> 1][(n8 & 1) * 2];
                mma_f16(oacc[mt][n8], ph[mt], bh);
                mma_f16(oacc[mt][n8], ph[mt], bl);
                mma_f16(oacc[mt][n8], pl[mt], bh);
            }
    }
    __syncwarp();

    // epilogue: scale by 1/l, hi/lo split, store
#pragma unroll
    for (int mt = 0; mt < 2; mt++) {
        const int r0 = wm * 32 + mt * 16 + (lane >> 2);
        const float inv0 = df[r0], inv1 = df[r0 + 8];
#pragma unroll
        for (int n8 = 0; n8 < 8; n8++) {
            const int c0 = n8 * 8 + (lane & 3) * 2;
#pragma unroll
            for (int hrow = 0; hrow < 2; hrow++) {
                const int rr = r0 + hrow * 8;
                const float inv = hrow ? inv1 : inv0;
#pragma unroll
                for (int cc = 0; cc < 2; cc++) {
                    const float val = oacc[mt][n8][hrow * 2 + cc] * inv;
                    const __nv_bfloat16 hh = __float2bfloat16(val);
                    const size_t o = base + (size_t)rr * D_MODEL + c0 + cc;
                    aoh[o] = hh;
                    aol[o] = __float2bfloat16(val - __bfloat162float(hh));
                }
            }
        }
    }
}

// ---------------------------------------------------------------- launch
extern "C" void kernel_launch(void* const* d_in, const int* in_sizes, int n_in,
                              void* d_out, int out_size)
{
    const float* x     = (const float*)d_in[0];
    const float* Wq    = (const float*)d_in[1];
    const float* bq    = (const float*)d_in[2];
    const float* Wk    = (const float*)d_in[3];
    const float* bk    = (const float*)d_in[4];
    const float* Wv    = (const float*)d_in[5];
    const float* bv    = (const float*)d_in[6];
    const float* Wo    = (const float*)d_in[7];
    const float* bo    = (const float*)d_in[8];
    const float* decay = (const float*)d_in[9];
    float* out = (float*)d_out;

    float *q, *k, *v;
    __nv_bfloat16 *xh, *xl, *aoh, *aol, *wth, *wtl;
    cudaGetSymbolAddress((void**)&q,   g_q);
    cudaGetSymbolAddress((void**)&k,   g_k);
    cudaGetSymbolAddress((void**)&v,   g_v);
    cudaGetSymbolAddress((void**)&xh,  g_xh);
    cudaGetSymbolAddress((void**)&xl,  g_xl);
    cudaGetSymbolAddress((void**)&aoh, g_aoh);
    cudaGetSymbolAddress((void**)&aol, g_aol);
    cudaGetSymbolAddress((void**)&wth, g_wth);
    cudaGetSymbolAddress((void**)&wtl, g_wtl);

    cudaFuncSetAttribute(gemm_tc, cudaFuncAttributeMaxDynamicSharedMemorySize, GSMEM);
    cudaFuncSetAttribute(attn_tc, cudaFuncAttributeMaxDynamicSharedMemorySize, AT_SZ);

    dim3 wgrid(NDIM / 32, KDIM / 32), wblk(32, 8);
    wsplit<<<wgrid, wblk>>>(Wq, wth + 0 * WSL, wtl + 0 * WSL);
    wsplit<<<wgrid, wblk>>>(Wk, wth + 1 * WSL, wtl + 1 * WSL);
    wsplit<<<wgrid, wblk>>>(Wv, wth + 2 * WSL, wtl + 2 * WSL);
    wsplit<<<wgrid, wblk>>>(Wo, wth + 3 * WSL, wtl + 3 * WSL);

    const int n4 = M_TOT * D_MODEL / 4;
    split_f32<<<(n4 + 255) / 256, 256>>>((const float4*)x, (uint2*)xh, (uint2*)xl, n4);

    dim3 ggrid(NDIM / BN, M_TOT / BM);
    gemm_tc<<<ggrid, 256, GSMEM>>>(xh, xl, wth + 0 * WSL, wtl + 0 * WSL, bq, q, M_TOT, NDIM, KDIM);
    gemm_tc<<<ggrid, 256, GSMEM>>>(xh, xl, wth + 1 * WSL, wtl + 1 * WSL, bk, k, M_TOT, NDIM, KDIM);
    gemm_tc<<<ggrid, 256, GSMEM>>>(xh, xl, wth + 2 * WSL, wtl + 2 * WSL, bv, v, M_TOT, NDIM, KDIM);

    attn_tc<<<dim3(NCHUNK, N_HEADS, B_SZ), 128, AT_SZ>>>(q, k, v, decay, aoh, aol);

    gemm_tc<<<ggrid, 256, GSMEM>>>(aoh, aol, wth + 3 * WSL, wtl + 3 * WSL, bo, out, M_TOT, NDIM, KDIM);
}

// round 7
// speedup vs baseline: 2.3203x; 1.2226x over previous
#include <cuda_runtime.h>
#include <cuda_bf16.h>
#include <cuda_fp16.h>
#include <math.h>
#include <stdint.h>

// ---------------------------------------------------------------- constants
#define B_SZ 4
#define L_SZ 4096
#define D_MODEL 1024
#define N_HEADS 16
#define D_HEAD 64
#define CHUNK 128
#define NCHUNK 32
#define M_TOT (B_SZ * L_SZ)      // 16384
#define KDIM 1024
#define NDIM 1024
#define WSL (KDIM * NDIM)

// GEMM tiling
#define BM 128
#define BN 128
#define BK 32
#define NKSTEP (KDIM / BK)       // 32
#define PAD_K 40
#define TILE_B (128 * PAD_K * 2) // 10240 B per 128x32 fp16 tile
#define STG (3 * TILE_B)         // Ah, Al, B per stage = 30720
#define NSTAGE 3
#define GSMEM (NSTAGE * STG)     // 92160

// attention smem layout (bytes) — unchanged from R5
#define AT_QH 0
#define AT_QL 18432
#define AT_KH 36864
#define AT_KL 57600
#define AT_VH 78336
#define AT_VL 97792
#define AT_DF 117248
#define AT_S  117760
#define SPITCH 168
#define PL_OFF 336
#define AT_SZ (AT_S + 128 * SPITCH * 4)   // 203776

// ---------------------------------------------------------------- scratch
__device__ float g_q[M_TOT * D_MODEL];
__device__ float g_k[M_TOT * D_MODEL];
__device__ float g_v[M_TOT * D_MODEL];
__device__ __half g_xh[M_TOT * D_MODEL];
__device__ __half g_xl[M_TOT * D_MODEL];
__device__ __half g_aoh[M_TOT * D_MODEL];
__device__ __half g_aol[M_TOT * D_MODEL];
__device__ __half g_wt[4 * WSL];           // W^T [N,K] fp16 (single)

// ---------------------------------------------------------------- helpers
__device__ __forceinline__ uint32_t smem_u32(const void* p) {
    uint32_t a;
    asm("{ .reg .u64 t; cvta.to.shared.u64 t, %1; cvt.u32.u64 %0, t; }" : "=r"(a) : "l"(p));
    return a;
}
__device__ __forceinline__ void cp16(uint32_t so, const void* g) {
    asm volatile("cp.async.cg.shared.global [%0], [%1], 16;" :: "r"(so), "l"(g));
}
#define CP_COMMIT() asm volatile("cp.async.commit_group;" ::: "memory")
#define CP_WAIT1()  asm volatile("cp.async.wait_group 1;" ::: "memory")

__device__ __forceinline__ void ldm_x4(uint32_t* r, uint32_t addr) {
    asm volatile("ldmatrix.sync.aligned.m8n8.x4.shared.b16 {%0,%1,%2,%3}, [%4];"
                 : "=r"(r[0]), "=r"(r[1]), "=r"(r[2]), "=r"(r[3]) : "r"(addr));
}
__device__ __forceinline__ void mma_bf16(float* c, const uint32_t* a, const uint32_t* b) {
    asm volatile(
        "mma.sync.aligned.m16n8k16.row.col.f32.bf16.bf16.f32 "
        "{%0,%1,%2,%3}, {%4,%5,%6,%7}, {%8,%9}, {%0,%1,%2,%3};"
        : "+f"(c[0]), "+f"(c[1]), "+f"(c[2]), "+f"(c[3])
        : "r"(a[0]), "r"(a[1]), "r"(a[2]), "r"(a[3]), "r"(b[0]), "r"(b[1]));
}
__device__ __forceinline__ void mma_f16(float* c, const uint32_t* a, const uint32_t* b) {
    asm volatile(
        "mma.sync.aligned.m16n8k16.row.col.f32.f16.f16.f32 "
        "{%0,%1,%2,%3}, {%4,%5,%6,%7}, {%8,%9}, {%0,%1,%2,%3};"
        : "+f"(c[0]), "+f"(c[1]), "+f"(c[2]), "+f"(c[3])
        : "r"(a[0]), "r"(a[1]), "r"(a[2]), "r"(a[3]), "r"(b[0]), "r"(b[1]));
}

// ---------------------------------------------------------------- tensor GEMM
// C[M,N] = (Ah+Al)[M,K] @ B[N,K]^T + bias,  A fp16 hi/lo, B single fp16.
__device__ __forceinline__ void tile_async(uint32_t sdst, const __half* src,
                                           int row0, int k0, int K) {
    const int tid = threadIdx.x;
#pragma unroll
    for (int c = 0; c < 2; c++) {
        const int chunk = tid + c * 256;
        const int r = chunk >> 2, c16 = chunk & 3;
        cp16(sdst + (uint32_t)(r * (PAD_K * 2) + c16 * 16),
             src + (size_t)(row0 + r) * K + k0 + c16 * 8);
    }
}

__global__ __launch_bounds__(256, 1)
void gemm_tc(const __half* __restrict__ Ah, const __half* __restrict__ Al,
             const __half* __restrict__ Bw,
             const float* __restrict__ bias, float* __restrict__ C,
             int M, int N, int K)
{
    extern __shared__ char sm[];
    const uint32_t sb = smem_u32(sm);
    const int tid = threadIdx.x;
    const int wid = tid >> 5, lane = tid & 31;
    const int wm = wid & 1, wn = wid >> 1;          // 2 x 4 warp grid
    const int row0 = blockIdx.y * BM, col0 = blockIdx.x * BN;

    float acc[4][4][4];
#pragma unroll
    for (int i = 0; i < 4; i++)
#pragma unroll
        for (int j = 0; j < 4; j++)
#pragma unroll
            for (int t = 0; t < 4; t++) acc[i][j][t] = 0.f;

#pragma unroll
    for (int s = 0; s < 2; s++) {
        const uint32_t st = sb + s * STG;
        const int k0 = s * BK;
        tile_async(st + 0 * TILE_B, Ah, row0, k0, K);
        tile_async(st + 1 * TILE_B, Al, row0, k0, K);
        tile_async(st + 2 * TILE_B, Bw, col0, k0, K);
        CP_COMMIT();
    }

    const uint32_t a_row = (uint32_t)(wm * 64 + (lane & 15));
    const uint32_t a_kof = (uint32_t)((lane >> 4) * 8);
    const uint32_t b_row = (uint32_t)(wn * 32 + (lane & 7) + ((lane >> 4) << 3));
    const uint32_t b_kof = (uint32_t)(((lane >> 3) & 1) * 8);

    for (int it = 0; it < NKSTEP; it++) {
        CP_WAIT1();
        __syncthreads();

        if (it + 2 < NKSTEP) {
            const uint32_t st = sb + ((it + 2) % NSTAGE) * STG;
            const int k0 = (it + 2) * BK;
            tile_async(st + 0 * TILE_B, Ah, row0, k0, K);
            tile_async(st + 1 * TILE_B, Al, row0, k0, K);
            tile_async(st + 2 * TILE_B, Bw, col0, k0, K);
        }
        CP_COMMIT();

        const uint32_t st = sb + (it % NSTAGE) * STG;
#pragma unroll
        for (int kk = 0; kk < BK; kk += 16) {
            uint32_t ah[4][4], al[4][4], bw[2][4];
#pragma unroll
            for (int i = 0; i < 4; i++) {
                const uint32_t ao = ((a_row + i * 16) * PAD_K + kk + a_kof) * 2;
                ldm_x4(ah[i], st + 0 * TILE_B + ao);
                ldm_x4(al[i], st + 1 * TILE_B + ao);
            }
#pragma unroll
            for (int p = 0; p < 2; p++) {
                const uint32_t bo = ((b_row + p * 16) * PAD_K + kk + b_kof) * 2;
                ldm_x4(bw[p], st + 2 * TILE_B + bo);
            }
#pragma unroll
            for (int i = 0; i < 4; i++)
#pragma unroll
                for (int j = 0; j < 4; j++) {
                    const uint32_t* bf = &bw[j >> 1][(j & 1) * 2];
                    mma_f16(acc[i][j], ah[i], bf);
                    mma_f16(acc[i][j], al[i], bf);
                }
        }
        __syncthreads();
    }

    const int rbase = row0 + wm * 64 + (lane >> 2);
    const int cbase = col0 + wn * 32 + (lane & 3) * 2;
#pragma unroll
    for (int i = 0; i < 4; i++)
#pragma unroll
        for (int j = 0; j < 4; j++) {
            const int cc = cbase + j * 8;
            const float b0 = bias[cc], b1 = bias[cc + 1];
#pragma unroll
            for (int hrow = 0; hrow < 2; hrow++) {
                const int rr = rbase + i * 16 + hrow * 8;
                float2 o;
                o.x = acc[i][j][hrow * 2 + 0] + b0;
                o.y = acc[i][j][hrow * 2 + 1] + b1;
                *(float2*)(C + (size_t)rr * N + cc) = o;
            }
        }
}

// ---------------------------------------------------------------- conversions
// x fp32 -> fp16 hi/lo
__global__ void split_f16(const float4* __restrict__ in, uint2* __restrict__ hi,
                          uint2* __restrict__ lo, int n4)
{
    const int i = blockIdx.x * blockDim.x + threadIdx.x;
    if (i >= n4) return;
    const float4 a = in[i];
    const __half h0 = __float2half_rn(a.x), h1 = __float2half_rn(a.y);
    const __half h2 = __float2half_rn(a.z), h3 = __float2half_rn(a.w);
    const __half l0 = __float2half_rn(a.x - __half2float(h0));
    const __half l1 = __float2half_rn(a.y - __half2float(h1));
    const __half l2 = __float2half_rn(a.z - __half2float(h2));
    const __half l3 = __float2half_rn(a.w - __half2float(h3));
    hi[i] = make_uint2((uint32_t)__half_as_ushort(h0) | ((uint32_t)__half_as_ushort(h1) << 16),
                       (uint32_t)__half_as_ushort(h2) | ((uint32_t)__half_as_ushort(h3) << 16));
    lo[i] = make_uint2((uint32_t)__half_as_ushort(l0) | ((uint32_t)__half_as_ushort(l1) << 16),
                       (uint32_t)__half_as_ushort(l2) | ((uint32_t)__half_as_ushort(l3) << 16));
}

// W[K,N] fp32 -> W^T[N,K] fp16
__global__ void wsplit(const float* __restrict__ W, __half* __restrict__ th)
{
    __shared__ float t[32][33];
    const int n0 = blockIdx.x * 32, k0 = blockIdx.y * 32;
    const int tx = threadIdx.x, ty = threadIdx.y;
    for (int i = ty; i < 32; i += 8)
        t[i][tx] = W[(size_t)(k0 + i) * NDIM + n0 + tx];
    __syncthreads();
    for (int i = ty; i < 32; i += 8)
        th[(size_t)(n0 + i) * KDIM + k0 + tx] = __float2half_rn(t[tx][i]);
}

// ---------------------------------------------------------------- attention (tensor core)
__global__ __launch_bounds__(128, 1) void attn_tc(
    const float* __restrict__ q, const float* __restrict__ k,
    const float* __restrict__ v, const float* __restrict__ decay,
    __half* __restrict__ aoh, __half* __restrict__ aol)
{
    const int c = blockIdx.x, h = blockIdx.y, b = blockIdx.z;
    const int tid = threadIdx.x, wm = tid >> 5, lane = tid & 31;

    extern __shared__ char sma[];
    const uint32_t sb = smem_u32(sma);
    __nv_bfloat16* Qh = (__nv_bfloat16*)(sma + AT_QH);
    __nv_bfloat16* Ql = (__nv_bfloat16*)(sma + AT_QL);
    __nv_bfloat16* Kh = (__nv_bfloat16*)(sma + AT_KH);
    __nv_bfloat16* Kl = (__nv_bfloat16*)(sma + AT_KL);
    __half* Vh = (__half*)(sma + AT_VH);
    __half* Vl = (__half*)(sma + AT_VL);
    float* df = (float*)(sma + AT_DF);
    float* S  = (float*)(sma + AT_S);

    const size_t base = ((size_t)b * L_SZ + (size_t)c * CHUNK) * D_MODEL + h * D_HEAD;

    {
        uint4 z = make_uint4(0, 0, 0, 0);
        uint4* vz = (uint4*)(sma + AT_VH);
        for (int i = tid; i < (2 * 64 * 152 * 2) / 16; i += 128) vz[i] = z;
        for (int i = tid; i < 15 * 72; i += 128) {
            Kh[129 * 72 + i] = __float2bfloat16(0.f);
            Kl[129 * 72 + i] = __float2bfloat16(0.f);
        }
    }
    __syncthreads();

    for (int idx = tid; idx < 128 * 64; idx += 128) {
        const int r = idx >> 6, d = idx & 63;
        const float val = q[base + (size_t)r * D_MODEL + d];
        const __nv_bfloat16 hh = __float2bfloat16(val);
        Qh[r * 72 + d] = hh;
        Ql[r * 72 + d] = __float2bfloat16(val - __bfloat162float(hh));
    }
    for (int idx = tid; idx < 129 * 64; idx += 128) {
        const int j = idx >> 6, d = idx & 63;
        float kk = 0.f, vv = 0.f;
        if (j > 0 || c > 0) {
            const size_t g = base + (size_t)(j - 1) * D_MODEL + d;
            kk = k[g]; vv = v[g];
        }
        const __nv_bfloat16 kh = __float2bfloat16(kk);
        Kh[j * 72 + d] = kh;
        Kl[j * 72 + d] = __float2bfloat16(kk - __bfloat162float(kh));
        const __half vh = __float2half_rn(vv);
        Vh[d * 152 + j] = vh;
        Vl[d * 152 + j] = __float2half_rn(vv - __half2float(vh));
    }
    df[tid] = 0.125f * powf(decay[h], (float)tid);
    __syncthreads();

    // S = Q Kf^T
    const uint32_t a_ro = (uint32_t)(lane & 15);
    const uint32_t a_ko = (uint32_t)((lane >> 4) * 8);
    const uint32_t b_ro = (uint32_t)((lane & 7) + ((lane >> 4) << 3));
    const uint32_t b_ko = (uint32_t)(((lane >> 3) & 1) * 8);

    uint32_t qh[2][4][4], ql[2][4][4];
#pragma unroll
    for (int mt = 0; mt < 2; mt++)
#pragma unroll
        for (int kt = 0; kt < 4; kt++) {
            const uint32_t ao = ((wm * 32 + mt * 16 + a_ro) * 72 + kt * 16 + a_ko) * 2;
            ldm_x4(qh[mt][kt], sb + AT_QH + ao);
            ldm_x4(ql[mt][kt], sb + AT_QL + ao);
        }

#pragma unroll
    for (int nt = 0; nt < 9; nt++) {
        uint32_t kh[4][4], kl[4][4];
#pragma unroll
        for (int kt = 0; kt < 4; kt++) {
            const uint32_t bo = ((nt * 16 + b_ro) * 72 + kt * 16 + b_ko) * 2;
            ldm_x4(kh[kt], sb + AT_KH + bo);
            ldm_x4(kl[kt], sb + AT_KL + bo);
        }
#pragma unroll
        for (int mt = 0; mt < 2; mt++)
#pragma unroll
            for (int half = 0; half < 2; half++) {
                float acc[4] = {0.f, 0.f, 0.f, 0.f};
#pragma unroll
                for (int kt = 0; kt < 4; kt++) {
                    mma_bf16(acc, qh[mt][kt], &kh[kt][half * 2]);
                    mma_bf16(acc, qh[mt][kt], &kl[kt][half * 2]);
                    mma_bf16(acc, ql[mt][kt], &kh[kt][half * 2]);
                }
                const int r0 = wm * 32 + mt * 16 + (lane >> 2);
                const int c0 = nt * 16 + half * 8 + (lane & 3) * 2;
                *(float2*)&S[r0 * SPITCH + c0]       = make_float2(acc[0], acc[1]);
                *(float2*)&S[(r0 + 8) * SPITCH + c0] = make_float2(acc[2], acc[3]);
            }
    }
    __syncwarp();

    // softmax rows
    for (int rr = 0; rr < 32; rr++) {
        const int row = wm * 32 + rr;
        const float sf = df[row];
        float sv[5];
        float mx = -1e30f;
#pragma unroll
        for (int i = 0; i < 5; i++) {
            const int j = lane + 32 * i;
            sv[i] = (j < 129) ? S[row * SPITCH + j] * sf : -1e30f;
            mx = fmaxf(mx, sv[i]);
        }
#pragma unroll
        for (int off = 16; off > 0; off >>= 1)
            mx = fmaxf(mx, __shfl_xor_sync(0xFFFFFFFFu, mx, off));
        float lsum = 0.f;
        float pv[5];
#pragma unroll
        for (int i = 0; i < 5; i++) {
            pv[i] = __expf(sv[i] - mx);
            lsum += pv[i];
        }
#pragma unroll
        for (int off = 16; off > 0; off >>= 1)
            lsum += __shfl_xor_sync(0xFFFFFFFFu, lsum, off);
        char* prow = sma + AT_S + row * (SPITCH * 4);
#pragma unroll
        for (int i = 0; i < 5; i++) {
            const int j = lane + 32 * i;
            if (j < 144) {
                const float p = (j < 129) ? pv[i] : 0.f;
                const __half ph = __float2half_rn(p);
                ((__half*)prow)[j] = ph;
                ((__half*)(prow + PL_OFF))[j] = __float2half_rn(p - __half2float(ph));
            }
        }
        if (lane == 0) df[row] = 1.f / lsum;
    }
    __syncwarp();

    // O = P Vf
    float oacc[2][8][4];
#pragma unroll
    for (int mt = 0; mt < 2; mt++)
#pragma unroll
        for (int n8 = 0; n8 < 8; n8++)
#pragma unroll
            for (int t = 0; t < 4; t++) oacc[mt][n8][t] = 0.f;

#pragma unroll
    for (int kt = 0; kt < 9; kt++) {
        uint32_t ph[2][4], pl[2][4];
#pragma unroll
        for (int mt = 0; mt < 2; mt++) {
            const uint32_t ao = AT_S + (wm * 32 + mt * 16 + a_ro) * (SPITCH * 4)
                              + (kt * 16 + a_ko) * 2;
            ldm_x4(ph[mt], sb + ao);
            ldm_x4(pl[mt], sb + ao + PL_OFF);
        }
        uint32_t vh[4][4], vl[4][4];
#pragma unroll
        for (int g = 0; g < 4; g++) {
            const uint32_t bo = ((g * 16 + b_ro) * 152 + kt * 16 + b_ko) * 2;
            ldm_x4(vh[g], sb + AT_VH + bo);
            ldm_x4(vl[g], sb + AT_VL + bo);
        }
#pragma unroll
        for (int mt = 0; mt < 2; mt++)
#pragma unroll
            for (int n8 = 0; n8 < 8; n8++) {
                const uint32_t* bh = &vh[n8 >> 1][(n8 & 1) * 2];
                const uint32_t* bl = &vl[n8 >> 1][(n8 & 1) * 2];
                mma_f16(oacc[mt][n8], ph[mt], bh);
                mma_f16(oacc[mt][n8], ph[mt], bl);
                mma_f16(oacc[mt][n8], pl[mt], bh);
            }
    }
    __syncwarp();

    // epilogue: scale by 1/l, fp16 hi/lo split, store
#pragma unroll
    for (int mt = 0; mt < 2; mt++) {
        const int r0 = wm * 32 + mt * 16 + (lane >> 2);
        const float inv0 = df[r0], inv1 = df[r0 + 8];
#pragma unroll
        for (int n8 = 0; n8 < 8; n8++) {
            const int c0 = n8 * 8 + (lane & 3) * 2;
#pragma unroll
            for (int hrow = 0; hrow < 2; hrow++) {
                const int rr = r0 + hrow * 8;
                const float inv = hrow ? inv1 : inv0;
#pragma unroll
                for (int cc = 0; cc < 2; cc++) {
                    const float val = oacc[mt][n8][hrow * 2 + cc] * inv;
                    const __half hh = __float2half_rn(val);
                    const size_t o = base + (size_t)rr * D_MODEL + c0 + cc;
                    aoh[o] = hh;
                    aol[o] = __float2half_rn(val - __half2float(hh));
                }
            }
        }
    }
}

// ---------------------------------------------------------------- launch
extern "C" void kernel_launch(void* const* d_in, const int* in_sizes, int n_in,
                              void* d_out, int out_size)
{
    const float* x     = (const float*)d_in[0];
    const float* Wq    = (const float*)d_in[1];
    const float* bq    = (const float*)d_in[2];
    const float* Wk    = (const float*)d_in[3];
    const float* bk    = (const float*)d_in[4];
    const float* Wv    = (const float*)d_in[5];
    const float* bv    = (const float*)d_in[6];
    const float* Wo    = (const float*)d_in[7];
    const float* bo    = (const float*)d_in[8];
    const float* decay = (const float*)d_in[9];
    float* out = (float*)d_out;

    float *q, *k, *v;
    __half *xh, *xl, *aoh, *aol, *wt;
    cudaGetSymbolAddress((void**)&q,   g_q);
    cudaGetSymbolAddress((void**)&k,   g_k);
    cudaGetSymbolAddress((void**)&v,   g_v);
    cudaGetSymbolAddress((void**)&xh,  g_xh);
    cudaGetSymbolAddress((void**)&xl,  g_xl);
    cudaGetSymbolAddress((void**)&aoh, g_aoh);
    cudaGetSymbolAddress((void**)&aol, g_aol);
    cudaGetSymbolAddress((void**)&wt,  g_wt);

    cudaFuncSetAttribute(gemm_tc, cudaFuncAttributeMaxDynamicSharedMemorySize, GSMEM);
    cudaFuncSetAttribute(attn_tc, cudaFuncAttributeMaxDynamicSharedMemorySize, AT_SZ);

    dim3 wgrid(NDIM / 32, KDIM / 32), wblk(32, 8);
    wsplit<<<wgrid, wblk>>>(Wq, wt + 0 * WSL);
    wsplit<<<wgrid, wblk>>>(Wk, wt + 1 * WSL);
    wsplit<<<wgrid, wblk>>>(Wv, wt + 2 * WSL);
    wsplit<<<wgrid, wblk>>>(Wo, wt + 3 * WSL);

    const int n4 = M_TOT * D_MODEL / 4;
    split_f16<<<(n4 + 255) / 256, 256>>>((const float4*)x, (uint2*)xh, (uint2*)xl, n4);

    dim3 ggrid(NDIM / BN, M_TOT / BM);
    gemm_tc<<<ggrid, 256, GSMEM>>>(xh, xl, wt + 0 * WSL, bq, q, M_TOT, NDIM, KDIM);
    gemm_tc<<<ggrid, 256, GSMEM>>>(xh, xl, wt + 1 * WSL, bk, k, M_TOT, NDIM, KDIM);
    gemm_tc<<<ggrid, 256, GSMEM>>>(xh, xl, wt + 2 * WSL, bv, v, M_TOT, NDIM, KDIM);

    attn_tc<<<dim3(NCHUNK, N_HEADS, B_SZ), 128, AT_SZ>>>(q, k, v, decay, aoh, aol);

    gemm_tc<<<ggrid, 256, GSMEM>>>(aoh, aol, wt + 3 * WSL, bo, out, M_TOT, NDIM, KDIM);
}

// round 9
// speedup vs baseline: 2.5258x; 1.0886x over previous
#include <cuda_runtime.h>
#include <cuda_bf16.h>
#include <cuda_fp16.h>
#include <math.h>
#include <stdint.h>

// ---------------------------------------------------------------- constants
#define B_SZ 4
#define L_SZ 4096
#define D_MODEL 1024
#define N_HEADS 16
#define D_HEAD 64
#define CHUNK 128
#define NCHUNK 32
#define M_TOT (B_SZ * L_SZ)      // 16384
#define KDIM 1024
#define NDIM 1024
#define WSL (KDIM * NDIM)

// GEMM tiling
#define BM 128
#define BN 128
#define BK 32
#define NKSTEP (KDIM / BK)       // 32
#define PAD_K 40
#define TILE_B (128 * PAD_K * 2)
#define STG (3 * TILE_B)
#define NSTAGE 3
#define GSMEM (NSTAGE * STG)     // 92160

// attention smem layout (bytes)
#define AT_QH 0                   // Qh bf16 [128][72]
#define AT_QL 18432
#define AT_KH 36864               // Kh bf16 [144][72]
#define AT_KL 57600
#define AT_VH 78336               // Vth fp16 [64][152]
#define AT_VL 97792
#define AT_DF 117248              // decay prefactor -> 1/l, 128 f32
#define AT_P  117760              // Ph fp16 [128][168]; Pl at +43008
#define PPITCH_B 336              // bytes per P row (168 halves)
#define PL_OFF 43008
#define AT_SZ (AT_P + 2 * 128 * PPITCH_B)   // 203776

// ---------------------------------------------------------------- scratch
__device__ float g_q[M_TOT * D_MODEL];
__device__ float g_k[M_TOT * D_MODEL];
__device__ float g_v[M_TOT * D_MODEL];
__device__ __half g_xh[M_TOT * D_MODEL];
__device__ __half g_xl[M_TOT * D_MODEL];
__device__ __half g_aoh[M_TOT * D_MODEL];
__device__ __half g_aol[M_TOT * D_MODEL];
__device__ __half g_wt[4 * WSL];           // W^T [N,K] fp16

// ---------------------------------------------------------------- helpers
__device__ __forceinline__ uint32_t smem_u32(const void* p) {
    uint32_t a;
    asm("{ .reg .u64 t; cvta.to.shared.u64 t, %1; cvt.u32.u64 %0, t; }" : "=r"(a) : "l"(p));
    return a;
}
__device__ __forceinline__ void cp16(uint32_t so, const void* g) {
    asm volatile("cp.async.cg.shared.global [%0], [%1], 16;" :: "r"(so), "l"(g));
}
#define CP_COMMIT() asm volatile("cp.async.commit_group;" ::: "memory")
#define CP_WAIT1()  asm volatile("cp.async.wait_group 1;" ::: "memory")

__device__ __forceinline__ void ldm_x4(uint32_t* r, uint32_t addr) {
    asm volatile("ldmatrix.sync.aligned.m8n8.x4.shared.b16 {%0,%1,%2,%3}, [%4];"
                 : "=r"(r[0]), "=r"(r[1]), "=r"(r[2]), "=r"(r[3]) : "r"(addr));
}
__device__ __forceinline__ void mma_bf16(float* c, const uint32_t* a, const uint32_t* b) {
    asm volatile(
        "mma.sync.aligned.m16n8k16.row.col.f32.bf16.bf16.f32 "
        "{%0,%1,%2,%3}, {%4,%5,%6,%7}, {%8,%9}, {%0,%1,%2,%3};"
        : "+f"(c[0]), "+f"(c[1]), "+f"(c[2]), "+f"(c[3])
        : "r"(a[0]), "r"(a[1]), "r"(a[2]), "r"(a[3]), "r"(b[0]), "r"(b[1]));
}
__device__ __forceinline__ void mma_f16(float* c, const uint32_t* a, const uint32_t* b) {
    asm volatile(
        "mma.sync.aligned.m16n8k16.row.col.f32.f16.f16.f32 "
        "{%0,%1,%2,%3}, {%4,%5,%6,%7}, {%8,%9}, {%0,%1,%2,%3};"
        : "+f"(c[0]), "+f"(c[1]), "+f"(c[2]), "+f"(c[3])
        : "r"(a[0]), "r"(a[1]), "r"(a[2]), "r"(a[3]), "r"(b[0]), "r"(b[1]));
}

// ---------------------------------------------------------------- tensor GEMM (unchanged from R7)
__device__ __forceinline__ void tile_async(uint32_t sdst, const __half* src,
                                           int row0, int k0, int K) {
    const int tid = threadIdx.x;
#pragma unroll
    for (int c = 0; c < 2; c++) {
        const int chunk = tid + c * 256;
        const int r = chunk >> 2, c16 = chunk & 3;
        cp16(sdst + (uint32_t)(r * (PAD_K * 2) + c16 * 16),
             src + (size_t)(row0 + r) * K + k0 + c16 * 8);
    }
}

__global__ __launch_bounds__(256, 1)
void gemm_tc(const __half* __restrict__ Ah, const __half* __restrict__ Al,
             const __half* __restrict__ Bw,
             const float* __restrict__ bias, float* __restrict__ C,
             int M, int N, int K)
{
    extern __shared__ char sm[];
    const uint32_t sb = smem_u32(sm);
    const int tid = threadIdx.x;
    const int wid = tid >> 5, lane = tid & 31;
    const int wm = wid & 1, wn = wid >> 1;
    const int row0 = blockIdx.y * BM, col0 = blockIdx.x * BN;

    float acc[4][4][4];
#pragma unroll
    for (int i = 0; i < 4; i++)
#pragma unroll
        for (int j = 0; j < 4; j++)
#pragma unroll
            for (int t = 0; t < 4; t++) acc[i][j][t] = 0.f;

#pragma unroll
    for (int s = 0; s < 2; s++) {
        const uint32_t st = sb + s * STG;
        const int k0 = s * BK;
        tile_async(st + 0 * TILE_B, Ah, row0, k0, K);
        tile_async(st + 1 * TILE_B, Al, row0, k0, K);
        tile_async(st + 2 * TILE_B, Bw, col0, k0, K);
        CP_COMMIT();
    }

    const uint32_t a_row = (uint32_t)(wm * 64 + (lane & 15));
    const uint32_t a_kof = (uint32_t)((lane >> 4) * 8);
    const uint32_t b_row = (uint32_t)(wn * 32 + (lane & 7) + ((lane >> 4) << 3));
    const uint32_t b_kof = (uint32_t)(((lane >> 3) & 1) * 8);

    for (int it = 0; it < NKSTEP; it++) {
        CP_WAIT1();
        __syncthreads();

        if (it + 2 < NKSTEP) {
            const uint32_t st = sb + ((it + 2) % NSTAGE) * STG;
            const int k0 = (it + 2) * BK;
            tile_async(st + 0 * TILE_B, Ah, row0, k0, K);
            tile_async(st + 1 * TILE_B, Al, row0, k0, K);
            tile_async(st + 2 * TILE_B, Bw, col0, k0, K);
        }
        CP_COMMIT();

        const uint32_t st = sb + (it % NSTAGE) * STG;
#pragma unroll
        for (int kk = 0; kk < BK; kk += 16) {
            uint32_t ah[4][4], al[4][4], bw[2][4];
#pragma unroll
            for (int i = 0; i < 4; i++) {
                const uint32_t ao = ((a_row + i * 16) * PAD_K + kk + a_kof) * 2;
                ldm_x4(ah[i], st + 0 * TILE_B + ao);
                ldm_x4(al[i], st + 1 * TILE_B + ao);
            }
#pragma unroll
            for (int p = 0; p < 2; p++) {
                const uint32_t bo = ((b_row + p * 16) * PAD_K + kk + b_kof) * 2;
                ldm_x4(bw[p], st + 2 * TILE_B + bo);
            }
#pragma unroll
            for (int i = 0; i < 4; i++)
#pragma unroll
                for (int j = 0; j < 4; j++) {
                    const uint32_t* bf = &bw[j >> 1][(j & 1) * 2];
                    mma_f16(acc[i][j], ah[i], bf);
                    mma_f16(acc[i][j], al[i], bf);
                }
        }
        __syncthreads();
    }

    const int rbase = row0 + wm * 64 + (lane >> 2);
    const int cbase = col0 + wn * 32 + (lane & 3) * 2;
#pragma unroll
    for (int i = 0; i < 4; i++)
#pragma unroll
        for (int j = 0; j < 4; j++) {
            const int cc = cbase + j * 8;
            const float b0 = bias[cc], b1 = bias[cc + 1];
#pragma unroll
            for (int hrow = 0; hrow < 2; hrow++) {
                const int rr = rbase + i * 16 + hrow * 8;
                float2 o;
                o.x = acc[i][j][hrow * 2 + 0] + b0;
                o.y = acc[i][j][hrow * 2 + 1] + b1;
                *(float2*)(C + (size_t)rr * N + cc) = o;
            }
        }
}

// ---------------------------------------------------------------- conversions
__global__ void split_f16(const float4* __restrict__ in, uint2* __restrict__ hi,
                          uint2* __restrict__ lo, int n4)
{
    const int i = blockIdx.x * blockDim.x + threadIdx.x;
    if (i >= n4) return;
    const float4 a = in[i];
    const __half h0 = __float2half_rn(a.x), h1 = __float2half_rn(a.y);
    const __half h2 = __float2half_rn(a.z), h3 = __float2half_rn(a.w);
    const __half l0 = __float2half_rn(a.x - __half2float(h0));
    const __half l1 = __float2half_rn(a.y - __half2float(h1));
    const __half l2 = __float2half_rn(a.z - __half2float(h2));
    const __half l3 = __float2half_rn(a.w - __half2float(h3));
    hi[i] = make_uint2((uint32_t)__half_as_ushort(h0) | ((uint32_t)__half_as_ushort(h1) << 16),
                       (uint32_t)__half_as_ushort(h2) | ((uint32_t)__half_as_ushort(h3) << 16));
    lo[i] = make_uint2((uint32_t)__half_as_ushort(l0) | ((uint32_t)__half_as_ushort(l1) << 16),
                       (uint32_t)__half_as_ushort(l2) | ((uint32_t)__half_as_ushort(l3) << 16));
}

__global__ void wsplit(const float* __restrict__ W, __half* __restrict__ th)
{
    __shared__ float t[32][33];
    const int n0 = blockIdx.x * 32, k0 = blockIdx.y * 32;
    const int tx = threadIdx.x, ty = threadIdx.y;
    for (int i = ty; i < 32; i += 8)
        t[i][tx] = W[(size_t)(k0 + i) * NDIM + n0 + tx];
    __syncthreads();
    for (int i = ty; i < 32; i += 8)
        th[(size_t)(n0 + i) * KDIM + k0 + tx] = __float2half_rn(t[tx][i]);
}

// ---------------------------------------------------------------- attention
// exp on S fragments in registers, P fp16 hi/lo straight to smem, row-sum l
// via 2 shuffles. No max subtraction (scores bounded; identical math).
__global__ __launch_bounds__(128, 1) void attn_tc(
    const float* __restrict__ q, const float* __restrict__ k,
    const float* __restrict__ v, const float* __restrict__ decay,
    __half* __restrict__ aoh, __half* __restrict__ aol)
{
    const int c = blockIdx.x, h = blockIdx.y, b = blockIdx.z;
    const int tid = threadIdx.x, wm = tid >> 5, lane = tid & 31;

    extern __shared__ char sma[];
    const uint32_t sb = smem_u32(sma);
    __nv_bfloat16* Qh = (__nv_bfloat16*)(sma + AT_QH);
    __nv_bfloat16* Ql = (__nv_bfloat16*)(sma + AT_QL);
    __nv_bfloat16* Kh = (__nv_bfloat16*)(sma + AT_KH);
    __nv_bfloat16* Kl = (__nv_bfloat16*)(sma + AT_KL);
    __half* Vh = (__half*)(sma + AT_VH);
    __half* Vl = (__half*)(sma + AT_VL);
    float* df = (float*)(sma + AT_DF);

    const size_t base = ((size_t)b * L_SZ + (size_t)c * CHUNK) * D_MODEL + h * D_HEAD;

    // zero V pad region + K pad rows
    {
        uint4 z = make_uint4(0, 0, 0, 0);
        uint4* vz = (uint4*)(sma + AT_VH);
        for (int i = tid; i < (2 * 64 * 152 * 2) / 16; i += 128) vz[i] = z;
        for (int i = tid; i < 15 * 72; i += 128) {
            Kh[129 * 72 + i] = __float2bfloat16(0.f);
            Kl[129 * 72 + i] = __float2bfloat16(0.f);
        }
    }
    __syncthreads();

    // load Q (vectorized): 128 rows x 16 float4
    for (int idx = tid; idx < 128 * 16; idx += 128) {
        const int r = idx >> 4, d = (idx & 15) * 4;
        const float4 a = *(const float4*)(q + base + (size_t)r * D_MODEL + d);
        ushort4 hh, ll;
        hh.x = __bfloat16_as_ushort(__float2bfloat16(a.x));
        hh.y = __bfloat16_as_ushort(__float2bfloat16(a.y));
        hh.z = __bfloat16_as_ushort(__float2bfloat16(a.z));
        hh.w = __bfloat16_as_ushort(__float2bfloat16(a.w));
        ll.x = __bfloat16_as_ushort(__float2bfloat16(a.x - __bfloat162float(__ushort_as_bfloat16(hh.x))));
        ll.y = __bfloat16_as_ushort(__float2bfloat16(a.y - __bfloat162float(__ushort_as_bfloat16(hh.y))));
        ll.z = __bfloat16_as_ushort(__float2bfloat16(a.z - __bfloat162float(__ushort_as_bfloat16(hh.z))));
        ll.w = __bfloat16_as_ushort(__float2bfloat16(a.w - __bfloat162float(__ushort_as_bfloat16(hh.w))));
        *(ushort4*)&Qh[r * 72 + d] = hh;
        *(ushort4*)&Ql[r * 72 + d] = ll;
    }
    // load Kf + Vf (vectorized): 129 rows x 16 float4
    for (int idx = tid; idx < 129 * 16; idx += 128) {
        const int j = idx >> 4, d = (idx & 15) * 4;
        float4 a = make_float4(0.f, 0.f, 0.f, 0.f);
        float4 vv = make_float4(0.f, 0.f, 0.f, 0.f);
        if (j > 0 || c > 0) {
            const size_t g = base + (size_t)(j - 1) * D_MODEL + d;
            a  = *(const float4*)(k + g);
            vv = *(const float4*)(v + g);
        }
        ushort4 hh, ll;
        hh.x = __bfloat16_as_ushort(__float2bfloat16(a.x));
        hh.y = __bfloat16_as_ushort(__float2bfloat16(a.y));
        hh.z = __bfloat16_as_ushort(__float2bfloat16(a.z));
        hh.w = __bfloat16_as_ushort(__float2bfloat16(a.w));
        ll.x = __bfloat16_as_ushort(__float2bfloat16(a.x - __bfloat162float(__ushort_as_bfloat16(hh.x))));
        ll.y = __bfloat16_as_ushort(__float2bfloat16(a.y - __bfloat162float(__ushort_as_bfloat16(hh.y))));
        ll.z = __bfloat16_as_ushort(__float2bfloat16(a.z - __bfloat162float(__ushort_as_bfloat16(hh.z))));
        ll.w = __bfloat16_as_ushort(__float2bfloat16(a.w - __bfloat162float(__ushort_as_bfloat16(hh.w))));
        *(ushort4*)&Kh[j * 72 + d] = hh;
        *(ushort4*)&Kl[j * 72 + d] = ll;
        const float vf[4] = {vv.x, vv.y, vv.z, vv.w};
#pragma unroll
        for (int e = 0; e < 4; e++) {
            const __half vh = __float2half_rn(vf[e]);
            Vh[(d + e) * 152 + j] = vh;
            Vl[(d + e) * 152 + j] = __float2half_rn(vf[e] - __half2float(vh));
        }
    }
    df[tid] = 0.125f * powf(decay[h], (float)tid);
    __syncthreads();

    // ---------------- S = Q Kf^T  ->  exp -> P (fp16 hi/lo) ----------------
    const uint32_t a_ro = (uint32_t)(lane & 15);
    const uint32_t a_ko = (uint32_t)((lane >> 4) * 8);
    const uint32_t b_ro = (uint32_t)((lane & 7) + ((lane >> 4) << 3));
    const uint32_t b_ko = (uint32_t)(((lane >> 3) & 1) * 8);

    uint32_t qh[2][4][4], ql[2][4][4];
#pragma unroll
    for (int mt = 0; mt < 2; mt++)
#pragma unroll
        for (int kt = 0; kt < 4; kt++) {
            const uint32_t ao = ((wm * 32 + mt * 16 + a_ro) * 72 + kt * 16 + a_ko) * 2;
            ldm_x4(qh[mt][kt], sb + AT_QH + ao);
            ldm_x4(ql[mt][kt], sb + AT_QL + ao);
        }

    const int r0a = wm * 32 + (lane >> 2);         // mt=0 row
    const float sf0a = df[r0a],      sf0b = df[r0a + 8];
    const float sf1a = df[r0a + 16], sf1b = df[r0a + 24];
    float lsum[2][2] = {{0.f, 0.f}, {0.f, 0.f}};   // [mt][rowhalf]

#pragma unroll
    for (int nt = 0; nt < 9; nt++) {
        uint32_t kh[4][4], kl[4][4];
#pragma unroll
        for (int kt = 0; kt < 4; kt++) {
            const uint32_t bo = ((nt * 16 + b_ro) * 72 + kt * 16 + b_ko) * 2;
            ldm_x4(kh[kt], sb + AT_KH + bo);
            ldm_x4(kl[kt], sb + AT_KL + bo);
        }
#pragma unroll
        for (int mt = 0; mt < 2; mt++) {
            const float sfa = mt ? sf1a : sf0a;
            const float sfb = mt ? sf1b : sf0b;
            const int row = wm * 32 + mt * 16 + (lane >> 2);
#pragma unroll
            for (int half = 0; half < 2; half++) {
                float acc[4] = {0.f, 0.f, 0.f, 0.f};
#pragma unroll
                for (int kt = 0; kt < 4; kt++) {
                    mma_bf16(acc, qh[mt][kt], &kh[kt][half * 2]);
                    mma_bf16(acc, qh[mt][kt], &kl[kt][half * 2]);
                    mma_bf16(acc, ql[mt][kt], &kh[kt][half * 2]);
                }
                const int c0 = nt * 16 + half * 8 + (lane & 3) * 2;
                const float p0 = (c0     < 129) ? __expf(acc[0] * sfa) : 0.f;
                const float p1 = (c0 + 1 < 129) ? __expf(acc[1] * sfa) : 0.f;
                const float p2 = (c0     < 129) ? __expf(acc[2] * sfb) : 0.f;
                const float p3 = (c0 + 1 < 129) ? __expf(acc[3] * sfb) : 0.f;
                lsum[mt][0] += p0 + p1;
                lsum[mt][1] += p2 + p3;
                const __half h0 = __float2half_rn(p0), h1 = __float2half_rn(p1);
                const __half h2 = __float2half_rn(p2), h3 = __float2half_rn(p3);
                char* pr0 = sma + AT_P + row * PPITCH_B + c0 * 2;
                char* pr1 = pr0 + 8 * PPITCH_B;
                *(__half2*)pr0 = __halves2half2(h0, h1);
                *(__half2*)pr1 = __halves2half2(h2, h3);
                *(__half2*)(pr0 + PL_OFF) = __halves2half2(
                    __float2half_rn(p0 - __half2float(h0)),
                    __float2half_rn(p1 - __half2float(h1)));
                *(__half2*)(pr1 + PL_OFF) = __halves2half2(
                    __float2half_rn(p2 - __half2float(h2)),
                    __float2half_rn(p3 - __half2float(h3)));
            }
        }
    }
    __syncwarp();
    // reduce l over the 4-lane row group, store 1/l into df
#pragma unroll
    for (int mt = 0; mt < 2; mt++) {
#pragma unroll
        for (int rh = 0; rh < 2; rh++) {
            float s = lsum[mt][rh];
            s += __shfl_xor_sync(0xFFFFFFFFu, s, 1);
            s += __shfl_xor_sync(0xFFFFFFFFu, s, 2);
            lsum[mt][rh] = s;
        }
        if ((lane & 3) == 0) {
            const int row = wm * 32 + mt * 16 + (lane >> 2);
            df[row]     = 1.f / lsum[mt][0];
            df[row + 8] = 1.f / lsum[mt][1];
        }
    }
    __syncwarp();

    // ---------------- O = P Vf ----------------
    float oacc[2][8][4];
#pragma unroll
    for (int mt = 0; mt < 2; mt++)
#pragma unroll
        for (int n8 = 0; n8 < 8; n8++)
#pragma unroll
            for (int t = 0; t < 4; t++) oacc[mt][n8][t] = 0.f;

#pragma unroll
    for (int kt = 0; kt < 9; kt++) {
        uint32_t ph[2][4], pl[2][4];
#pragma unroll
        for (int mt = 0; mt < 2; mt++) {
            const uint32_t ao = AT_P + (wm * 32 + mt * 16 + a_ro) * PPITCH_B
                              + (kt * 16 + a_ko) * 2;
            ldm_x4(ph[mt], sb + ao);
            ldm_x4(pl[mt], sb + ao + PL_OFF);
        }
        uint32_t vh[4][4], vl[4][4];
#pragma unroll
        for (int g = 0; g < 4; g++) {
            const uint32_t bo = ((g * 16 + b_ro) * 152 + kt * 16 + b_ko) * 2;
            ldm_x4(vh[g], sb + AT_VH + bo);
            ldm_x4(vl[g], sb + AT_VL + bo);
        }
#pragma unroll
        for (int mt = 0; mt < 2; mt++)
#pragma unroll
            for (int n8 = 0; n8 < 8; n8++) {
                const uint32_t* bh = &vh[n8 >> 1][(n8 & 1) * 2];
                const uint32_t* bl = &vl[n8 >> 1][(n8 & 1) * 2];
                mma_f16(oacc[mt][n8], ph[mt], bh);
                mma_f16(oacc[mt][n8], ph[mt], bl);
                mma_f16(oacc[mt][n8], pl[mt], bh);
            }
    }
    __syncwarp();

    // epilogue: scale by 1/l, fp16 hi/lo split, store
#pragma unroll
    for (int mt = 0; mt < 2; mt++) {
        const int r0 = wm * 32 + mt * 16 + (lane >> 2);
        const float inv0 = df[r0], inv1 = df[r0 + 8];
#pragma unroll
        for (int n8 = 0; n8 < 8; n8++) {
            const int c0 = n8 * 8 + (lane & 3) * 2;
#pragma unroll
            for (int hrow = 0; hrow < 2; hrow++) {
                const int rr = r0 + hrow * 8;
                const float inv = hrow ? inv1 : inv0;
#pragma unroll
                for (int cc = 0; cc < 2; cc++) {
                    const float val = oacc[mt][n8][hrow * 2 + cc] * inv;
                    const __half hh = __float2half_rn(val);
                    const size_t o = base + (size_t)rr * D_MODEL + c0 + cc;
                    aoh[o] = hh;
                    aol[o] = __float2half_rn(val - __half2float(hh));
                }
            }
        }
    }
}

// ---------------------------------------------------------------- launch
extern "C" void kernel_launch(void* const* d_in, const int* in_sizes, int n_in,
                              void* d_out, int out_size)
{
    const float* x     = (const float*)d_in[0];
    const float* Wq    = (const float*)d_in[1];
    const float* bq    = (const float*)d_in[2];
    const float* Wk    = (const float*)d_in[3];
    const float* bk    = (const float*)d_in[4];
    const float* Wv    = (const float*)d_in[5];
    const float* bv    = (const float*)d_in[6];
    const float* Wo    = (const float*)d_in[7];
    const float* bo    = (const float*)d_in[8];
    const float* decay = (const float*)d_in[9];
    float* out = (float*)d_out;

    float *q, *k, *v;
    __half *xh, *xl, *aoh, *aol, *wt;
    cudaGetSymbolAddress((void**)&q,   g_q);
    cudaGetSymbolAddress((void**)&k,   g_k);
    cudaGetSymbolAddress((void**)&v,   g_v);
    cudaGetSymbolAddress((void**)&xh,  g_xh);
    cudaGetSymbolAddress((void**)&xl,  g_xl);
    cudaGetSymbolAddress((void**)&aoh, g_aoh);
    cudaGetSymbolAddress((void**)&aol, g_aol);
    cudaGetSymbolAddress((void**)&wt,  g_wt);

    cudaFuncSetAttribute(gemm_tc, cudaFuncAttributeMaxDynamicSharedMemorySize, GSMEM);
    cudaFuncSetAttribute(attn_tc, cudaFuncAttributeMaxDynamicSharedMemorySize, AT_SZ);

    dim3 wgrid(NDIM / 32, KDIM / 32), wblk(32, 8);
    wsplit<<<wgrid, wblk>>>(Wq, wt + 0 * WSL);
    wsplit<<<wgrid, wblk>>>(Wk, wt + 1 * WSL);
    wsplit<<<wgrid, wblk>>>(Wv, wt + 2 * WSL);
    wsplit<<<wgrid, wblk>>>(Wo, wt + 3 * WSL);

    const int n4 = M_TOT * D_MODEL / 4;
    split_f16<<<(n4 + 255) / 256, 256>>>((const float4*)x, (uint2*)xh, (uint2*)xl, n4);

    dim3 ggrid(NDIM / BN, M_TOT / BM);
    gemm_tc<<<ggrid, 256, GSMEM>>>(xh, xl, wt + 0 * WSL, bq, q, M_TOT, NDIM, KDIM);
    gemm_tc<<<ggrid, 256, GSMEM>>>(xh, xl, wt + 1 * WSL, bk, k, M_TOT, NDIM, KDIM);
    gemm_tc<<<ggrid, 256, GSMEM>>>(xh, xl, wt + 2 * WSL, bv, v, M_TOT, NDIM, KDIM);

    attn_tc<<<dim3(NCHUNK, N_HEADS, B_SZ), 128, AT_SZ>>>(q, k, v, decay, aoh, aol);

    gemm_tc<<<ggrid, 256, GSMEM>>>(aoh, aol, wt + 3 * WSL, bo, out, M_TOT, NDIM, KDIM);
}

// round 10
// speedup vs baseline: 3.9756x; 1.5740x over previous
#include <cuda_runtime.h>
#include <cuda_bf16.h>
#include <cuda_fp16.h>
#include <math.h>
#include <stdint.h>

// ---------------------------------------------------------------- constants
#define B_SZ 4
#define L_SZ 4096
#define D_MODEL 1024
#define N_HEADS 16
#define D_HEAD 64
#define CHUNK 128
#define NCHUNK 32
#define M_TOT (B_SZ * L_SZ)      // 16384
#define KDIM 1024
#define NDIM 1024
#define WSL (KDIM * NDIM)

// GEMM tiling
#define BM 128
#define BN 128
#define BK 32
#define NKSTEP (KDIM / BK)       // 32
#define PAD_K 40
#define TILE_B (128 * PAD_K * 2) // 10240 B per 128x32 fp16 tile
#define STG (2 * TILE_B)         // A, B per stage = 20480
#define NSTAGE 3
#define GSMEM (NSTAGE * STG)     // 61440

// attention smem layout (bytes)
#define AT_QH 0                   // Qh bf16 [128][72]
#define AT_QL 18432
#define AT_KH 36864               // Kh bf16 [144][72]
#define AT_KL 57600
#define AT_VH 78336               // V fp16 [144][72] row-major (ldmatrix.trans)
#define AT_VL 99072
#define AT_DF 119808              // decay prefactor -> 1/l, 128 f32
#define AT_P  120320              // Ph fp16 [128][168]; Pl at +43008
#define PPITCH_B 336
#define PL_OFF 43008
#define AT_SZ (AT_P + 2 * 128 * PPITCH_B)   // 206336

// ---------------------------------------------------------------- scratch
__device__ float g_q[M_TOT * D_MODEL];
__device__ float g_k[M_TOT * D_MODEL];
__device__ float g_v[M_TOT * D_MODEL];
__device__ __half g_xh[M_TOT * D_MODEL];
__device__ __half g_ao[M_TOT * D_MODEL];
__device__ __half g_wt[4 * WSL];           // W^T [N,K] fp16

// ---------------------------------------------------------------- helpers
__device__ __forceinline__ uint32_t smem_u32(const void* p) {
    uint32_t a;
    asm("{ .reg .u64 t; cvta.to.shared.u64 t, %1; cvt.u32.u64 %0, t; }" : "=r"(a) : "l"(p));
    return a;
}
__device__ __forceinline__ void cp16(uint32_t so, const void* g) {
    asm volatile("cp.async.cg.shared.global [%0], [%1], 16;" :: "r"(so), "l"(g));
}
#define CP_COMMIT() asm volatile("cp.async.commit_group;" ::: "memory")
#define CP_WAIT1()  asm volatile("cp.async.wait_group 1;" ::: "memory")

__device__ __forceinline__ void ldm_x4(uint32_t* r, uint32_t addr) {
    asm volatile("ldmatrix.sync.aligned.m8n8.x4.shared.b16 {%0,%1,%2,%3}, [%4];"
                 : "=r"(r[0]), "=r"(r[1]), "=r"(r[2]), "=r"(r[3]) : "r"(addr));
}
__device__ __forceinline__ void ldm_x4_t(uint32_t* r, uint32_t addr) {
    asm volatile("ldmatrix.sync.aligned.m8n8.x4.trans.shared.b16 {%0,%1,%2,%3}, [%4];"
                 : "=r"(r[0]), "=r"(r[1]), "=r"(r[2]), "=r"(r[3]) : "r"(addr));
}
__device__ __forceinline__ void mma_bf16(float* c, const uint32_t* a, const uint32_t* b) {
    asm volatile(
        "mma.sync.aligned.m16n8k16.row.col.f32.bf16.bf16.f32 "
        "{%0,%1,%2,%3}, {%4,%5,%6,%7}, {%8,%9}, {%0,%1,%2,%3};"
        : "+f"(c[0]), "+f"(c[1]), "+f"(c[2]), "+f"(c[3])
        : "r"(a[0]), "r"(a[1]), "r"(a[2]), "r"(a[3]), "r"(b[0]), "r"(b[1]));
}
__device__ __forceinline__ void mma_f16(float* c, const uint32_t* a, const uint32_t* b) {
    asm volatile(
        "mma.sync.aligned.m16n8k16.row.col.f32.f16.f16.f32 "
        "{%0,%1,%2,%3}, {%4,%5,%6,%7}, {%8,%9}, {%0,%1,%2,%3};"
        : "+f"(c[0]), "+f"(c[1]), "+f"(c[2]), "+f"(c[3])
        : "r"(a[0]), "r"(a[1]), "r"(a[2]), "r"(a[3]), "r"(b[0]), "r"(b[1]));
}

// ---------------------------------------------------------------- tensor GEMM
// C[M,N] = A[M,K] @ B[N,K]^T + bias, single fp16 x fp16, fp32 accum.
__device__ __forceinline__ void tile_async(uint32_t sdst, const __half* src,
                                           int row0, int k0, int K) {
    const int tid = threadIdx.x;
#pragma unroll
    for (int c = 0; c < 2; c++) {
        const int chunk = tid + c * 256;
        const int r = chunk >> 2, c16 = chunk & 3;
        cp16(sdst + (uint32_t)(r * (PAD_K * 2) + c16 * 16),
             src + (size_t)(row0 + r) * K + k0 + c16 * 8);
    }
}

__global__ __launch_bounds__(256)
void gemm_tc(const __half* __restrict__ Aw, const __half* __restrict__ Bw,
             const float* __restrict__ bias, float* __restrict__ C,
             int M, int N, int K)
{
    extern __shared__ char sm[];
    const uint32_t sb = smem_u32(sm);
    const int tid = threadIdx.x;
    const int wid = tid >> 5, lane = tid & 31;
    const int wm = wid & 1, wn = wid >> 1;
    const int row0 = blockIdx.y * BM, col0 = blockIdx.x * BN;

    float acc[4][4][4];
#pragma unroll
    for (int i = 0; i < 4; i++)
#pragma unroll
        for (int j = 0; j < 4; j++)
#pragma unroll
            for (int t = 0; t < 4; t++) acc[i][j][t] = 0.f;

#pragma unroll
    for (int s = 0; s < 2; s++) {
        const uint32_t st = sb + s * STG;
        const int k0 = s * BK;
        tile_async(st + 0 * TILE_B, Aw, row0, k0, K);
        tile_async(st + 1 * TILE_B, Bw, col0, k0, K);
        CP_COMMIT();
    }

    const uint32_t a_row = (uint32_t)(wm * 64 + (lane & 15));
    const uint32_t a_kof = (uint32_t)((lane >> 4) * 8);
    const uint32_t b_row = (uint32_t)(wn * 32 + (lane & 7) + ((lane >> 4) << 3));
    const uint32_t b_kof = (uint32_t)(((lane >> 3) & 1) * 8);

    for (int it = 0; it < NKSTEP; it++) {
        CP_WAIT1();
        __syncthreads();

        if (it + 2 < NKSTEP) {
            const uint32_t st = sb + ((it + 2) % NSTAGE) * STG;
            const int k0 = (it + 2) * BK;
            tile_async(st + 0 * TILE_B, Aw, row0, k0, K);
            tile_async(st + 1 * TILE_B, Bw, col0, k0, K);
        }
        CP_COMMIT();

        const uint32_t st = sb + (it % NSTAGE) * STG;
#pragma unroll
        for (int kk = 0; kk < BK; kk += 16) {
            uint32_t aw[4][4], bw[2][4];
#pragma unroll
            for (int i = 0; i < 4; i++) {
                const uint32_t ao = ((a_row + i * 16) * PAD_K + kk + a_kof) * 2;
                ldm_x4(aw[i], st + 0 * TILE_B + ao);
            }
#pragma unroll
            for (int p = 0; p < 2; p++) {
                const uint32_t bo = ((b_row + p * 16) * PAD_K + kk + b_kof) * 2;
                ldm_x4(bw[p], st + 1 * TILE_B + bo);
            }
#pragma unroll
            for (int i = 0; i < 4; i++)
#pragma unroll
                for (int j = 0; j < 4; j++)
                    mma_f16(acc[i][j], aw[i], &bw[j >> 1][(j & 1) * 2]);
        }
        __syncthreads();
    }

    const int rbase = row0 + wm * 64 + (lane >> 2);
    const int cbase = col0 + wn * 32 + (lane & 3) * 2;
#pragma unroll
    for (int i = 0; i < 4; i++)
#pragma unroll
        for (int j = 0; j < 4; j++) {
            const int cc = cbase + j * 8;
            const float b0 = bias[cc], b1 = bias[cc + 1];
#pragma unroll
            for (int hrow = 0; hrow < 2; hrow++) {
                const int rr = rbase + i * 16 + hrow * 8;
                float2 o;
                o.x = acc[i][j][hrow * 2 + 0] + b0;
                o.y = acc[i][j][hrow * 2 + 1] + b1;
                *(float2*)(C + (size_t)rr * N + cc) = o;
            }
        }
}

// ---------------------------------------------------------------- conversions
__global__ void tof16(const float4* __restrict__ in, uint2* __restrict__ hi, int n4)
{
    const int i = blockIdx.x * blockDim.x + threadIdx.x;
    if (i >= n4) return;
    const float4 a = in[i];
    hi[i] = make_uint2(
        (uint32_t)__half_as_ushort(__float2half_rn(a.x)) |
        ((uint32_t)__half_as_ushort(__float2half_rn(a.y)) << 16),
        (uint32_t)__half_as_ushort(__float2half_rn(a.z)) |
        ((uint32_t)__half_as_ushort(__float2half_rn(a.w)) << 16));
}

__global__ void wsplit(const float* __restrict__ W, __half* __restrict__ th)
{
    __shared__ float t[32][33];
    const int n0 = blockIdx.x * 32, k0 = blockIdx.y * 32;
    const int tx = threadIdx.x, ty = threadIdx.y;
    for (int i = ty; i < 32; i += 8)
        t[i][tx] = W[(size_t)(k0 + i) * NDIM + n0 + tx];
    __syncthreads();
    for (int i = ty; i < 32; i += 8)
        th[(size_t)(n0 + i) * KDIM + k0 + tx] = __float2half_rn(t[tx][i]);
}

// ---------------------------------------------------------------- attention
__global__ __launch_bounds__(128, 1) void attn_tc(
    const float* __restrict__ q, const float* __restrict__ k,
    const float* __restrict__ v, const float* __restrict__ decay,
    __half* __restrict__ ao)
{
    const int c = blockIdx.x, h = blockIdx.y, b = blockIdx.z;
    const int tid = threadIdx.x, wm = tid >> 5, lane = tid & 31;

    extern __shared__ char sma[];
    const uint32_t sb = smem_u32(sma);
    __nv_bfloat16* Qh = (__nv_bfloat16*)(sma + AT_QH);
    __nv_bfloat16* Ql = (__nv_bfloat16*)(sma + AT_QL);
    __nv_bfloat16* Kh = (__nv_bfloat16*)(sma + AT_KH);
    __nv_bfloat16* Kl = (__nv_bfloat16*)(sma + AT_KL);
    __half* Vh = (__half*)(sma + AT_VH);
    __half* Vl = (__half*)(sma + AT_VL);
    float* df = (float*)(sma + AT_DF);

    const size_t base = ((size_t)b * L_SZ + (size_t)c * CHUNK) * D_MODEL + h * D_HEAD;

    // zero K/V pad rows 129..143
    for (int i = tid; i < 15 * 72; i += 128) {
        Kh[129 * 72 + i] = __float2bfloat16(0.f);
        Kl[129 * 72 + i] = __float2bfloat16(0.f);
        Vh[129 * 72 + i] = __float2half_rn(0.f);
        Vl[129 * 72 + i] = __float2half_rn(0.f);
    }

    // load Q (vectorized): 128 rows x 16 float4
    for (int idx = tid; idx < 128 * 16; idx += 128) {
        const int r = idx >> 4, d = (idx & 15) * 4;
        const float4 a = *(const float4*)(q + base + (size_t)r * D_MODEL + d);
        ushort4 hh, ll;
        hh.x = __bfloat16_as_ushort(__float2bfloat16(a.x));
        hh.y = __bfloat16_as_ushort(__float2bfloat16(a.y));
        hh.z = __bfloat16_as_ushort(__float2bfloat16(a.z));
        hh.w = __bfloat16_as_ushort(__float2bfloat16(a.w));
        ll.x = __bfloat16_as_ushort(__float2bfloat16(a.x - __bfloat162float(__ushort_as_bfloat16(hh.x))));
        ll.y = __bfloat16_as_ushort(__float2bfloat16(a.y - __bfloat162float(__ushort_as_bfloat16(hh.y))));
        ll.z = __bfloat16_as_ushort(__float2bfloat16(a.z - __bfloat162float(__ushort_as_bfloat16(hh.z))));
        ll.w = __bfloat16_as_ushort(__float2bfloat16(a.w - __bfloat162float(__ushort_as_bfloat16(hh.w))));
        *(ushort4*)&Qh[r * 72 + d] = hh;
        *(ushort4*)&Ql[r * 72 + d] = ll;
    }
    // load Kf + Vf: 129 rows x 16 float4, both row-major now
    for (int idx = tid; idx < 129 * 16; idx += 128) {
        const int j = idx >> 4, d = (idx & 15) * 4;
        float4 a = make_float4(0.f, 0.f, 0.f, 0.f);
        float4 vv = make_float4(0.f, 0.f, 0.f, 0.f);
        if (j > 0 || c > 0) {
            const size_t g = base + (size_t)(j - 1) * D_MODEL + d;
            a  = *(const float4*)(k + g);
            vv = *(const float4*)(v + g);
        }
        ushort4 hh, ll;
        hh.x = __bfloat16_as_ushort(__float2bfloat16(a.x));
        hh.y = __bfloat16_as_ushort(__float2bfloat16(a.y));
        hh.z = __bfloat16_as_ushort(__float2bfloat16(a.z));
        hh.w = __bfloat16_as_ushort(__float2bfloat16(a.w));
        ll.x = __bfloat16_as_ushort(__float2bfloat16(a.x - __bfloat162float(__ushort_as_bfloat16(hh.x))));
        ll.y = __bfloat16_as_ushort(__float2bfloat16(a.y - __bfloat162float(__ushort_as_bfloat16(hh.y))));
        ll.z = __bfloat16_as_ushort(__float2bfloat16(a.z - __bfloat162float(__ushort_as_bfloat16(hh.z))));
        ll.w = __bfloat16_as_ushort(__float2bfloat16(a.w - __bfloat162float(__ushort_as_bfloat16(hh.w))));
        *(ushort4*)&Kh[j * 72 + d] = hh;
        *(ushort4*)&Kl[j * 72 + d] = ll;
        ushort4 vh4, vl4;
        vh4.x = __half_as_ushort(__float2half_rn(vv.x));
        vh4.y = __half_as_ushort(__float2half_rn(vv.y));
        vh4.z = __half_as_ushort(__float2half_rn(vv.z));
        vh4.w = __half_as_ushort(__float2half_rn(vv.w));
        vl4.x = __half_as_ushort(__float2half_rn(vv.x - __half2float(__ushort_as_half(vh4.x))));
        vl4.y = __half_as_ushort(__float2half_rn(vv.y - __half2float(__ushort_as_half(vh4.y))));
        vl4.z = __half_as_ushort(__float2half_rn(vv.z - __half2float(__ushort_as_half(vh4.z))));
        vl4.w = __half_as_ushort(__float2half_rn(vv.w - __half2float(__ushort_as_half(vh4.w))));
        *(ushort4*)&Vh[j * 72 + d] = vh4;
        *(ushort4*)&Vl[j * 72 + d] = vl4;
    }
    df[tid] = 0.125f * powf(decay[h], (float)tid);
    __syncthreads();

    // ---------------- S = Q Kf^T  ->  exp -> P (fp16 hi/lo) ----------------
    const uint32_t a_ro = (uint32_t)(lane & 15);
    const uint32_t a_ko = (uint32_t)((lane >> 4) * 8);
    const uint32_t b_ro = (uint32_t)((lane & 7) + ((lane >> 4) << 3));
    const uint32_t b_ko = (uint32_t)(((lane >> 3) & 1) * 8);

    uint32_t qh[2][4][4], ql[2][4][4];
#pragma unroll
    for (int mt = 0; mt < 2; mt++)
#pragma unroll
        for (int kt = 0; kt < 4; kt++) {
            const uint32_t aoff = ((wm * 32 + mt * 16 + a_ro) * 72 + kt * 16 + a_ko) * 2;
            ldm_x4(qh[mt][kt], sb + AT_QH + aoff);
            ldm_x4(ql[mt][kt], sb + AT_QL + aoff);
        }

    const int r0a = wm * 32 + (lane >> 2);
    const float sf0a = df[r0a],      sf0b = df[r0a + 8];
    const float sf1a = df[r0a + 16], sf1b = df[r0a + 24];
    float lsum[2][2] = {{0.f, 0.f}, {0.f, 0.f}};

#pragma unroll
    for (int nt = 0; nt < 9; nt++) {
        uint32_t kh[4][4], kl[4][4];
#pragma unroll
        for (int kt = 0; kt < 4; kt++) {
            const uint32_t bo = ((nt * 16 + b_ro) * 72 + kt * 16 + b_ko) * 2;
            ldm_x4(kh[kt], sb + AT_KH + bo);
            ldm_x4(kl[kt], sb + AT_KL + bo);
        }
#pragma unroll
        for (int mt = 0; mt < 2; mt++) {
            const float sfa = mt ? sf1a : sf0a;
            const float sfb = mt ? sf1b : sf0b;
            const int row = wm * 32 + mt * 16 + (lane >> 2);
#pragma unroll
            for (int half = 0; half < 2; half++) {
                float acc[4] = {0.f, 0.f, 0.f, 0.f};
#pragma unroll
                for (int kt = 0; kt < 4; kt++) {
                    mma_bf16(acc, qh[mt][kt], &kh[kt][half * 2]);
                    mma_bf16(acc, qh[mt][kt], &kl[kt][half * 2]);
                    mma_bf16(acc, ql[mt][kt], &kh[kt][half * 2]);
                }
                const int c0 = nt * 16 + half * 8 + (lane & 3) * 2;
                const float p0 = (c0     < 129) ? __expf(acc[0] * sfa) : 0.f;
                const float p1 = (c0 + 1 < 129) ? __expf(acc[1] * sfa) : 0.f;
                const float p2 = (c0     < 129) ? __expf(acc[2] * sfb) : 0.f;
                const float p3 = (c0 + 1 < 129) ? __expf(acc[3] * sfb) : 0.f;
                lsum[mt][0] += p0 + p1;
                lsum[mt][1] += p2 + p3;
                const __half h0 = __float2half_rn(p0), h1 = __float2half_rn(p1);
                const __half h2 = __float2half_rn(p2), h3 = __float2half_rn(p3);
                char* pr0 = sma + AT_P + row * PPITCH_B + c0 * 2;
                char* pr1 = pr0 + 8 * PPITCH_B;
                *(__half2*)pr0 = __halves2half2(h0, h1);
                *(__half2*)pr1 = __halves2half2(h2, h3);
                *(__half2*)(pr0 + PL_OFF) = __halves2half2(
                    __float2half_rn(p0 - __half2float(h0)),
                    __float2half_rn(p1 - __half2float(h1)));
                *(__half2*)(pr1 + PL_OFF) = __halves2half2(
                    __float2half_rn(p2 - __half2float(h2)),
                    __float2half_rn(p3 - __half2float(h3)));
            }
        }
    }
    __syncwarp();
#pragma unroll
    for (int mt = 0; mt < 2; mt++) {
#pragma unroll
        for (int rh = 0; rh < 2; rh++) {
            float s = lsum[mt][rh];
            s += __shfl_xor_sync(0xFFFFFFFFu, s, 1);
            s += __shfl_xor_sync(0xFFFFFFFFu, s, 2);
            lsum[mt][rh] = s;
        }
        if ((lane & 3) == 0) {
            const int row = wm * 32 + mt * 16 + (lane >> 2);
            df[row]     = 1.f / lsum[mt][0];
            df[row + 8] = 1.f / lsum[mt][1];
        }
    }
    __syncwarp();

    // ---------------- O = P V (V row-major via ldmatrix.trans) ----------------
    float oacc[2][8][4];
#pragma unroll
    for (int mt = 0; mt < 2; mt++)
#pragma unroll
        for (int n8 = 0; n8 < 8; n8++)
#pragma unroll
            for (int t = 0; t < 4; t++) oacc[mt][n8][t] = 0.f;

    const uint32_t v_ro = (uint32_t)(lane & 15);        // k row within 16
    const uint32_t v_co = (uint32_t)((lane >> 4) << 3); // n col offset 0/8

#pragma unroll
    for (int kt = 0; kt < 9; kt++) {
        uint32_t ph[2][4], pl[2][4];
#pragma unroll
        for (int mt = 0; mt < 2; mt++) {
            const uint32_t aoff = AT_P + (wm * 32 + mt * 16 + a_ro) * PPITCH_B
                                + (kt * 16 + a_ko) * 2;
            ldm_x4(ph[mt], sb + aoff);
            ldm_x4(pl[mt], sb + aoff + PL_OFF);
        }
        uint32_t vh[4][4], vl[4][4];
#pragma unroll
        for (int g = 0; g < 4; g++) {
            const uint32_t bo = ((kt * 16 + v_ro) * 72 + g * 16 + v_co) * 2;
            ldm_x4_t(vh[g], sb + AT_VH + bo);
            ldm_x4_t(vl[g], sb + AT_VL + bo);
        }
#pragma unroll
        for (int mt = 0; mt < 2; mt++)
#pragma unroll
            for (int n8 = 0; n8 < 8; n8++) {
                const uint32_t* bh = &vh[n8 >> 1][(n8 & 1) * 2];
                const uint32_t* bl = &vl[n8 >> 1][(n8 & 1) * 2];
                mma_f16(oacc[mt][n8], ph[mt], bh);
                mma_f16(oacc[mt][n8], ph[mt], bl);
                mma_f16(oacc[mt][n8], pl[mt], bh);
            }
    }
    __syncwarp();

    // epilogue: scale by 1/l, single fp16 store
#pragma unroll
    for (int mt = 0; mt < 2; mt++) {
        const int r0 = wm * 32 + mt * 16 + (lane >> 2);
        const float inv0 = df[r0], inv1 = df[r0 + 8];
#pragma unroll
        for (int n8 = 0; n8 < 8; n8++) {
            const int c0 = n8 * 8 + (lane & 3) * 2;
#pragma unroll
            for (int hrow = 0; hrow < 2; hrow++) {
                const int rr = r0 + hrow * 8;
                const float inv = hrow ? inv1 : inv0;
                __half2 o2 = __halves2half2(
                    __float2half_rn(oacc[mt][n8][hrow * 2 + 0] * inv),
                    __float2half_rn(oacc[mt][n8][hrow * 2 + 1] * inv));
                *(__half2*)(ao + base + (size_t)rr * D_MODEL + c0) = o2;
            }
        }
    }
}

// ---------------------------------------------------------------- launch
extern "C" void kernel_launch(void* const* d_in, const int* in_sizes, int n_in,
                              void* d_out, int out_size)
{
    const float* x     = (const float*)d_in[0];
    const float* Wq    = (const float*)d_in[1];
    const float* bq    = (const float*)d_in[2];
    const float* Wk    = (const float*)d_in[3];
    const float* bk    = (const float*)d_in[4];
    const float* Wv    = (const float*)d_in[5];
    const float* bv    = (const float*)d_in[6];
    const float* Wo    = (const float*)d_in[7];
    const float* bo    = (const float*)d_in[8];
    const float* decay = (const float*)d_in[9];
    float* out = (float*)d_out;

    float *q, *k, *v;
    __half *xh, *ao, *wt;
    cudaGetSymbolAddress((void**)&q,  g_q);
    cudaGetSymbolAddress((void**)&k,  g_k);
    cudaGetSymbolAddress((void**)&v,  g_v);
    cudaGetSymbolAddress((void**)&xh, g_xh);
    cudaGetSymbolAddress((void**)&ao, g_ao);
    cudaGetSymbolAddress((void**)&wt, g_wt);

    cudaFuncSetAttribute(gemm_tc, cudaFuncAttributeMaxDynamicSharedMemorySize, GSMEM);
    cudaFuncSetAttribute(attn_tc, cudaFuncAttributeMaxDynamicSharedMemorySize, AT_SZ);

    dim3 wgrid(NDIM / 32, KDIM / 32), wblk(32, 8);
    wsplit<<<wgrid, wblk>>>(Wq, wt + 0 * WSL);
    wsplit<<<wgrid, wblk>>>(Wk, wt + 1 * WSL);
    wsplit<<<wgrid, wblk>>>(Wv, wt + 2 * WSL);
    wsplit<<<wgrid, wblk>>>(Wo, wt + 3 * WSL);

    const int n4 = M_TOT * D_MODEL / 4;
    tof16<<<(n4 + 255) / 256, 256>>>((const float4*)x, (uint2*)xh, n4);

    dim3 ggrid(NDIM / BN, M_TOT / BM);
    gemm_tc<<<ggrid, 256, GSMEM>>>(xh, wt + 0 * WSL, bq, q, M_TOT, NDIM, KDIM);
    gemm_tc<<<ggrid, 256, GSMEM>>>(xh, wt + 1 * WSL, bk, k, M_TOT, NDIM, KDIM);
    gemm_tc<<<ggrid, 256, GSMEM>>>(xh, wt + 2 * WSL, bv, v, M_TOT, NDIM, KDIM);

    attn_tc<<<dim3(NCHUNK, N_HEADS, B_SZ), 128, AT_SZ>>>(q, k, v, decay, ao);

    gemm_tc<<<ggrid, 256, GSMEM>>>(ao, wt + 3 * WSL, bo, out, M_TOT, NDIM, KDIM);
}

// round 12
// speedup vs baseline: 5.4166x; 1.3625x over previous
#include <cuda_runtime.h>
#include <cuda_bf16.h>
#include <cuda_fp16.h>
#include <math.h>
#include <stdint.h>

// ---------------------------------------------------------------- constants
#define B_SZ 4
#define L_SZ 4096
#define D_MODEL 1024
#define N_HEADS 16
#define D_HEAD 64
#define CHUNK 128
#define NCHUNK 32
#define M_TOT (B_SZ * L_SZ)      // 16384
#define KDIM 1024
#define NDIM 1024
#define WSL (KDIM * NDIM)

// GEMM tiling
#define BM 128
#define BN 128
#define BK 32
#define NKSTEP (KDIM / BK)       // 32
#define PAD_K 40
#define TILE_B (128 * PAD_K * 2)
#define STG (2 * TILE_B)         // 20480
#define NSTAGE 3
#define GSMEM (NSTAGE * STG)     // 61440

// attention smem layout (bytes)
#define AT_QH 0                   // Qh bf16 [128][72]
#define AT_QL 18432               // Ql bf16 [128][72]
#define AT_KH 36864               // Kh bf16 [144][72]
#define AT_KL 57600               // Kl bf16 [144][72]
#define AT_VH 78336               // Vh fp16 [144][72] row-major (ldmatrix.trans)
#define AT_DF 99072               // decay prefactor -> 1/l, 128 f32
#define AT_P  99584               // Ph fp16 [128][152]
#define PPITCH_B 304              // bytes per P row (152 halves)
#define AT_SZ (AT_P + 128 * PPITCH_B)   // 138496

// ---------------------------------------------------------------- scratch
__device__ __half g_xh[M_TOT * D_MODEL];
__device__ __half g_ao[M_TOT * D_MODEL];
__device__ __half g_wt[4 * WSL];                 // W^T [N,K] fp16
__device__ __nv_bfloat16 g_qh[M_TOT * D_MODEL];
__device__ __nv_bfloat16 g_ql[M_TOT * D_MODEL];
__device__ __nv_bfloat16 g_kh[M_TOT * D_MODEL];
__device__ __nv_bfloat16 g_kl[M_TOT * D_MODEL];
__device__ __half g_vh[M_TOT * D_MODEL];

// ---------------------------------------------------------------- helpers
__device__ __forceinline__ uint32_t smem_u32(const void* p) {
    uint32_t a;
    asm("{ .reg .u64 t; cvta.to.shared.u64 t, %1; cvt.u32.u64 %0, t; }" : "=r"(a) : "l"(p));
    return a;
}
__device__ __forceinline__ void cp16(uint32_t so, const void* g) {
    asm volatile("cp.async.cg.shared.global [%0], [%1], 16;" :: "r"(so), "l"(g));
}
#define CP_COMMIT() asm volatile("cp.async.commit_group;" ::: "memory")
#define CP_WAIT1()  asm volatile("cp.async.wait_group 1;" ::: "memory")
#define CP_WAIT0()  asm volatile("cp.async.wait_group 0;" ::: "memory")

__device__ __forceinline__ void ldm_x4(uint32_t* r, uint32_t addr) {
    asm volatile("ldmatrix.sync.aligned.m8n8.x4.shared.b16 {%0,%1,%2,%3}, [%4];"
                 : "=r"(r[0]), "=r"(r[1]), "=r"(r[2]), "=r"(r[3]) : "r"(addr));
}
__device__ __forceinline__ void ldm_x4_t(uint32_t* r, uint32_t addr) {
    asm volatile("ldmatrix.sync.aligned.m8n8.x4.trans.shared.b16 {%0,%1,%2,%3}, [%4];"
                 : "=r"(r[0]), "=r"(r[1]), "=r"(r[2]), "=r"(r[3]) : "r"(addr));
}
__device__ __forceinline__ void mma_bf16(float* c, const uint32_t* a, const uint32_t* b) {
    asm volatile(
        "mma.sync.aligned.m16n8k16.row.col.f32.bf16.bf16.f32 "
        "{%0,%1,%2,%3}, {%4,%5,%6,%7}, {%8,%9}, {%0,%1,%2,%3};"
        : "+f"(c[0]), "+f"(c[1]), "+f"(c[2]), "+f"(c[3])
        : "r"(a[0]), "r"(a[1]), "r"(a[2]), "r"(a[3]), "r"(b[0]), "r"(b[1]));
}
__device__ __forceinline__ void mma_f16(float* c, const uint32_t* a, const uint32_t* b) {
    asm volatile(
        "mma.sync.aligned.m16n8k16.row.col.f32.f16.f16.f32 "
        "{%0,%1,%2,%3}, {%4,%5,%6,%7}, {%8,%9}, {%0,%1,%2,%3};"
        : "+f"(c[0]), "+f"(c[1]), "+f"(c[2]), "+f"(c[3])
        : "r"(a[0]), "r"(a[1]), "r"(a[2]), "r"(a[3]), "r"(b[0]), "r"(b[1]));
}
__device__ __forceinline__ uint32_t pack_bf16(float a, float b) {
    return (uint32_t)__bfloat16_as_ushort(__float2bfloat16(a)) |
           ((uint32_t)__bfloat16_as_ushort(__float2bfloat16(b)) << 16);
}

// ---------------------------------------------------------------- tensor GEMM
// C = A[M,K] @ B[N,K]^T + bias. Epilogue modes:
//  0: fp32 -> outA
//  1: bf16 hi/lo -> outA/outB
//  2: fp16 -> outA
__device__ __forceinline__ void tile_async(uint32_t sdst, const __half* src,
                                           int row0, int k0, int K) {
    const int tid = threadIdx.x;
#pragma unroll
    for (int c = 0; c < 2; c++) {
        const int chunk = tid + c * 256;
        const int r = chunk >> 2, c16 = chunk & 3;
        cp16(sdst + (uint32_t)(r * (PAD_K * 2) + c16 * 16),
             src + (size_t)(row0 + r) * K + k0 + c16 * 8);
    }
}

__global__ __launch_bounds__(256)
void gemm_tc(const __half* __restrict__ Aw, const __half* __restrict__ Bw,
             const float* __restrict__ bias,
             void* __restrict__ outA, void* __restrict__ outB, int mode,
             int M, int N, int K)
{
    extern __shared__ char sm[];
    const uint32_t sb = smem_u32(sm);
    const int tid = threadIdx.x;
    const int wid = tid >> 5, lane = tid & 31;
    const int wm = wid & 1, wn = wid >> 1;
    const int row0 = blockIdx.y * BM, col0 = blockIdx.x * BN;

    float acc[4][4][4];
#pragma unroll
    for (int i = 0; i < 4; i++)
#pragma unroll
        for (int j = 0; j < 4; j++)
#pragma unroll
            for (int t = 0; t < 4; t++) acc[i][j][t] = 0.f;

#pragma unroll
    for (int s = 0; s < 2; s++) {
        const uint32_t st = sb + s * STG;
        const int k0 = s * BK;
        tile_async(st + 0 * TILE_B, Aw, row0, k0, K);
        tile_async(st + 1 * TILE_B, Bw, col0, k0, K);
        CP_COMMIT();
    }

    const uint32_t a_row = (uint32_t)(wm * 64 + (lane & 15));
    const uint32_t a_kof = (uint32_t)((lane >> 4) * 8);
    const uint32_t b_row = (uint32_t)(wn * 32 + (lane & 7) + ((lane >> 4) << 3));
    const uint32_t b_kof = (uint32_t)(((lane >> 3) & 1) * 8);

    for (int it = 0; it < NKSTEP; it++) {
        CP_WAIT1();
        __syncthreads();

        if (it + 2 < NKSTEP) {
            const uint32_t st = sb + ((it + 2) % NSTAGE) * STG;
            const int k0 = (it + 2) * BK;
            tile_async(st + 0 * TILE_B, Aw, row0, k0, K);
            tile_async(st + 1 * TILE_B, Bw, col0, k0, K);
        }
        CP_COMMIT();

        const uint32_t st = sb + (it % NSTAGE) * STG;
#pragma unroll
        for (int kk = 0; kk < BK; kk += 16) {
            uint32_t aw[4][4], bw[2][4];
#pragma unroll
            for (int i = 0; i < 4; i++) {
                const uint32_t ao = ((a_row + i * 16) * PAD_K + kk + a_kof) * 2;
                ldm_x4(aw[i], st + 0 * TILE_B + ao);
            }
#pragma unroll
            for (int p = 0; p < 2; p++) {
                const uint32_t bo = ((b_row + p * 16) * PAD_K + kk + b_kof) * 2;
                ldm_x4(bw[p], st + 1 * TILE_B + bo);
            }
#pragma unroll
            for (int i = 0; i < 4; i++)
#pragma unroll
                for (int j = 0; j < 4; j++)
                    mma_f16(acc[i][j], aw[i], &bw[j >> 1][(j & 1) * 2]);
        }
        __syncthreads();
    }

    const int rbase = row0 + wm * 64 + (lane >> 2);
    const int cbase = col0 + wn * 32 + (lane & 3) * 2;
#pragma unroll
    for (int i = 0; i < 4; i++)
#pragma unroll
        for (int j = 0; j < 4; j++) {
            const int cc = cbase + j * 8;
            const float b0 = bias[cc], b1 = bias[cc + 1];
#pragma unroll
            for (int hrow = 0; hrow < 2; hrow++) {
                const int rr = rbase + i * 16 + hrow * 8;
                const float v0 = acc[i][j][hrow * 2 + 0] + b0;
                const float v1 = acc[i][j][hrow * 2 + 1] + b1;
                const size_t o = (size_t)rr * N + cc;
                if (mode == 0) {
                    *(float2*)((float*)outA + o) = make_float2(v0, v1);
                } else if (mode == 1) {
                    const __nv_bfloat16 h0 = __float2bfloat16(v0);
                    const __nv_bfloat16 h1 = __float2bfloat16(v1);
                    *(uint32_t*)((__nv_bfloat16*)outA + o) =
                        (uint32_t)__bfloat16_as_ushort(h0) |
                        ((uint32_t)__bfloat16_as_ushort(h1) << 16);
                    *(uint32_t*)((__nv_bfloat16*)outB + o) =
                        pack_bf16(v0 - __bfloat162float(h0), v1 - __bfloat162float(h1));
                } else {
                    *(__half2*)((__half*)outA + o) =
                        __halves2half2(__float2half_rn(v0), __float2half_rn(v1));
                }
            }
        }
}

// ---------------------------------------------------------------- conversions
__global__ void tof16(const float4* __restrict__ in, uint2* __restrict__ hi, int n4)
{
    const int i = blockIdx.x * blockDim.x + threadIdx.x;
    if (i >= n4) return;
    const float4 a = in[i];
    hi[i] = make_uint2(
        (uint32_t)__half_as_ushort(__float2half_rn(a.x)) |
        ((uint32_t)__half_as_ushort(__float2half_rn(a.y)) << 16),
        (uint32_t)__half_as_ushort(__float2half_rn(a.z)) |
        ((uint32_t)__half_as_ushort(__float2half_rn(a.w)) << 16));
}

__global__ void wsplit(const float* __restrict__ W, __half* __restrict__ th)
{
    __shared__ float t[32][33];
    const int n0 = blockIdx.x * 32, k0 = blockIdx.y * 32;
    const int tx = threadIdx.x, ty = threadIdx.y;
    for (int i = ty; i < 32; i += 8)
        t[i][tx] = W[(size_t)(k0 + i) * NDIM + n0 + tx];
    __syncthreads();
    for (int i = ty; i < 32; i += 8)
        th[(size_t)(n0 + i) * KDIM + k0 + tx] = __float2half_rn(t[tx][i]);
}

// ---------------------------------------------------------------- attention
// Inputs already split: Qh/Ql/Kh/Kl bf16, Vh fp16. Loads are pure cp.async.
// S = QK^T (3-product bf16) -> exp in registers -> Ph fp16 -> O = Ph Vh
// (1 product, ldmatrix.trans on V) -> scale 1/l -> ao fp16.
__global__ __launch_bounds__(128, 1) void attn_tc(
    const __nv_bfloat16* __restrict__ qh_g, const __nv_bfloat16* __restrict__ ql_g,
    const __nv_bfloat16* __restrict__ kh_g, const __nv_bfloat16* __restrict__ kl_g,
    const __half* __restrict__ vh_g, const float* __restrict__ decay,
    __half* __restrict__ ao)
{
    const int c = blockIdx.x, h = blockIdx.y, b = blockIdx.z;
    const int tid = threadIdx.x, wm = tid >> 5, lane = tid & 31;

    extern __shared__ char sma[];
    const uint32_t sb = smem_u32(sma);
    float* df = (float*)(sma + AT_DF);

    const size_t base = ((size_t)b * L_SZ + (size_t)c * CHUNK) * D_MODEL + h * D_HEAD;

    // zero pad rows 129..143 of Kh/Kl/Vh (15 rows x 144B each)
    {
        const uint4 z = make_uint4(0, 0, 0, 0);
        for (int i = tid; i < 135; i += 128) {
            *(uint4*)(sma + AT_KH + 129 * 144 + i * 16) = z;
            *(uint4*)(sma + AT_KL + 129 * 144 + i * 16) = z;
            *(uint4*)(sma + AT_VH + 129 * 144 + i * 16) = z;
        }
        // row 0 of K/V: zeros if c==0 (overwritten by cp.async below if c>0)
        if (c == 0 && tid < 9) {
            const int ch = tid;           // 9 x 16B = 144B row
            *(uint4*)(sma + AT_KH + ch * 16) = z;
            *(uint4*)(sma + AT_KL + ch * 16) = z;
            *(uint4*)(sma + AT_VH + ch * 16) = z;
        }
    }

    // cp.async loads: Q 128 rows x 8 chunks, K/V rows 1..128 (+row0 if c>0)
    for (int idx = tid; idx < 128 * 8; idx += 128) {
        const int r = idx >> 3, ch = idx & 7;
        const uint32_t so = (uint32_t)(r * 144 + ch * 16);
        const size_t g = base + (size_t)r * D_MODEL + ch * 8;
        cp16(sb + AT_QH + so, qh_g + g);
        cp16(sb + AT_QL + so, ql_g + g);
        cp16(sb + AT_KH + 144 + so, kh_g + g);
        cp16(sb + AT_KL + 144 + so, kl_g + g);
        cp16(sb + AT_VH + 144 + so, vh_g + g);
    }
    if (c > 0 && tid < 8) {
        const size_t g0 = base - D_MODEL + tid * 8;
        cp16(sb + AT_KH + tid * 16, kh_g + g0);
        cp16(sb + AT_KL + tid * 16, kl_g + g0);
        cp16(sb + AT_VH + tid * 16, vh_g + g0);
    }
    CP_COMMIT();
    df[tid] = 0.125f * powf(decay[h], (float)tid);
    CP_WAIT0();
    __syncthreads();

    // ---------------- S = Q Kf^T  ->  exp -> Ph ----------------
    const uint32_t a_ro = (uint32_t)(lane & 15);
    const uint32_t a_ko = (uint32_t)((lane >> 4) * 8);
    const uint32_t b_ro = (uint32_t)((lane & 7) + ((lane >> 4) << 3));
    const uint32_t b_ko = (uint32_t)(((lane >> 3) & 1) * 8);

    uint32_t qh[2][4][4], ql[2][4][4];
#pragma unroll
    for (int mt = 0; mt < 2; mt++)
#pragma unroll
        for (int kt = 0; kt < 4; kt++) {
            const uint32_t aoff = ((wm * 32 + mt * 16 + a_ro) * 72 + kt * 16 + a_ko) * 2;
            ldm_x4(qh[mt][kt], sb + AT_QH + aoff);
            ldm_x4(ql[mt][kt], sb + AT_QL + aoff);
        }

    const int r0a = wm * 32 + (lane >> 2);
    const float sf0a = df[r0a],      sf0b = df[r0a + 8];
    const float sf1a = df[r0a + 16], sf1b = df[r0a + 24];
    float lsum[2][2] = {{0.f, 0.f}, {0.f, 0.f}};

#pragma unroll
    for (int nt = 0; nt < 9; nt++) {
        uint32_t kh[4][4], kl[4][4];
#pragma unroll
        for (int kt = 0; kt < 4; kt++) {
            const uint32_t bo = ((nt * 16 + b_ro) * 72 + kt * 16 + b_ko) * 2;
            ldm_x4(kh[kt], sb + AT_KH + bo);
            ldm_x4(kl[kt], sb + AT_KL + bo);
        }
#pragma unroll
        for (int mt = 0; mt < 2; mt++) {
            const float sfa = mt ? sf1a : sf0a;
            const float sfb = mt ? sf1b : sf0b;
            const int row = wm * 32 + mt * 16 + (lane >> 2);
#pragma unroll
            for (int half = 0; half < 2; half++) {
                float acc[4] = {0.f, 0.f, 0.f, 0.f};
#pragma unroll
                for (int kt = 0; kt < 4; kt++) {
                    mma_bf16(acc, qh[mt][kt], &kh[kt][half * 2]);
                    mma_bf16(acc, qh[mt][kt], &kl[kt][half * 2]);
                    mma_bf16(acc, ql[mt][kt], &kh[kt][half * 2]);
                }
                const int c0 = nt * 16 + half * 8 + (lane & 3) * 2;
                const float p0 = (c0     < 129) ? __expf(acc[0] * sfa) : 0.f;
                const float p1 = (c0 + 1 < 129) ? __expf(acc[1] * sfa) : 0.f;
                const float p2 = (c0     < 129) ? __expf(acc[2] * sfb) : 0.f;
                const float p3 = (c0 + 1 < 129) ? __expf(acc[3] * sfb) : 0.f;
                lsum[mt][0] += p0 + p1;
                lsum[mt][1] += p2 + p3;
                char* pr0 = sma + AT_P + row * PPITCH_B + c0 * 2;
                char* pr1 = pr0 + 8 * PPITCH_B;
                *(__half2*)pr0 = __halves2half2(__float2half_rn(p0), __float2half_rn(p1));
                *(__half2*)pr1 = __halves2half2(__float2half_rn(p2), __float2half_rn(p3));
            }
        }
    }
    __syncwarp();
#pragma unroll
    for (int mt = 0; mt < 2; mt++) {
#pragma unroll
        for (int rh = 0; rh < 2; rh++) {
            float s = lsum[mt][rh];
            s += __shfl_xor_sync(0xFFFFFFFFu, s, 1);
            s += __shfl_xor_sync(0xFFFFFFFFu, s, 2);
            lsum[mt][rh] = s;
        }
        if ((lane & 3) == 0) {
            const int row = wm * 32 + mt * 16 + (lane >> 2);
            df[row]     = 1.f / lsum[mt][0];
            df[row + 8] = 1.f / lsum[mt][1];
        }
    }
    __syncwarp();

    // ---------------- O = Ph Vh ----------------
    float oacc[2][8][4];
#pragma unroll
    for (int mt = 0; mt < 2; mt++)
#pragma unroll
        for (int n8 = 0; n8 < 8; n8++)
#pragma unroll
            for (int t = 0; t < 4; t++) oacc[mt][n8][t] = 0.f;

    const uint32_t v_ro = (uint32_t)(lane & 15);
    const uint32_t v_co = (uint32_t)((lane >> 4) << 3);

#pragma unroll
    for (int kt = 0; kt < 9; kt++) {
        uint32_t ph[2][4];
#pragma unroll
        for (int mt = 0; mt < 2; mt++) {
            const uint32_t aoff = AT_P + (wm * 32 + mt * 16 + a_ro) * PPITCH_B
                                + (kt * 16 + a_ko) * 2;
            ldm_x4(ph[mt], sb + aoff);
        }
        uint32_t vh[4][4];
#pragma unroll
        for (int g = 0; g < 4; g++) {
            const uint32_t bo = ((kt * 16 + v_ro) * 72 + g * 16 + v_co) * 2;
            ldm_x4_t(vh[g], sb + AT_VH + bo);
        }
#pragma unroll
        for (int mt = 0; mt < 2; mt++)
#pragma unroll
            for (int n8 = 0; n8 < 8; n8++)
                mma_f16(oacc[mt][n8], ph[mt], &vh[n8 >> 1][(n8 & 1) * 2]);
    }
    __syncwarp();

    // epilogue
#pragma unroll
    for (int mt = 0; mt < 2; mt++) {
        const int r0 = wm * 32 + mt * 16 + (lane >> 2);
        const float inv0 = df[r0], inv1 = df[r0 + 8];
#pragma unroll
        for (int n8 = 0; n8 < 8; n8++) {
            const int c0 = n8 * 8 + (lane & 3) * 2;
#pragma unroll
            for (int hrow = 0; hrow < 2; hrow++) {
                const int rr = r0 + hrow * 8;
                const float inv = hrow ? inv1 : inv0;
                *(__half2*)(ao + base + (size_t)rr * D_MODEL + c0) = __halves2half2(
                    __float2half_rn(oacc[mt][n8][hrow * 2 + 0] * inv),
                    __float2half_rn(oacc[mt][n8][hrow * 2 + 1] * inv));
            }
        }
    }
}

// ---------------------------------------------------------------- launch
extern "C" void kernel_launch(void* const* d_in, const int* in_sizes, int n_in,
                              void* d_out, int out_size)
{
    const float* x     = (const float*)d_in[0];
    const float* Wq    = (const float*)d_in[1];
    const float* bq    = (const float*)d_in[2];
    const float* Wk    = (const float*)d_in[3];
    const float* bk    = (const float*)d_in[4];
    const float* Wv    = (const float*)d_in[5];
    const float* bv    = (const float*)d_in[6];
    const float* Wo    = (const float*)d_in[7];
    const float* bo    = (const float*)d_in[8];
    const float* decay = (const float*)d_in[9];
    float* out = (float*)d_out;

    __half *xh, *ao, *wt, *vh;
    __nv_bfloat16 *qh, *ql, *kh, *kl;
    cudaGetSymbolAddress((void**)&xh, g_xh);
    cudaGetSymbolAddress((void**)&ao, g_ao);
    cudaGetSymbolAddress((void**)&wt, g_wt);
    cudaGetSymbolAddress((void**)&qh, g_qh);
    cudaGetSymbolAddress((void**)&ql, g_ql);
    cudaGetSymbolAddress((void**)&kh, g_kh);
    cudaGetSymbolAddress((void**)&kl, g_kl);
    cudaGetSymbolAddress((void**)&vh, g_vh);

    cudaFuncSetAttribute(gemm_tc, cudaFuncAttributeMaxDynamicSharedMemorySize, GSMEM);
    cudaFuncSetAttribute(attn_tc, cudaFuncAttributeMaxDynamicSharedMemorySize, AT_SZ);

    dim3 wgrid(NDIM / 32, KDIM / 32), wblk(32, 8);
    wsplit<<<wgrid, wblk>>>(Wq, wt + 0 * WSL);
    wsplit<<<wgrid, wblk>>>(Wk, wt + 1 * WSL);
    wsplit<<<wgrid, wblk>>>(Wv, wt + 2 * WSL);
    wsplit<<<wgrid, wblk>>>(Wo, wt + 3 * WSL);

    const int n4 = M_TOT * D_MODEL / 4;
    tof16<<<(n4 + 255) / 256, 256>>>((const float4*)x, (uint2*)xh, n4);

    dim3 ggrid(NDIM / BN, M_TOT / BM);
    gemm_tc<<<ggrid, 256, GSMEM>>>(xh, wt + 0 * WSL, bq, qh, ql, 1, M_TOT, NDIM, KDIM);
    gemm_tc<<<ggrid, 256, GSMEM>>>(xh, wt + 1 * WSL, bk, kh, kl, 1, M_TOT, NDIM, KDIM);
    gemm_tc<<<ggrid, 256, GSMEM>>>(xh, wt + 2 * WSL, bv, vh, nullptr, 2, M_TOT, NDIM, KDIM);

    attn_tc<<<dim3(NCHUNK, N_HEADS, B_SZ), 128, AT_SZ>>>(qh, ql, kh, kl, vh, decay, ao);

    gemm_tc<<<ggrid, 256, GSMEM>>>(ao, wt + 3 * WSL, bo, out, nullptr, 0, M_TOT, NDIM, KDIM);
}

// round 13
// speedup vs baseline: 6.4163x; 1.1845x over previous
#include <cuda_runtime.h>
#include <cuda_bf16.h>
#include <cuda_fp16.h>
#include <math.h>
#include <stdint.h>

// ---------------------------------------------------------------- constants
#define B_SZ 4
#define L_SZ 4096
#define D_MODEL 1024
#define N_HEADS 16
#define D_HEAD 64
#define CHUNK 128
#define NCHUNK 32
#define M_TOT (B_SZ * L_SZ)      // 16384
#define KDIM 1024
#define NDIM 1024
#define WSL (KDIM * NDIM)

// GEMM tiling
#define BM 128
#define BN 128
#define BK 32
#define NKSTEP (KDIM / BK)       // 32
#define PAD_K 40
#define TILE_B (128 * PAD_K * 2)
#define STG (2 * TILE_B)         // 20480
#define NSTAGE 3
#define GSMEM (NSTAGE * STG)     // 61440

// attention smem layout (bytes) — no P buffer (P lives in registers)
#define AT_QH 0                   // Qh bf16 [128][72]
#define AT_QL 18432               // Ql bf16 [128][72]
#define AT_KH 36864               // Kh bf16 [144][72]
#define AT_KL 57600               // Kl bf16 [144][72]
#define AT_VH 78336               // Vh fp16 [144][72] row-major (ldmatrix.trans)
#define AT_DF 99072               // decay prefactor, 128 f32
#define AT_SZ 99584               // 97.25 KB -> 2 CTAs/SM

// ---------------------------------------------------------------- scratch
__device__ __half g_xh[M_TOT * D_MODEL];
__device__ __half g_ao[M_TOT * D_MODEL];
__device__ __half g_wt[4 * WSL];                 // W^T [N,K] fp16
__device__ __nv_bfloat16 g_qh[M_TOT * D_MODEL];
__device__ __nv_bfloat16 g_ql[M_TOT * D_MODEL];
__device__ __nv_bfloat16 g_kh[M_TOT * D_MODEL];
__device__ __nv_bfloat16 g_kl[M_TOT * D_MODEL];
__device__ __half g_vh[M_TOT * D_MODEL];

// ---------------------------------------------------------------- helpers
__device__ __forceinline__ uint32_t smem_u32(const void* p) {
    uint32_t a;
    asm("{ .reg .u64 t; cvta.to.shared.u64 t, %1; cvt.u32.u64 %0, t; }" : "=r"(a) : "l"(p));
    return a;
}
__device__ __forceinline__ void cp16(uint32_t so, const void* g) {
    asm volatile("cp.async.cg.shared.global [%0], [%1], 16;" :: "r"(so), "l"(g));
}
#define CP_COMMIT() asm volatile("cp.async.commit_group;" ::: "memory")
#define CP_WAIT1()  asm volatile("cp.async.wait_group 1;" ::: "memory")
#define CP_WAIT0()  asm volatile("cp.async.wait_group 0;" ::: "memory")

__device__ __forceinline__ void ldm_x4(uint32_t* r, uint32_t addr) {
    asm volatile("ldmatrix.sync.aligned.m8n8.x4.shared.b16 {%0,%1,%2,%3}, [%4];"
                 : "=r"(r[0]), "=r"(r[1]), "=r"(r[2]), "=r"(r[3]) : "r"(addr));
}
__device__ __forceinline__ void ldm_x4_t(uint32_t* r, uint32_t addr) {
    asm volatile("ldmatrix.sync.aligned.m8n8.x4.trans.shared.b16 {%0,%1,%2,%3}, [%4];"
                 : "=r"(r[0]), "=r"(r[1]), "=r"(r[2]), "=r"(r[3]) : "r"(addr));
}
__device__ __forceinline__ void mma_bf16(float* c, const uint32_t* a, const uint32_t* b) {
    asm volatile(
        "mma.sync.aligned.m16n8k16.row.col.f32.bf16.bf16.f32 "
        "{%0,%1,%2,%3}, {%4,%5,%6,%7}, {%8,%9}, {%0,%1,%2,%3};"
        : "+f"(c[0]), "+f"(c[1]), "+f"(c[2]), "+f"(c[3])
        : "r"(a[0]), "r"(a[1]), "r"(a[2]), "r"(a[3]), "r"(b[0]), "r"(b[1]));
}
__device__ __forceinline__ void mma_f16(float* c, const uint32_t* a, const uint32_t* b) {
    asm volatile(
        "mma.sync.aligned.m16n8k16.row.col.f32.f16.f16.f32 "
        "{%0,%1,%2,%3}, {%4,%5,%6,%7}, {%8,%9}, {%0,%1,%2,%3};"
        : "+f"(c[0]), "+f"(c[1]), "+f"(c[2]), "+f"(c[3])
        : "r"(a[0]), "r"(a[1]), "r"(a[2]), "r"(a[3]), "r"(b[0]), "r"(b[1]));
}
__device__ __forceinline__ uint32_t pack_bf16(float a, float b) {
    return (uint32_t)__bfloat16_as_ushort(__float2bfloat16(a)) |
           ((uint32_t)__bfloat16_as_ushort(__float2bfloat16(b)) << 16);
}
__device__ __forceinline__ uint32_t pack_f16(float a, float b) {
    const __half2 h = __halves2half2(__float2half_rn(a), __float2half_rn(b));
    return *(const uint32_t*)&h;
}

// ---------------------------------------------------------------- GEMM core
__device__ __forceinline__ void tile_async(uint32_t sdst, const __half* src,
                                           int row0, int k0, int K) {
    const int tid = threadIdx.x;
#pragma unroll
    for (int c = 0; c < 2; c++) {
        const int chunk = tid + c * 256;
        const int r = chunk >> 2, c16 = chunk & 3;
        cp16(sdst + (uint32_t)(r * (PAD_K * 2) + c16 * 16),
             src + (size_t)(row0 + r) * K + k0 + c16 * 8);
    }
}

// Mainloop producing acc[4][4][4]; shared by both GEMM kernels.
__device__ __forceinline__ void gemm_main(const __half* Aw, const __half* Bw,
                                          uint32_t sb, int row0, int col0, int K,
                                          float acc[4][4][4]) {
    const int tid = threadIdx.x;
    const int wid = tid >> 5, lane = tid & 31;
    const int wm = wid & 1, wn = wid >> 1;

#pragma unroll
    for (int i = 0; i < 4; i++)
#pragma unroll
        for (int j = 0; j < 4; j++)
#pragma unroll
            for (int t = 0; t < 4; t++) acc[i][j][t] = 0.f;

#pragma unroll
    for (int s = 0; s < 2; s++) {
        const uint32_t st = sb + s * STG;
        tile_async(st + 0 * TILE_B, Aw, row0, s * BK, K);
        tile_async(st + 1 * TILE_B, Bw, col0, s * BK, K);
        CP_COMMIT();
    }

    const uint32_t a_row = (uint32_t)(wm * 64 + (lane & 15));
    const uint32_t a_kof = (uint32_t)((lane >> 4) * 8);
    const uint32_t b_row = (uint32_t)(wn * 32 + (lane & 7) + ((lane >> 4) << 3));
    const uint32_t b_kof = (uint32_t)(((lane >> 3) & 1) * 8);

    for (int it = 0; it < NKSTEP; it++) {
        CP_WAIT1();
        __syncthreads();

        if (it + 2 < NKSTEP) {
            const uint32_t st = sb + ((it + 2) % NSTAGE) * STG;
            const int k0 = (it + 2) * BK;
            tile_async(st + 0 * TILE_B, Aw, row0, k0, K);
            tile_async(st + 1 * TILE_B, Bw, col0, k0, K);
        }
        CP_COMMIT();

        const uint32_t st = sb + (it % NSTAGE) * STG;
#pragma unroll
        for (int kk = 0; kk < BK; kk += 16) {
            uint32_t aw[4][4], bw[2][4];
#pragma unroll
            for (int i = 0; i < 4; i++) {
                const uint32_t ao = ((a_row + i * 16) * PAD_K + kk + a_kof) * 2;
                ldm_x4(aw[i], st + 0 * TILE_B + ao);
            }
#pragma unroll
            for (int p = 0; p < 2; p++) {
                const uint32_t bo = ((b_row + p * 16) * PAD_K + kk + b_kof) * 2;
                ldm_x4(bw[p], st + 1 * TILE_B + bo);
            }
#pragma unroll
            for (int i = 0; i < 4; i++)
#pragma unroll
                for (int j = 0; j < 4; j++)
                    mma_f16(acc[i][j], aw[i], &bw[j >> 1][(j & 1) * 2]);
        }
        __syncthreads();
    }
}

// Fused QKV GEMM: z=0 -> qh/ql (bf16 hi/lo), z=1 -> kh/kl, z=2 -> vh (fp16)
__global__ __launch_bounds__(256)
void gemm_qkv(const __half* __restrict__ Aw, const __half* __restrict__ wt,
              const float* __restrict__ bq, const float* __restrict__ bk,
              const float* __restrict__ bv,
              __nv_bfloat16* __restrict__ qh, __nv_bfloat16* __restrict__ ql,
              __nv_bfloat16* __restrict__ kh, __nv_bfloat16* __restrict__ kl,
              __half* __restrict__ vh, int M, int N, int K)
{
    extern __shared__ char sm[];
    const uint32_t sb = smem_u32(sm);
    const int z = blockIdx.z;
    const int row0 = blockIdx.y * BM, col0 = blockIdx.x * BN;
    const __half* Bw = wt + (size_t)z * WSL;
    const float* bias = (z == 0) ? bq : (z == 1) ? bk : bv;

    float acc[4][4][4];
    gemm_main(Aw, Bw, sb, row0, col0, K, acc);

    const int tid = threadIdx.x;
    const int wid = tid >> 5, lane = tid & 31;
    const int wm = wid & 1, wn = wid >> 1;
    const int rbase = row0 + wm * 64 + (lane >> 2);
    const int cbase = col0 + wn * 32 + (lane & 3) * 2;

    __nv_bfloat16* oh = (z == 0) ? qh : kh;
    __nv_bfloat16* ol = (z == 0) ? ql : kl;
#pragma unroll
    for (int i = 0; i < 4; i++)
#pragma unroll
        for (int j = 0; j < 4; j++) {
            const int cc = cbase + j * 8;
            const float b0 = bias[cc], b1 = bias[cc + 1];
#pragma unroll
            for (int hrow = 0; hrow < 2; hrow++) {
                const int rr = rbase + i * 16 + hrow * 8;
                const float v0 = acc[i][j][hrow * 2 + 0] + b0;
                const float v1 = acc[i][j][hrow * 2 + 1] + b1;
                const size_t o = (size_t)rr * N + cc;
                if (z == 2) {
                    *(uint32_t*)(vh + o) = pack_f16(v0, v1);
                } else {
                    const __nv_bfloat16 h0 = __float2bfloat16(v0);
                    const __nv_bfloat16 h1 = __float2bfloat16(v1);
                    *(uint32_t*)(oh + o) =
                        (uint32_t)__bfloat16_as_ushort(h0) |
                        ((uint32_t)__bfloat16_as_ushort(h1) << 16);
                    *(uint32_t*)(ol + o) =
                        pack_bf16(v0 - __bfloat162float(h0), v1 - __bfloat162float(h1));
                }
            }
        }
}

// Output GEMM: fp32 out
__global__ __launch_bounds__(256)
void gemm_out(const __half* __restrict__ Aw, const __half* __restrict__ Bw,
              const float* __restrict__ bias, float* __restrict__ C,
              int M, int N, int K)
{
    extern __shared__ char sm[];
    const uint32_t sb = smem_u32(sm);
    const int row0 = blockIdx.y * BM, col0 = blockIdx.x * BN;

    float acc[4][4][4];
    gemm_main(Aw, Bw, sb, row0, col0, K, acc);

    const int tid = threadIdx.x;
    const int wid = tid >> 5, lane = tid & 31;
    const int wm = wid & 1, wn = wid >> 1;
    const int rbase = row0 + wm * 64 + (lane >> 2);
    const int cbase = col0 + wn * 32 + (lane & 3) * 2;
#pragma unroll
    for (int i = 0; i < 4; i++)
#pragma unroll
        for (int j = 0; j < 4; j++) {
            const int cc = cbase + j * 8;
            const float b0 = bias[cc], b1 = bias[cc + 1];
#pragma unroll
            for (int hrow = 0; hrow < 2; hrow++) {
                const int rr = rbase + i * 16 + hrow * 8;
                *(float2*)(C + (size_t)rr * N + cc) = make_float2(
                    acc[i][j][hrow * 2 + 0] + b0, acc[i][j][hrow * 2 + 1] + b1);
            }
        }
}

// ---------------------------------------------------------------- conversions
__global__ void tof16(const float4* __restrict__ in, uint2* __restrict__ hi, int n4)
{
    const int i = blockIdx.x * blockDim.x + threadIdx.x;
    if (i >= n4) return;
    const float4 a = in[i];
    hi[i] = make_uint2(pack_f16(a.x, a.y), pack_f16(a.z, a.w));
}

// all 4 weight transposes in one launch (z selects weight)
__global__ void wsplit4(const float* __restrict__ Wq, const float* __restrict__ Wk,
                        const float* __restrict__ Wv, const float* __restrict__ Wo,
                        __half* __restrict__ th)
{
    __shared__ float t[32][33];
    const int z = blockIdx.z;
    const float* W = (z == 0) ? Wq : (z == 1) ? Wk : (z == 2) ? Wv : Wo;
    __half* out = th + (size_t)z * WSL;
    const int n0 = blockIdx.x * 32, k0 = blockIdx.y * 32;
    const int tx = threadIdx.x, ty = threadIdx.y;
    for (int i = ty; i < 32; i += 8)
        t[i][tx] = W[(size_t)(k0 + i) * NDIM + n0 + tx];
    __syncthreads();
    for (int i = ty; i < 32; i += 8)
        out[(size_t)(n0 + i) * KDIM + k0 + tx] = __float2half_rn(t[tx][i]);
}

// ---------------------------------------------------------------- attention
// Flash-style: per 16-key tile compute S (bf16 3-product), exp in registers,
// repack accumulators as fp16 A-fragments (identity relayout), immediately
// accumulate O += P*V. No P smem, no P ldmatrix. 1/l via shfl.
__global__ __launch_bounds__(128, 2) void attn_tc(
    const __nv_bfloat16* __restrict__ qh_g, const __nv_bfloat16* __restrict__ ql_g,
    const __nv_bfloat16* __restrict__ kh_g, const __nv_bfloat16* __restrict__ kl_g,
    const __half* __restrict__ vh_g, const float* __restrict__ decay,
    __half* __restrict__ ao)
{
    const int c = blockIdx.x, h = blockIdx.y, b = blockIdx.z;
    const int tid = threadIdx.x, wm = tid >> 5, lane = tid & 31;

    extern __shared__ char sma[];
    const uint32_t sb = smem_u32(sma);
    float* df = (float*)(sma + AT_DF);

    const size_t base = ((size_t)b * L_SZ + (size_t)c * CHUNK) * D_MODEL + h * D_HEAD;

    // zero pad rows 129..143 of Kh/Kl/Vh
    {
        const uint4 z = make_uint4(0, 0, 0, 0);
        for (int i = tid; i < 135; i += 128) {
            *(uint4*)(sma + AT_KH + 129 * 144 + i * 16) = z;
            *(uint4*)(sma + AT_KL + 129 * 144 + i * 16) = z;
            *(uint4*)(sma + AT_VH + 129 * 144 + i * 16) = z;
        }
        if (c == 0 && tid < 9) {
            *(uint4*)(sma + AT_KH + tid * 16) = z;
            *(uint4*)(sma + AT_KL + tid * 16) = z;
            *(uint4*)(sma + AT_VH + tid * 16) = z;
        }
    }

    // cp.async loads
    for (int idx = tid; idx < 128 * 8; idx += 128) {
        const int r = idx >> 3, ch = idx & 7;
        const uint32_t so = (uint32_t)(r * 144 + ch * 16);
        const size_t g = base + (size_t)r * D_MODEL + ch * 8;
        cp16(sb + AT_QH + so, qh_g + g);
        cp16(sb + AT_QL + so, ql_g + g);
        cp16(sb + AT_KH + 144 + so, kh_g + g);
        cp16(sb + AT_KL + 144 + so, kl_g + g);
        cp16(sb + AT_VH + 144 + so, vh_g + g);
    }
    if (c > 0 && tid < 8) {
        const size_t g0 = base - D_MODEL + tid * 8;
        cp16(sb + AT_KH + tid * 16, kh_g + g0);
        cp16(sb + AT_KL + tid * 16, kl_g + g0);
        cp16(sb + AT_VH + tid * 16, vh_g + g0);
    }
    CP_COMMIT();
    df[tid] = 0.125f * powf(decay[h], (float)tid);
    CP_WAIT0();
    __syncthreads();

    const uint32_t a_ro = (uint32_t)(lane & 15);
    const uint32_t a_ko = (uint32_t)((lane >> 4) * 8);
    const uint32_t b_ro = (uint32_t)((lane & 7) + ((lane >> 4) << 3));
    const uint32_t b_ko = (uint32_t)(((lane >> 3) & 1) * 8);
    const uint32_t v_ro = (uint32_t)(lane & 15);
    const uint32_t v_co = (uint32_t)((lane >> 4) << 3);

    // preload Q fragments
    uint32_t qh[2][4][4], ql[2][4][4];
#pragma unroll
    for (int mt = 0; mt < 2; mt++)
#pragma unroll
        for (int kt = 0; kt < 4; kt++) {
            const uint32_t aoff = ((wm * 32 + mt * 16 + a_ro) * 72 + kt * 16 + a_ko) * 2;
            ldm_x4(qh[mt][kt], sb + AT_QH + aoff);
            ldm_x4(ql[mt][kt], sb + AT_QL + aoff);
        }

    const int gr = lane >> 2;
    const int r0a = wm * 32 + gr;
    const float sf0a = df[r0a],      sf0b = df[r0a + 8];
    const float sf1a = df[r0a + 16], sf1b = df[r0a + 24];
    float lsum[2][2] = {{0.f, 0.f}, {0.f, 0.f}};
    float oacc[2][8][4];
#pragma unroll
    for (int mt = 0; mt < 2; mt++)
#pragma unroll
        for (int n8 = 0; n8 < 8; n8++)
#pragma unroll
            for (int t = 0; t < 4; t++) oacc[mt][n8][t] = 0.f;

#pragma unroll
    for (int nt = 0; nt < 9; nt++) {
        // K fragments for this 16-key tile
        uint32_t kh[4][4], kl[4][4];
#pragma unroll
        for (int kt = 0; kt < 4; kt++) {
            const uint32_t bo = ((nt * 16 + b_ro) * 72 + kt * 16 + b_ko) * 2;
            ldm_x4(kh[kt], sb + AT_KH + bo);
            ldm_x4(kl[kt], sb + AT_KL + bo);
        }
        // V fragments for this 16-key k-tile (keys x 64 dims)
        uint32_t vfr[4][4];
#pragma unroll
        for (int g = 0; g < 4; g++) {
            const uint32_t bo = ((nt * 16 + v_ro) * 72 + g * 16 + v_co) * 2;
            ldm_x4_t(vfr[g], sb + AT_VH + bo);
        }

#pragma unroll
        for (int mt = 0; mt < 2; mt++) {
            const float sfa = mt ? sf1a : sf0a;
            const float sfb = mt ? sf1b : sf0b;
            float pf[2][4];
#pragma unroll
            for (int half = 0; half < 2; half++) {
                float acc[4] = {0.f, 0.f, 0.f, 0.f};
#pragma unroll
                for (int kt = 0; kt < 4; kt++) {
                    mma_bf16(acc, qh[mt][kt], &kh[kt][half * 2]);
                    mma_bf16(acc, qh[mt][kt], &kl[kt][half * 2]);
                    mma_bf16(acc, ql[mt][kt], &kh[kt][half * 2]);
                }
                const int c0 = nt * 16 + half * 8 + (lane & 3) * 2;
                pf[half][0] = (c0     < 129) ? __expf(acc[0] * sfa) : 0.f;
                pf[half][1] = (c0 + 1 < 129) ? __expf(acc[1] * sfa) : 0.f;
                pf[half][2] = (c0     < 129) ? __expf(acc[2] * sfb) : 0.f;
                pf[half][3] = (c0 + 1 < 129) ? __expf(acc[3] * sfb) : 0.f;
                lsum[mt][0] += pf[half][0] + pf[half][1];
                lsum[mt][1] += pf[half][2] + pf[half][3];
            }
            // accumulator -> A-fragment relayout (identity in registers)
            uint32_t pa[4];
            pa[0] = pack_f16(pf[0][0], pf[0][1]);   // (gr,   2c),(gr,   2c+1)
            pa[1] = pack_f16(pf[0][2], pf[0][3]);   // (gr+8, 2c),(gr+8, 2c+1)
            pa[2] = pack_f16(pf[1][0], pf[1][1]);   // (gr,   2c+8),(gr, 2c+9)
            pa[3] = pack_f16(pf[1][2], pf[1][3]);   // (gr+8, 2c+8),...
#pragma unroll
            for (int n8 = 0; n8 < 8; n8++)
                mma_f16(oacc[mt][n8], pa, &vfr[n8 >> 1][(n8 & 1) * 2]);
        }
    }

    // 1/l in registers via 4-lane shuffle reduce
    float inv[2][2];
#pragma unroll
    for (int mt = 0; mt < 2; mt++)
#pragma unroll
        for (int rh = 0; rh < 2; rh++) {
            float s = lsum[mt][rh];
            s += __shfl_xor_sync(0xFFFFFFFFu, s, 1);
            s += __shfl_xor_sync(0xFFFFFFFFu, s, 2);
            inv[mt][rh] = 1.f / s;
        }

    // epilogue
#pragma unroll
    for (int mt = 0; mt < 2; mt++) {
        const int r0 = wm * 32 + mt * 16 + gr;
#pragma unroll
        for (int n8 = 0; n8 < 8; n8++) {
            const int c0 = n8 * 8 + (lane & 3) * 2;
#pragma unroll
            for (int hrow = 0; hrow < 2; hrow++) {
                const int rr = r0 + hrow * 8;
                const float iv = inv[mt][hrow];
                *(uint32_t*)(ao + base + (size_t)rr * D_MODEL + c0) = pack_f16(
                    oacc[mt][n8][hrow * 2 + 0] * iv,
                    oacc[mt][n8][hrow * 2 + 1] * iv);
            }
        }
    }
}

// ---------------------------------------------------------------- launch
extern "C" void kernel_launch(void* const* d_in, const int* in_sizes, int n_in,
                              void* d_out, int out_size)
{
    const float* x     = (const float*)d_in[0];
    const float* Wq    = (const float*)d_in[1];
    const float* bq    = (const float*)d_in[2];
    const float* Wk    = (const float*)d_in[3];
    const float* bk    = (const float*)d_in[4];
    const float* Wv    = (const float*)d_in[5];
    const float* bv    = (const float*)d_in[6];
    const float* Wo    = (const float*)d_in[7];
    const float* bo    = (const float*)d_in[8];
    const float* decay = (const float*)d_in[9];
    float* out = (float*)d_out;

    __half *xh, *ao, *wt, *vh;
    __nv_bfloat16 *qh, *ql, *kh, *kl;
    cudaGetSymbolAddress((void**)&xh, g_xh);
    cudaGetSymbolAddress((void**)&ao, g_ao);
    cudaGetSymbolAddress((void**)&wt, g_wt);
    cudaGetSymbolAddress((void**)&qh, g_qh);
    cudaGetSymbolAddress((void**)&ql, g_ql);
    cudaGetSymbolAddress((void**)&kh, g_kh);
    cudaGetSymbolAddress((void**)&kl, g_kl);
    cudaGetSymbolAddress((void**)&vh, g_vh);

    cudaFuncSetAttribute(gemm_qkv, cudaFuncAttributeMaxDynamicSharedMemorySize, GSMEM);
    cudaFuncSetAttribute(gemm_out, cudaFuncAttributeMaxDynamicSharedMemorySize, GSMEM);
    cudaFuncSetAttribute(attn_tc, cudaFuncAttributeMaxDynamicSharedMemorySize, AT_SZ);

    wsplit4<<<dim3(NDIM / 32, KDIM / 32, 4), dim3(32, 8)>>>(Wq, Wk, Wv, Wo, wt);

    const int n4 = M_TOT * D_MODEL / 4;
    tof16<<<(n4 + 255) / 256, 256>>>((const float4*)x, (uint2*)xh, n4);

    gemm_qkv<<<dim3(NDIM / BN, M_TOT / BM, 3), 256, GSMEM>>>(
        xh, wt, bq, bk, bv, qh, ql, kh, kl, vh, M_TOT, NDIM, KDIM);

    attn_tc<<<dim3(NCHUNK, N_HEADS, B_SZ), 128, AT_SZ>>>(qh, ql, kh, kl, vh, decay, ao);

    gemm_out<<<dim3(NDIM / BN, M_TOT / BM), 256, GSMEM>>>(
        ao, wt + 3 * (size_t)WSL, bo, out, M_TOT, NDIM, KDIM);
}

// round 14
// speedup vs baseline: 6.9250x; 1.0793x over previous
#include <cuda_runtime.h>
#include <cuda_bf16.h>
#include <cuda_fp16.h>
#include <math.h>
#include <stdint.h>

// ---------------------------------------------------------------- constants
#define B_SZ 4
#define L_SZ 4096
#define D_MODEL 1024
#define N_HEADS 16
#define D_HEAD 64
#define CHUNK 128
#define NCHUNK 32
#define M_TOT (B_SZ * L_SZ)      // 16384
#define KDIM 1024
#define NDIM 1024
#define WSL (KDIM * NDIM)

// GEMM tiling
#define BM 128
#define BN 128
#define BK 32
#define NKSTEP (KDIM / BK)       // 32
#define PAD_K 40
#define TILE_B (128 * PAD_K * 2)
#define STG (2 * TILE_B)         // 20480
#define NSTAGE 3
#define GSMEM (NSTAGE * STG)     // 61440

// attention smem layout (bytes) — all fp16, no hi/lo, no P buffer
#define AT_Q 0                    // Q fp16 [128][72]
#define AT_K 18432                // K fp16 [144][72]
#define AT_V 39168                // V fp16 [144][72] row-major (ldmatrix.trans)
#define AT_DF 59904               // decay prefactor, 128 f32
#define AT_SZ 60416               // 59 KB

// ---------------------------------------------------------------- scratch
__device__ __half g_xh[M_TOT * D_MODEL];
__device__ __half g_ao[M_TOT * D_MODEL];
__device__ __half g_wt[4 * WSL];                 // W^T [N,K] fp16
__device__ __half g_q16[M_TOT * D_MODEL];
__device__ __half g_k16[M_TOT * D_MODEL];
__device__ __half g_v16[M_TOT * D_MODEL];

// ---------------------------------------------------------------- helpers
__device__ __forceinline__ uint32_t smem_u32(const void* p) {
    uint32_t a;
    asm("{ .reg .u64 t; cvta.to.shared.u64 t, %1; cvt.u32.u64 %0, t; }" : "=r"(a) : "l"(p));
    return a;
}
__device__ __forceinline__ void cp16(uint32_t so, const void* g) {
    asm volatile("cp.async.cg.shared.global [%0], [%1], 16;" :: "r"(so), "l"(g));
}
#define CP_COMMIT() asm volatile("cp.async.commit_group;" ::: "memory")
#define CP_WAIT1()  asm volatile("cp.async.wait_group 1;" ::: "memory")
#define CP_WAIT0()  asm volatile("cp.async.wait_group 0;" ::: "memory")

__device__ __forceinline__ void ldm_x4(uint32_t* r, uint32_t addr) {
    asm volatile("ldmatrix.sync.aligned.m8n8.x4.shared.b16 {%0,%1,%2,%3}, [%4];"
                 : "=r"(r[0]), "=r"(r[1]), "=r"(r[2]), "=r"(r[3]) : "r"(addr));
}
__device__ __forceinline__ void ldm_x4_t(uint32_t* r, uint32_t addr) {
    asm volatile("ldmatrix.sync.aligned.m8n8.x4.trans.shared.b16 {%0,%1,%2,%3}, [%4];"
                 : "=r"(r[0]), "=r"(r[1]), "=r"(r[2]), "=r"(r[3]) : "r"(addr));
}
__device__ __forceinline__ void mma_f16(float* c, const uint32_t* a, const uint32_t* b) {
    asm volatile(
        "mma.sync.aligned.m16n8k16.row.col.f32.f16.f16.f32 "
        "{%0,%1,%2,%3}, {%4,%5,%6,%7}, {%8,%9}, {%0,%1,%2,%3};"
        : "+f"(c[0]), "+f"(c[1]), "+f"(c[2]), "+f"(c[3])
        : "r"(a[0]), "r"(a[1]), "r"(a[2]), "r"(a[3]), "r"(b[0]), "r"(b[1]));
}
__device__ __forceinline__ uint32_t pack_f16(float a, float b) {
    const __half2 h = __halves2half2(__float2half_rn(a), __float2half_rn(b));
    return *(const uint32_t*)&h;
}

// ---------------------------------------------------------------- GEMM core
__device__ __forceinline__ void tile_async(uint32_t sdst, const __half* src,
                                           int row0, int k0, int K) {
    const int tid = threadIdx.x;
#pragma unroll
    for (int c = 0; c < 2; c++) {
        const int chunk = tid + c * 256;
        const int r = chunk >> 2, c16 = chunk & 3;
        cp16(sdst + (uint32_t)(r * (PAD_K * 2) + c16 * 16),
             src + (size_t)(row0 + r) * K + k0 + c16 * 8);
    }
}

__device__ __forceinline__ void gemm_main(const __half* Aw, const __half* Bw,
                                          uint32_t sb, int row0, int col0, int K,
                                          float acc[4][4][4]) {
    const int tid = threadIdx.x;
    const int wid = tid >> 5, lane = tid & 31;
    const int wm = wid & 1, wn = wid >> 1;

#pragma unroll
    for (int i = 0; i < 4; i++)
#pragma unroll
        for (int j = 0; j < 4; j++)
#pragma unroll
            for (int t = 0; t < 4; t++) acc[i][j][t] = 0.f;

#pragma unroll
    for (int s = 0; s < 2; s++) {
        const uint32_t st = sb + s * STG;
        tile_async(st + 0 * TILE_B, Aw, row0, s * BK, K);
        tile_async(st + 1 * TILE_B, Bw, col0, s * BK, K);
        CP_COMMIT();
    }

    const uint32_t a_row = (uint32_t)(wm * 64 + (lane & 15));
    const uint32_t a_kof = (uint32_t)((lane >> 4) * 8);
    const uint32_t b_row = (uint32_t)(wn * 32 + (lane & 7) + ((lane >> 4) << 3));
    const uint32_t b_kof = (uint32_t)(((lane >> 3) & 1) * 8);

    for (int it = 0; it < NKSTEP; it++) {
        CP_WAIT1();
        __syncthreads();

        if (it + 2 < NKSTEP) {
            const uint32_t st = sb + ((it + 2) % NSTAGE) * STG;
            const int k0 = (it + 2) * BK;
            tile_async(st + 0 * TILE_B, Aw, row0, k0, K);
            tile_async(st + 1 * TILE_B, Bw, col0, k0, K);
        }
        CP_COMMIT();

        const uint32_t st = sb + (it % NSTAGE) * STG;
#pragma unroll
        for (int kk = 0; kk < BK; kk += 16) {
            uint32_t aw[4][4], bw[2][4];
#pragma unroll
            for (int i = 0; i < 4; i++) {
                const uint32_t ao = ((a_row + i * 16) * PAD_K + kk + a_kof) * 2;
                ldm_x4(aw[i], st + 0 * TILE_B + ao);
            }
#pragma unroll
            for (int p = 0; p < 2; p++) {
                const uint32_t bo = ((b_row + p * 16) * PAD_K + kk + b_kof) * 2;
                ldm_x4(bw[p], st + 1 * TILE_B + bo);
            }
#pragma unroll
            for (int i = 0; i < 4; i++)
#pragma unroll
                for (int j = 0; j < 4; j++)
                    mma_f16(acc[i][j], aw[i], &bw[j >> 1][(j & 1) * 2]);
        }
        __syncthreads();
    }
}

// Fused QKV GEMM: z selects weight slice + bias + output (all fp16 out)
__global__ __launch_bounds__(256)
void gemm_qkv(const __half* __restrict__ Aw, const __half* __restrict__ wt,
              const float* __restrict__ bq, const float* __restrict__ bk,
              const float* __restrict__ bv,
              __half* __restrict__ q16, __half* __restrict__ k16,
              __half* __restrict__ v16, int M, int N, int K)
{
    extern __shared__ char sm[];
    const uint32_t sb = smem_u32(sm);
    const int z = blockIdx.z;
    const int row0 = blockIdx.y * BM, col0 = blockIdx.x * BN;
    const __half* Bw = wt + (size_t)z * WSL;
    const float* bias = (z == 0) ? bq : (z == 1) ? bk : bv;
    __half* outp = (z == 0) ? q16 : (z == 1) ? k16 : v16;

    float acc[4][4][4];
    gemm_main(Aw, Bw, sb, row0, col0, K, acc);

    const int tid = threadIdx.x;
    const int wid = tid >> 5, lane = tid & 31;
    const int wm = wid & 1, wn = wid >> 1;
    const int rbase = row0 + wm * 64 + (lane >> 2);
    const int cbase = col0 + wn * 32 + (lane & 3) * 2;
#pragma unroll
    for (int i = 0; i < 4; i++)
#pragma unroll
        for (int j = 0; j < 4; j++) {
            const int cc = cbase + j * 8;
            const float b0 = bias[cc], b1 = bias[cc + 1];
#pragma unroll
            for (int hrow = 0; hrow < 2; hrow++) {
                const int rr = rbase + i * 16 + hrow * 8;
                *(uint32_t*)(outp + (size_t)rr * N + cc) = pack_f16(
                    acc[i][j][hrow * 2 + 0] + b0, acc[i][j][hrow * 2 + 1] + b1);
            }
        }
}

// Output GEMM: fp32 out
__global__ __launch_bounds__(256)
void gemm_out(const __half* __restrict__ Aw, const __half* __restrict__ Bw,
              const float* __restrict__ bias, float* __restrict__ C,
              int M, int N, int K)
{
    extern __shared__ char sm[];
    const uint32_t sb = smem_u32(sm);
    const int row0 = blockIdx.y * BM, col0 = blockIdx.x * BN;

    float acc[4][4][4];
    gemm_main(Aw, Bw, sb, row0, col0, K, acc);

    const int tid = threadIdx.x;
    const int wid = tid >> 5, lane = tid & 31;
    const int wm = wid & 1, wn = wid >> 1;
    const int rbase = row0 + wm * 64 + (lane >> 2);
    const int cbase = col0 + wn * 32 + (lane & 3) * 2;
#pragma unroll
    for (int i = 0; i < 4; i++)
#pragma unroll
        for (int j = 0; j < 4; j++) {
            const int cc = cbase + j * 8;
            const float b0 = bias[cc], b1 = bias[cc + 1];
#pragma unroll
            for (int hrow = 0; hrow < 2; hrow++) {
                const int rr = rbase + i * 16 + hrow * 8;
                *(float2*)(C + (size_t)rr * N + cc) = make_float2(
                    acc[i][j][hrow * 2 + 0] + b0, acc[i][j][hrow * 2 + 1] + b1);
            }
        }
}

// ---------------------------------------------------------------- conversions
__global__ void tof16(const float4* __restrict__ in, uint2* __restrict__ hi, int n4)
{
    const int i = blockIdx.x * blockDim.x + threadIdx.x;
    if (i >= n4) return;
    const float4 a = in[i];
    hi[i] = make_uint2(pack_f16(a.x, a.y), pack_f16(a.z, a.w));
}

__global__ void wsplit4(const float* __restrict__ Wq, const float* __restrict__ Wk,
                        const float* __restrict__ Wv, const float* __restrict__ Wo,
                        __half* __restrict__ th)
{
    __shared__ float t[32][33];
    const int z = blockIdx.z;
    const float* W = (z == 0) ? Wq : (z == 1) ? Wk : (z == 2) ? Wv : Wo;
    __half* out = th + (size_t)z * WSL;
    const int n0 = blockIdx.x * 32, k0 = blockIdx.y * 32;
    const int tx = threadIdx.x, ty = threadIdx.y;
    for (int i = ty; i < 32; i += 8)
        t[i][tx] = W[(size_t)(k0 + i) * NDIM + n0 + tx];
    __syncthreads();
    for (int i = ty; i < 32; i += 8)
        out[(size_t)(n0 + i) * KDIM + k0 + tx] = __float2half_rn(t[tx][i]);
}

// ---------------------------------------------------------------- attention
// All-fp16 flash-style: S = Q K^T (single product), exp in registers,
// accumulator->A-fragment identity relayout, O += P*V. 1/l via shfl.
__global__ __launch_bounds__(128, 2) void attn_tc(
    const __half* __restrict__ q_g, const __half* __restrict__ k_g,
    const __half* __restrict__ v_g, const float* __restrict__ decay,
    __half* __restrict__ ao)
{
    const int c = blockIdx.x, h = blockIdx.y, b = blockIdx.z;
    const int tid = threadIdx.x, wm = tid >> 5, lane = tid & 31;

    extern __shared__ char sma[];
    const uint32_t sb = smem_u32(sma);
    float* df = (float*)(sma + AT_DF);

    const size_t base = ((size_t)b * L_SZ + (size_t)c * CHUNK) * D_MODEL + h * D_HEAD;

    // zero pad rows 129..143 of K/V
    {
        const uint4 z = make_uint4(0, 0, 0, 0);
        for (int i = tid; i < 135; i += 128) {
            *(uint4*)(sma + AT_K + 129 * 144 + i * 16) = z;
            *(uint4*)(sma + AT_V + 129 * 144 + i * 16) = z;
        }
        if (c == 0 && tid < 9) {
            *(uint4*)(sma + AT_K + tid * 16) = z;
            *(uint4*)(sma + AT_V + tid * 16) = z;
        }
    }

    // cp.async loads: Q 128 rows, K/V rows 1..128 (+row0 if c>0)
    for (int idx = tid; idx < 128 * 8; idx += 128) {
        const int r = idx >> 3, ch = idx & 7;
        const uint32_t so = (uint32_t)(r * 144 + ch * 16);
        const size_t g = base + (size_t)r * D_MODEL + ch * 8;
        cp16(sb + AT_Q + so, q_g + g);
        cp16(sb + AT_K + 144 + so, k_g + g);
        cp16(sb + AT_V + 144 + so, v_g + g);
    }
    if (c > 0 && tid < 8) {
        const size_t g0 = base - D_MODEL + tid * 8;
        cp16(sb + AT_K + tid * 16, k_g + g0);
        cp16(sb + AT_V + tid * 16, v_g + g0);
    }
    CP_COMMIT();
    df[tid] = 0.125f * powf(decay[h], (float)tid);
    CP_WAIT0();
    __syncthreads();

    const uint32_t a_ro = (uint32_t)(lane & 15);
    const uint32_t a_ko = (uint32_t)((lane >> 4) * 8);
    const uint32_t b_ro = (uint32_t)((lane & 7) + ((lane >> 4) << 3));
    const uint32_t b_ko = (uint32_t)(((lane >> 3) & 1) * 8);
    const uint32_t v_ro = (uint32_t)(lane & 15);
    const uint32_t v_co = (uint32_t)((lane >> 4) << 3);

    // preload Q fragments
    uint32_t qf[2][4][4];
#pragma unroll
    for (int mt = 0; mt < 2; mt++)
#pragma unroll
        for (int kt = 0; kt < 4; kt++) {
            const uint32_t aoff = ((wm * 32 + mt * 16 + a_ro) * 72 + kt * 16 + a_ko) * 2;
            ldm_x4(qf[mt][kt], sb + AT_Q + aoff);
        }

    const int gr = lane >> 2;
    const int r0a = wm * 32 + gr;
    const float sf0a = df[r0a],      sf0b = df[r0a + 8];
    const float sf1a = df[r0a + 16], sf1b = df[r0a + 24];
    float lsum[2][2] = {{0.f, 0.f}, {0.f, 0.f}};
    float oacc[2][8][4];
#pragma unroll
    for (int mt = 0; mt < 2; mt++)
#pragma unroll
        for (int n8 = 0; n8 < 8; n8++)
#pragma unroll
            for (int t = 0; t < 4; t++) oacc[mt][n8][t] = 0.f;

#pragma unroll
    for (int nt = 0; nt < 9; nt++) {
        uint32_t kf[4][4];
#pragma unroll
        for (int kt = 0; kt < 4; kt++) {
            const uint32_t bo = ((nt * 16 + b_ro) * 72 + kt * 16 + b_ko) * 2;
            ldm_x4(kf[kt], sb + AT_K + bo);
        }
        uint32_t vfr[4][4];
#pragma unroll
        for (int g = 0; g < 4; g++) {
            const uint32_t bo = ((nt * 16 + v_ro) * 72 + g * 16 + v_co) * 2;
            ldm_x4_t(vfr[g], sb + AT_V + bo);
        }

#pragma unroll
        for (int mt = 0; mt < 2; mt++) {
            const float sfa = mt ? sf1a : sf0a;
            const float sfb = mt ? sf1b : sf0b;
            float pf[2][4];
#pragma unroll
            for (int half = 0; half < 2; half++) {
                float acc[4] = {0.f, 0.f, 0.f, 0.f};
#pragma unroll
                for (int kt = 0; kt < 4; kt++)
                    mma_f16(acc, qf[mt][kt], &kf[kt][half * 2]);
                const int c0 = nt * 16 + half * 8 + (lane & 3) * 2;
                pf[half][0] = (c0     < 129) ? __expf(acc[0] * sfa) : 0.f;
                pf[half][1] = (c0 + 1 < 129) ? __expf(acc[1] * sfa) : 0.f;
                pf[half][2] = (c0     < 129) ? __expf(acc[2] * sfb) : 0.f;
                pf[half][3] = (c0 + 1 < 129) ? __expf(acc[3] * sfb) : 0.f;
                lsum[mt][0] += pf[half][0] + pf[half][1];
                lsum[mt][1] += pf[half][2] + pf[half][3];
            }
            uint32_t pa[4];
            pa[0] = pack_f16(pf[0][0], pf[0][1]);
            pa[1] = pack_f16(pf[0][2], pf[0][3]);
            pa[2] = pack_f16(pf[1][0], pf[1][1]);
            pa[3] = pack_f16(pf[1][2], pf[1][3]);
#pragma unroll
            for (int n8 = 0; n8 < 8; n8++)
                mma_f16(oacc[mt][n8], pa, &vfr[n8 >> 1][(n8 & 1) * 2]);
        }
    }

    float inv[2][2];
#pragma unroll
    for (int mt = 0; mt < 2; mt++)
#pragma unroll
        for (int rh = 0; rh < 2; rh++) {
            float s = lsum[mt][rh];
            s += __shfl_xor_sync(0xFFFFFFFFu, s, 1);
            s += __shfl_xor_sync(0xFFFFFFFFu, s, 2);
            inv[mt][rh] = 1.f / s;
        }

#pragma unroll
    for (int mt = 0; mt < 2; mt++) {
        const int r0 = wm * 32 + mt * 16 + gr;
#pragma unroll
        for (int n8 = 0; n8 < 8; n8++) {
            const int c0 = n8 * 8 + (lane & 3) * 2;
#pragma unroll
            for (int hrow = 0; hrow < 2; hrow++) {
                const int rr = r0 + hrow * 8;
                const float iv = inv[mt][hrow];
                *(uint32_t*)(ao + base + (size_t)rr * D_MODEL + c0) = pack_f16(
                    oacc[mt][n8][hrow * 2 + 0] * iv,
                    oacc[mt][n8][hrow * 2 + 1] * iv);
            }
        }
    }
}

// ---------------------------------------------------------------- launch
extern "C" void kernel_launch(void* const* d_in, const int* in_sizes, int n_in,
                              void* d_out, int out_size)
{
    const float* x     = (const float*)d_in[0];
    const float* Wq    = (const float*)d_in[1];
    const float* bq    = (const float*)d_in[2];
    const float* Wk    = (const float*)d_in[3];
    const float* bk    = (const float*)d_in[4];
    const float* Wv    = (const float*)d_in[5];
    const float* bv    = (const float*)d_in[6];
    const float* Wo    = (const float*)d_in[7];
    const float* bo    = (const float*)d_in[8];
    const float* decay = (const float*)d_in[9];
    float* out = (float*)d_out;

    __half *xh, *ao, *wt, *q16, *k16, *v16;
    cudaGetSymbolAddress((void**)&xh,  g_xh);
    cudaGetSymbolAddress((void**)&ao,  g_ao);
    cudaGetSymbolAddress((void**)&wt,  g_wt);
    cudaGetSymbolAddress((void**)&q16, g_q16);
    cudaGetSymbolAddress((void**)&k16, g_k16);
    cudaGetSymbolAddress((void**)&v16, g_v16);

    cudaFuncSetAttribute(gemm_qkv, cudaFuncAttributeMaxDynamicSharedMemorySize, GSMEM);
    cudaFuncSetAttribute(gemm_out, cudaFuncAttributeMaxDynamicSharedMemorySize, GSMEM);
    cudaFuncSetAttribute(attn_tc, cudaFuncAttributeMaxDynamicSharedMemorySize, AT_SZ);

    wsplit4<<<dim3(NDIM / 32, KDIM / 32, 4), dim3(32, 8)>>>(Wq, Wk, Wv, Wo, wt);

    const int n4 = M_TOT * D_MODEL / 4;
    tof16<<<(n4 + 255) / 256, 256>>>((const float4*)x, (uint2*)xh, n4);

    gemm_qkv<<<dim3(NDIM / BN, M_TOT / BM, 3), 256, GSMEM>>>(
        xh, wt, bq, bk, bv, q16, k16, v16, M_TOT, NDIM, KDIM);

    attn_tc<<<dim3(NCHUNK, N_HEADS, B_SZ), 128, AT_SZ>>>(q16, k16, v16, decay, ao);

    gemm_out<<<dim3(NDIM / BN, M_TOT / BM), 256, GSMEM>>>(
        ao, wt + 3 * (size_t)WSL, bo, out, M_TOT, NDIM, KDIM);
}

// round 17
// speedup vs baseline: 7.0358x; 1.0160x over previous
#include <cuda_runtime.h>
#include <cuda_bf16.h>
#include <cuda_fp16.h>
#include <math.h>
#include <stdint.h>

// ---------------------------------------------------------------- constants
#define B_SZ 4
#define L_SZ 4096
#define D_MODEL 1024
#define N_HEADS 16
#define D_HEAD 64
#define CHUNK 128
#define NCHUNK 32
#define M_TOT (B_SZ * L_SZ)      // 16384
#define KDIM 1024
#define NDIM 1024
#define WSL (KDIM * NDIM)

// GEMM tiling
#define BM 128
#define BN 128
#define BK 32
#define NKSTEP (KDIM / BK)       // 32
#define PAD_K 40
#define TILE_B (128 * PAD_K * 2)
#define STG (2 * TILE_B)         // 20480
#define NSTAGE 3
#define GSMEM (NSTAGE * STG)     // 61440

// attention smem layout (bytes) — all fp16
#define AT_Q 0                    // Q fp16 [128][72]
#define AT_K 18432                // K fp16 [144][72]
#define AT_V 39168                // V fp16 [144][72] row-major (ldmatrix.trans)
#define AT_DF 59904               // decay prefactor, 128 f32
#define AT_SZ 60416               // 59 KB -> 2 CTAs/SM

// ---------------------------------------------------------------- scratch
__device__ __half g_xh[M_TOT * D_MODEL];
__device__ __half g_ao[M_TOT * D_MODEL];
__device__ __half g_wt[4 * WSL];                 // W^T [N,K] fp16
__device__ __half g_q16[M_TOT * D_MODEL];
__device__ __half g_k16[M_TOT * D_MODEL];
__device__ __half g_v16[M_TOT * D_MODEL];

// ---------------------------------------------------------------- helpers
__device__ __forceinline__ uint32_t smem_u32(const void* p) {
    uint32_t a;
    asm("{ .reg .u64 t; cvta.to.shared.u64 t, %1; cvt.u32.u64 %0, t; }" : "=r"(a) : "l"(p));
    return a;
}
__device__ __forceinline__ void cp16(uint32_t so, const void* g) {
    asm volatile("cp.async.cg.shared.global [%0], [%1], 16;" :: "r"(so), "l"(g));
}
#define CP_COMMIT() asm volatile("cp.async.commit_group;" ::: "memory")
#define CP_WAIT1()  asm volatile("cp.async.wait_group 1;" ::: "memory")
#define CP_WAIT0()  asm volatile("cp.async.wait_group 0;" ::: "memory")

__device__ __forceinline__ void ldm_x4(uint32_t* r, uint32_t addr) {
    asm volatile("ldmatrix.sync.aligned.m8n8.x4.shared.b16 {%0,%1,%2,%3}, [%4];"
                 : "=r"(r[0]), "=r"(r[1]), "=r"(r[2]), "=r"(r[3]) : "r"(addr));
}
__device__ __forceinline__ void ldm_x4_t(uint32_t* r, uint32_t addr) {
    asm volatile("ldmatrix.sync.aligned.m8n8.x4.trans.shared.b16 {%0,%1,%2,%3}, [%4];"
                 : "=r"(r[0]), "=r"(r[1]), "=r"(r[2]), "=r"(r[3]) : "r"(addr));
}
__device__ __forceinline__ void mma_f16(float* c, const uint32_t* a, const uint32_t* b) {
    asm volatile(
        "mma.sync.aligned.m16n8k16.row.col.f32.f16.f16.f32 "
        "{%0,%1,%2,%3}, {%4,%5,%6,%7}, {%8,%9}, {%0,%1,%2,%3};"
        : "+f"(c[0]), "+f"(c[1]), "+f"(c[2]), "+f"(c[3])
        : "r"(a[0]), "r"(a[1]), "r"(a[2]), "r"(a[3]), "r"(b[0]), "r"(b[1]));
}
__device__ __forceinline__ uint32_t pack_f16(float a, float b) {
    const __half2 h = __halves2half2(__float2half_rn(a), __float2half_rn(b));
    return *(const uint32_t*)&h;
}

// ---------------------------------------------------------------- GEMM core
__device__ __forceinline__ void tile_async(uint32_t sdst, const __half* src,
                                           int row0, int k0, int K) {
    const int tid = threadIdx.x;
#pragma unroll
    for (int c = 0; c < 2; c++) {
        const int chunk = tid + c * 256;
        const int r = chunk >> 2, c16 = chunk & 3;
        cp16(sdst + (uint32_t)(r * (PAD_K * 2) + c16 * 16),
             src + (size_t)(row0 + r) * K + k0 + c16 * 8);
    }
}

__device__ __forceinline__ void gemm_main(const __half* Aw, const __half* Bw,
                                          uint32_t sb, int row0, int col0, int K,
                                          float acc[4][4][4]) {
    const int tid = threadIdx.x;
    const int wid = tid >> 5, lane = tid & 31;
    const int wm = wid & 1, wn = wid >> 1;

#pragma unroll
    for (int i = 0; i < 4; i++)
#pragma unroll
        for (int j = 0; j < 4; j++)
#pragma unroll
            for (int t = 0; t < 4; t++) acc[i][j][t] = 0.f;

#pragma unroll
    for (int s = 0; s < 2; s++) {
        const uint32_t st = sb + s * STG;
        tile_async(st + 0 * TILE_B, Aw, row0, s * BK, K);
        tile_async(st + 1 * TILE_B, Bw, col0, s * BK, K);
        CP_COMMIT();
    }

    const uint32_t a_row = (uint32_t)(wm * 64 + (lane & 15));
    const uint32_t a_kof = (uint32_t)((lane >> 4) * 8);
    const uint32_t b_row = (uint32_t)(wn * 32 + (lane & 7) + ((lane >> 4) << 3));
    const uint32_t b_kof = (uint32_t)(((lane >> 3) & 1) * 8);

    for (int it = 0; it < NKSTEP; it++) {
        CP_WAIT1();
        __syncthreads();

        if (it + 2 < NKSTEP) {
            const uint32_t st = sb + ((it + 2) % NSTAGE) * STG;
            const int k0 = (it + 2) * BK;
            tile_async(st + 0 * TILE_B, Aw, row0, k0, K);
            tile_async(st + 1 * TILE_B, Bw, col0, k0, K);
        }
        CP_COMMIT();

        const uint32_t st = sb + (it % NSTAGE) * STG;
#pragma unroll
        for (int kk = 0; kk < BK; kk += 16) {
            uint32_t aw[4][4], bw[2][4];
#pragma unroll
            for (int i = 0; i < 4; i++) {
                const uint32_t ao = ((a_row + i * 16) * PAD_K + kk + a_kof) * 2;
                ldm_x4(aw[i], st + 0 * TILE_B + ao);
            }
#pragma unroll
            for (int p = 0; p < 2; p++) {
                const uint32_t bo = ((b_row + p * 16) * PAD_K + kk + b_kof) * 2;
                ldm_x4(bw[p], st + 1 * TILE_B + bo);
            }
#pragma unroll
            for (int i = 0; i < 4; i++)
#pragma unroll
                for (int j = 0; j < 4; j++)
                    mma_f16(acc[i][j], aw[i], &bw[j >> 1][(j & 1) * 2]);
        }
        __syncthreads();
    }
}

// Fused QKV GEMM: z selects weight slice + bias + output (all fp16 out)
__global__ __launch_bounds__(256)
void gemm_qkv(const __half* __restrict__ Aw, const __half* __restrict__ wt,
              const float* __restrict__ bq, const float* __restrict__ bk,
              const float* __restrict__ bv,
              __half* __restrict__ q16, __half* __restrict__ k16,
              __half* __restrict__ v16, int M, int N, int K)
{
    extern __shared__ char sm[];
    const uint32_t sb = smem_u32(sm);
    const int z = blockIdx.z;
    const int row0 = blockIdx.y * BM, col0 = blockIdx.x * BN;
    const __half* Bw = wt + (size_t)z * WSL;
    const float* bias = (z == 0) ? bq : (z == 1) ? bk : bv;
    __half* outp = (z == 0) ? q16 : (z == 1) ? k16 : v16;

    float acc[4][4][4];
    gemm_main(Aw, Bw, sb, row0, col0, K, acc);

    const int tid = threadIdx.x;
    const int wid = tid >> 5, lane = tid & 31;
    const int wm = wid & 1, wn = wid >> 1;
    const int rbase = row0 + wm * 64 + (lane >> 2);
    const int cbase = col0 + wn * 32 + (lane & 3) * 2;
#pragma unroll
    for (int i = 0; i < 4; i++)
#pragma unroll
        for (int j = 0; j < 4; j++) {
            const int cc = cbase + j * 8;
            const float b0 = bias[cc], b1 = bias[cc + 1];
#pragma unroll
            for (int hrow = 0; hrow < 2; hrow++) {
                const int rr = rbase + i * 16 + hrow * 8;
                *(uint32_t*)(outp + (size_t)rr * N + cc) = pack_f16(
                    acc[i][j][hrow * 2 + 0] + b0, acc[i][j][hrow * 2 + 1] + b1);
            }
        }
}

// Output GEMM: fp32 out
__global__ __launch_bounds__(256)
void gemm_out(const __half* __restrict__ Aw, const __half* __restrict__ Bw,
              const float* __restrict__ bias, float* __restrict__ C,
              int M, int N, int K)
{
    extern __shared__ char sm[];
    const uint32_t sb = smem_u32(sm);
    const int row0 = blockIdx.y * BM, col0 = blockIdx.x * BN;

    float acc[4][4][4];
    gemm_main(Aw, Bw, sb, row0, col0, K, acc);

    const int tid = threadIdx.x;
    const int wid = tid >> 5, lane = tid & 31;
    const int wm = wid & 1, wn = wid >> 1;
    const int rbase = row0 + wm * 64 + (lane >> 2);
    const int cbase = col0 + wn * 32 + (lane & 3) * 2;
#pragma unroll
    for (int i = 0; i < 4; i++)
#pragma unroll
        for (int j = 0; j < 4; j++) {
            const int cc = cbase + j * 8;
            const float b0 = bias[cc], b1 = bias[cc + 1];
#pragma unroll
            for (int hrow = 0; hrow < 2; hrow++) {
                const int rr = rbase + i * 16 + hrow * 8;
                *(float2*)(C + (size_t)rr * N + cc) = make_float2(
                    acc[i][j][hrow * 2 + 0] + b0, acc[i][j][hrow * 2 + 1] + b1);
            }
        }
}

// ---------------------------------------------------------------- conversions
__global__ void tof16(const float4* __restrict__ in, uint2* __restrict__ hi, int n4)
{
    const int i = blockIdx.x * blockDim.x + threadIdx.x;
    if (i >= n4) return;
    const float4 a = in[i];
    hi[i] = make_uint2(pack_f16(a.x, a.y), pack_f16(a.z, a.w));
}

__global__ void wsplit4(const float* __restrict__ Wq, const float* __restrict__ Wk,
                        const float* __restrict__ Wv, const float* __restrict__ Wo,
                        __half* __restrict__ th)
{
    __shared__ float t[32][33];
    const int z = blockIdx.z;
    const float* W = (z == 0) ? Wq : (z == 1) ? Wk : (z == 2) ? Wv : Wo;
    __half* out = th + (size_t)z * WSL;
    const int n0 = blockIdx.x * 32, k0 = blockIdx.y * 32;
    const int tx = threadIdx.x, ty = threadIdx.y;
    for (int i = ty; i < 32; i += 8)
        t[i][tx] = W[(size_t)(k0 + i) * NDIM + n0 + tx];
    __syncthreads();
    for (int i = ty; i < 32; i += 8)
        out[(size_t)(n0 + i) * KDIM + k0 + tx] = __float2half_rn(t[tx][i]);
}

// ---------------------------------------------------------------- attention
// 256 threads / 8 warps; warp w owns query rows w*16..w*16+15. Flash-style:
// S = Q K^T (fp16), exp in registers, accumulator->A-frag identity relayout,
// O += P*V. Low regs -> 2 CTAs/SM (16 warps) for load/MUFU/MMA overlap.
__global__ __launch_bounds__(256, 2) void attn_tc(
    const __half* __restrict__ q_g, const __half* __restrict__ k_g,
    const __half* __restrict__ v_g, const float* __restrict__ decay,
    __half* __restrict__ ao)
{
    const int c = blockIdx.x, h = blockIdx.y, b = blockIdx.z;
    const int tid = threadIdx.x, wid = tid >> 5, lane = tid & 31;

    extern __shared__ char sma[];
    const uint32_t sb = smem_u32(sma);
    float* df = (float*)(sma + AT_DF);

    const size_t base = ((size_t)b * L_SZ + (size_t)c * CHUNK) * D_MODEL + h * D_HEAD;

    // zero pad rows 129..143 of K/V
    {
        const uint4 z = make_uint4(0, 0, 0, 0);
        for (int i = tid; i < 135; i += 256) {
            *(uint4*)(sma + AT_K + 129 * 144 + i * 16) = z;
            *(uint4*)(sma + AT_V + 129 * 144 + i * 16) = z;
        }
        if (c == 0 && tid < 9) {
            *(uint4*)(sma + AT_K + tid * 16) = z;
            *(uint4*)(sma + AT_V + tid * 16) = z;
        }
    }

    // cp.async loads: Q 128 rows x 8 chunks, K/V rows 1..128 (+row0 if c>0)
    for (int idx = tid; idx < 128 * 8; idx += 256) {
        const int r = idx >> 3, ch = idx & 7;
        const uint32_t so = (uint32_t)(r * 144 + ch * 16);
        const size_t g = base + (size_t)r * D_MODEL + ch * 8;
        cp16(sb + AT_Q + so, q_g + g);
        cp16(sb + AT_K + 144 + so, k_g + g);
        cp16(sb + AT_V + 144 + so, v_g + g);
    }
    if (c > 0 && tid < 8) {
        const size_t g0 = base - D_MODEL + tid * 8;
        cp16(sb + AT_K + tid * 16, k_g + g0);
        cp16(sb + AT_V + tid * 16, v_g + g0);
    }
    CP_COMMIT();
    if (tid < 128) df[tid] = 0.125f * powf(decay[h], (float)tid);
    CP_WAIT0();
    __syncthreads();

    const uint32_t a_ro = (uint32_t)(lane & 15);
    const uint32_t a_ko = (uint32_t)((lane >> 4) * 8);
    const uint32_t b_ro = (uint32_t)((lane & 7) + ((lane >> 4) << 3));
    const uint32_t b_ko = (uint32_t)(((lane >> 3) & 1) * 8);
    const uint32_t v_ro = (uint32_t)(lane & 15);
    const uint32_t v_co = (uint32_t)((lane >> 4) << 3);

    // preload Q fragments for this warp's 16 rows
    uint32_t qf[4][4];
#pragma unroll
    for (int kt = 0; kt < 4; kt++) {
        const uint32_t aoff = ((wid * 16 + a_ro) * 72 + kt * 16 + a_ko) * 2;
        ldm_x4(qf[kt], sb + AT_Q + aoff);
    }

    const int gr = lane >> 2;
    const int r0 = wid * 16 + gr;
    const float sfa = df[r0], sfb = df[r0 + 8];
    float lsum[2] = {0.f, 0.f};
    float oacc[8][4];
#pragma unroll
    for (int n8 = 0; n8 < 8; n8++)
#pragma unroll
        for (int t = 0; t < 4; t++) oacc[n8][t] = 0.f;

#pragma unroll
    for (int nt = 0; nt < 9; nt++) {
        uint32_t kf[4][4];
#pragma unroll
        for (int kt = 0; kt < 4; kt++) {
            const uint32_t bo = ((nt * 16 + b_ro) * 72 + kt * 16 + b_ko) * 2;
            ldm_x4(kf[kt], sb + AT_K + bo);
        }
        uint32_t vfr[4][4];
#pragma unroll
        for (int g = 0; g < 4; g++) {
            const uint32_t bo = ((nt * 16 + v_ro) * 72 + g * 16 + v_co) * 2;
            ldm_x4_t(vfr[g], sb + AT_V + bo);
        }

        float pf[2][4];
#pragma unroll
        for (int half = 0; half < 2; half++) {
            float acc[4] = {0.f, 0.f, 0.f, 0.f};
#pragma unroll
            for (int kt = 0; kt < 4; kt++)
                mma_f16(acc, qf[kt], &kf[kt][half * 2]);
            const int c0 = nt * 16 + half * 8 + (lane & 3) * 2;
            pf[half][0] = (c0     < 129) ? __expf(acc[0] * sfa) : 0.f;
            pf[half][1] = (c0 + 1 < 129) ? __expf(acc[1] * sfa) : 0.f;
            pf[half][2] = (c0     < 129) ? __expf(acc[2] * sfb) : 0.f;
            pf[half][3] = (c0 + 1 < 129) ? __expf(acc[3] * sfb) : 0.f;
            lsum[0] += pf[half][0] + pf[half][1];
            lsum[1] += pf[half][2] + pf[half][3];
        }
        uint32_t pa[4];
        pa[0] = pack_f16(pf[0][0], pf[0][1]);
        pa[1] = pack_f16(pf[0][2], pf[0][3]);
        pa[2] = pack_f16(pf[1][0], pf[1][1]);
        pa[3] = pack_f16(pf[1][2], pf[1][3]);
#pragma unroll
        for (int n8 = 0; n8 < 8; n8++)
            mma_f16(oacc[n8], pa, &vfr[n8 >> 1][(n8 & 1) * 2]);
    }

    float inv[2];
#pragma unroll
    for (int rh = 0; rh < 2; rh++) {
        float s = lsum[rh];
        s += __shfl_xor_sync(0xFFFFFFFFu, s, 1);
        s += __shfl_xor_sync(0xFFFFFFFFu, s, 2);
        inv[rh] = 1.f / s;
    }

#pragma unroll
    for (int n8 = 0; n8 < 8; n8++) {
        const int c0 = n8 * 8 + (lane & 3) * 2;
#pragma unroll
        for (int hrow = 0; hrow < 2; hrow++) {
            const int rr = r0 + hrow * 8;
            const float iv = inv[hrow];
            *(uint32_t*)(ao + base + (size_t)rr * D_MODEL + c0) = pack_f16(
                oacc[n8][hrow * 2 + 0] * iv, oacc[n8][hrow * 2 + 1] * iv);
        }
    }
}

// ---------------------------------------------------------------- launch
extern "C" void kernel_launch(void* const* d_in, const int* in_sizes, int n_in,
                              void* d_out, int out_size)
{
    const float* x     = (const float*)d_in[0];
    const float* Wq    = (const float*)d_in[1];
    const float* bq    = (const float*)d_in[2];
    const float* Wk    = (const float*)d_in[3];
    const float* bk    = (const float*)d_in[4];
    const float* Wv    = (const float*)d_in[5];
    const float* bv    = (const float*)d_in[6];
    const float* Wo    = (const float*)d_in[7];
    const float* bo    = (const float*)d_in[8];
    const float* decay = (const float*)d_in[9];
    float* out = (float*)d_out;

    __half *xh, *ao, *wt, *q16, *k16, *v16;
    cudaGetSymbolAddress((void**)&xh,  g_xh);
    cudaGetSymbolAddress((void**)&ao,  g_ao);
    cudaGetSymbolAddress((void**)&wt,  g_wt);
    cudaGetSymbolAddress((void**)&q16, g_q16);
    cudaGetSymbolAddress((void**)&k16, g_k16);
    cudaGetSymbolAddress((void**)&v16, g_v16);

    cudaFuncSetAttribute(gemm_qkv, cudaFuncAttributeMaxDynamicSharedMemorySize, GSMEM);
    cudaFuncSetAttribute(gemm_out, cudaFuncAttributeMaxDynamicSharedMemorySize, GSMEM);
    cudaFuncSetAttribute(attn_tc, cudaFuncAttributeMaxDynamicSharedMemorySize, AT_SZ);

    wsplit4<<<dim3(NDIM / 32, KDIM / 32, 4), dim3(32, 8)>>>(Wq, Wk, Wv, Wo, wt);

    const int n4 = M_TOT * D_MODEL / 4;
    tof16<<<(n4 + 255) / 256, 256>>>((const float4*)x, (uint2*)xh, n4);

    gemm_qkv<<<dim3(NDIM / BN, M_TOT / BM, 3), 256, GSMEM>>>(
        xh, wt, bq, bk, bv, q16, k16, v16, M_TOT, NDIM, KDIM);

    attn_tc<<<dim3(NCHUNK, N_HEADS, B_SZ), 256, AT_SZ>>>(q16, k16, v16, decay, ao);

    gemm_out<<<dim3(NDIM / BN, M_TOT / BM), 256, GSMEM>>>(
        ao, wt + 3 * (size_t)WSL, bo, out, M_TOT, NDIM, KDIM);
}